// round 1
// baseline (speedup 1.0000x reference)
#include <cuda_runtime.h>

#define Bsz 8
#define Nseq 16384
#define CIN 256     // DIM
#define Dd 512      // D
#define Hh 64       // DIM_HEAD
#define SCALEF 0.125f

// scratch (device globals; no allocation allowed)
__device__ __align__(16) float g_v[CIN];
__device__ float g_s0;
__device__ float g_c0[Hh];
__device__ __align__(16) float g_W1[Dd*Hh];
__device__ __align__(16) float g_A[CIN*Hh];
__device__ float g_ypart[Bsz*64*CIN];
__device__ float g_Spart[Bsz*64];
__device__ float g_aw[Bsz*Dd];
__device__ __align__(16) float g_M[Bsz*CIN*Hh];
__device__ float g_bias[Bsz*Hh];

__device__ __forceinline__ unsigned long long ffma2(unsigned long long a,
                                                    unsigned long long b,
                                                    unsigned long long c) {
    unsigned long long d;
    asm("fma.rn.f32x2 %0, %1, %2, %3;" : "=l"(d) : "l"(a), "l"(b), "l"(c));
    return d;
}

// ---------------------------------------------------------------------------
// k_prep_small: v = Wq@qw, s0 = bq.qw, c0 = (bq+bp)@Wo + bo
// ---------------------------------------------------------------------------
__global__ void k_prep_small(const float* __restrict__ Wq, const float* __restrict__ bq,
                             const float* __restrict__ qw, const float* __restrict__ bp,
                             const float* __restrict__ Wo, const float* __restrict__ bo) {
    int lane = threadIdx.x & 31;
    if (blockIdx.x < 32) {
        int g = blockIdx.x * 8 + (threadIdx.x >> 5);   // 0..255
        const float* row = Wq + (size_t)g * Dd;
        float acc = 0.f;
        #pragma unroll
        for (int i = 0; i < 16; ++i) acc += row[lane + 32*i] * qw[lane + 32*i];
        #pragma unroll
        for (int o = 16; o; o >>= 1) acc += __shfl_xor_sync(0xffffffffu, acc, o);
        if (lane == 0) g_v[g] = acc;
    } else {
        int t = threadIdx.x;
        if (t < 64) {
            float acc = bo[t];
            for (int d = 0; d < Dd; ++d) acc += (bq[d] + bp[d]) * Wo[d*Hh + t];
            g_c0[t] = acc;
        } else if (t < 96) {
            float acc = 0.f;
            #pragma unroll
            for (int i = 0; i < 16; ++i) acc += bq[lane + 32*i] * qw[lane + 32*i];
            #pragma unroll
            for (int o = 16; o; o >>= 1) acc += __shfl_xor_sync(0xffffffffu, acc, o);
            if (lane == 0) g_s0 = acc;
        }
    }
}

// ---------------------------------------------------------------------------
// 64x64 output tile SGEMM body (256 threads, 4x4 micro-tile), K multiple of 32
// ---------------------------------------------------------------------------
__device__ void gemm64(const float* __restrict__ Am, int lda,
                       const float* __restrict__ Bm, int ldb, int K,
                       const float* __restrict__ scale,   // nullable, len K (scales B rows)
                       const float* __restrict__ addend,  // nullable, ldc layout
                       float* __restrict__ C, int ldc)
{
    __shared__ float As[32][65];
    __shared__ float Bs[32][64];
    int tid = threadIdx.x;
    int tx = tid & 15, ty = tid >> 4;
    float acc[4][4] = {};
    for (int kc = 0; kc < K; kc += 32) {
        #pragma unroll
        for (int i = 0; i < 8; ++i) {
            int idx = tid + i*256;
            int m = idx >> 5, k = idx & 31;
            As[k][m] = Am[(size_t)m*lda + kc + k];
        }
        #pragma unroll
        for (int i = 0; i < 8; ++i) {
            int idx = tid + i*256;
            int k = idx >> 6, n = idx & 63;
            float bv = Bm[(size_t)(kc + k)*ldb + n];
            if (scale) bv *= scale[kc + k];
            Bs[k][n] = bv;
        }
        __syncthreads();
        #pragma unroll
        for (int k = 0; k < 32; ++k) {
            float a[4], bv[4];
            #pragma unroll
            for (int i = 0; i < 4; ++i) a[i] = As[k][ty*4+i];
            #pragma unroll
            for (int j = 0; j < 4; ++j) bv[j] = Bs[k][tx*4+j];
            #pragma unroll
            for (int i = 0; i < 4; ++i)
                #pragma unroll
                for (int j = 0; j < 4; ++j) acc[i][j] += a[i]*bv[j];
        }
        __syncthreads();
    }
    #pragma unroll
    for (int i = 0; i < 4; ++i) {
        int r = ty*4+i;
        #pragma unroll
        for (int j = 0; j < 4; ++j) {
            int cidx = r*ldc + tx*4+j;
            float vv = acc[i][j];
            if (addend) vv += addend[cidx];
            C[cidx] = vv;
        }
    }
}

// W1 = Wp@Wo (512x64), A = Wq@Wo (256x64)
__global__ void k_w1_a(const float* __restrict__ Wp, const float* __restrict__ Wq,
                       const float* __restrict__ Wo) {
    if (blockIdx.x < 8) {
        int row0 = blockIdx.x * 64;
        gemm64(Wp + (size_t)row0*Dd, Dd, Wo, Hh, Dd, nullptr, nullptr, g_W1 + row0*Hh, Hh);
    } else {
        int row0 = (blockIdx.x - 8) * 64;
        gemm64(Wq + (size_t)row0*Dd, Dd, Wo, Hh, Dd, nullptr, nullptr, g_A + row0*Hh, Hh);
    }
}

// ---------------------------------------------------------------------------
// pass 1: per block (tile of 256 tokens of batch b):
//   score_n = SCALE*(x_n . v + s0);  y += score_n * x_n;  S += score_n
// deterministic partials per block -> g_ypart / g_Spart
// ---------------------------------------------------------------------------
__global__ void k_pass1(const float* __restrict__ x) {
    __shared__ float y_sh[8][256];
    __shared__ float s_sh[8];
    int b = blockIdx.y;
    int tile = blockIdx.x;
    int warp = threadIdx.x >> 5, lane = threadIdx.x & 31;

    float4 v0 = *(const float4*)(g_v + 4*lane);
    float4 v1 = *(const float4*)(g_v + 128 + 4*lane);
    float s0 = g_s0;

    const float* xb = x + ((size_t)b*Nseq + (size_t)tile*256 + warp*32) * CIN;

    float y0[4] = {0,0,0,0}, y1[4] = {0,0,0,0};
    float Sacc = 0.f;
    for (int t = 0; t < 32; ++t) {
        const float* xr = xb + t*CIN;
        float4 a0 = *(const float4*)(xr + 4*lane);
        float4 a1 = *(const float4*)(xr + 128 + 4*lane);
        float p = a0.x*v0.x + a0.y*v0.y + a0.z*v0.z + a0.w*v0.w
                + a1.x*v1.x + a1.y*v1.y + a1.z*v1.z + a1.w*v1.w;
        #pragma unroll
        for (int o = 16; o; o >>= 1) p += __shfl_xor_sync(0xffffffffu, p, o);
        float score = (p + s0) * SCALEF;
        Sacc += score;
        y0[0] += score*a0.x; y0[1] += score*a0.y; y0[2] += score*a0.z; y0[3] += score*a0.w;
        y1[0] += score*a1.x; y1[1] += score*a1.y; y1[2] += score*a1.z; y1[3] += score*a1.w;
    }
    #pragma unroll
    for (int j = 0; j < 4; ++j) {
        y_sh[warp][4*lane + j]       = y0[j];
        y_sh[warp][128 + 4*lane + j] = y1[j];
    }
    if (lane == 0) s_sh[warp] = Sacc;
    __syncthreads();
    int c = threadIdx.x;
    float acc = 0.f;
    #pragma unroll
    for (int w = 0; w < 8; ++w) acc += y_sh[w][c];
    g_ypart[((size_t)b*64 + tile)*256 + c] = acc;
    if (threadIdx.x == 0) {
        float s = 0.f;
        for (int w = 0; w < 8; ++w) s += s_sh[w];
        g_Spart[b*64 + tile] = s;
    }
}

// ---------------------------------------------------------------------------
// aw[b,d] = y_b . Wq[:,d] + bq[d]*S_b   (reduces partials itself)
// ---------------------------------------------------------------------------
__global__ void k_aw(const float* __restrict__ Wq, const float* __restrict__ bq) {
    __shared__ float y_s[256];
    __shared__ float S_s;
    int b = blockIdx.y;
    int d = blockIdx.x * 128 + threadIdx.x;
    for (int c = threadIdx.x; c < 256; c += 128) {
        float acc = 0.f;
        #pragma unroll 8
        for (int p = 0; p < 64; ++p) acc += g_ypart[((size_t)b*64 + p)*256 + c];
        y_s[c] = acc;
    }
    if (threadIdx.x == 0) {
        float s = 0.f;
        for (int p = 0; p < 64; ++p) s += g_Spart[b*64 + p];
        S_s = s;
    }
    __syncthreads();
    float acc = bq[d] * S_s;
    #pragma unroll 8
    for (int c = 0; c < 256; ++c) acc += y_s[c] * Wq[(size_t)c*Dd + d];
    g_aw[b*Dd + d] = acc;
}

// ---------------------------------------------------------------------------
// M_b = Wk @ (diag(aw_b) W1) + A ;  bias_b = (aw_b . bk)@W1 + c0
// ---------------------------------------------------------------------------
__global__ void k_M(const float* __restrict__ Wk, const float* __restrict__ bk) {
    int b = blockIdx.y;
    if (blockIdx.x < 4) {
        int row0 = blockIdx.x * 64;
        gemm64(Wk + (size_t)row0*Dd, Dd, g_W1, Hh, Dd,
               g_aw + b*Dd, g_A + row0*Hh,
               g_M + ((size_t)b*CIN + row0)*Hh, Hh);
    } else {
        int h = threadIdx.x;
        if (h < 64) {
            float acc = g_c0[h];
            #pragma unroll 8
            for (int d = 0; d < Dd; ++d)
                acc += g_aw[b*Dd + d] * bk[d] * g_W1[d*Hh + h];
            g_bias[b*Hh + h] = acc;
        }
    }
}

// ---------------------------------------------------------------------------
// pass 2: out[b,n,:] = x[b,n,:] @ M_b + bias_b
// block: 128 tokens x 64 heads, 256 threads, K chunked by 32,
// packed fp32x2 FMA (sm_103a), smem-tiled.
// ---------------------------------------------------------------------------
__global__ void __launch_bounds__(256) k_pass2(const float* __restrict__ x,
                                               float* __restrict__ out) {
    __shared__ float x_s[128*36];   // 128 tokens x 32 k (pad 36)
    __shared__ float M_s[32*64];    // 32 k rows x 64 h
    __shared__ float bias_s[64];

    int b = blockIdx.y;
    int tok0 = blockIdx.x * 128;
    int tid = threadIdx.x;
    if (tid < 64) bias_s[tid] = g_bias[b*Hh + tid];

    int ht = tid & 3;        // head group of 16
    int pr = tid >> 2;       // token pair 0..63
    int h0 = ht * 16;

    unsigned long long acc0[8], acc1[8];
    #pragma unroll
    for (int j = 0; j < 8; ++j) { acc0[j] = 0ull; acc1[j] = 0ull; }

    const float* xb = x + ((size_t)b*Nseq + tok0) * CIN;
    const float* Mb = g_M + (size_t)b*CIN*Hh;

    for (int kc = 0; kc < 8; ++kc) {
        __syncthreads();
        // stage x chunk: 128 tokens x 32 channels (8 float4 per row)
        #pragma unroll
        for (int i = 0; i < 4; ++i) {
            int idx = tid + i*256;
            int m = idx >> 3, k4 = idx & 7;
            float4 val = *(const float4*)(xb + (size_t)m*CIN + kc*32 + k4*4);
            *(float4*)(x_s + m*36 + k4*4) = val;
        }
        // stage M chunk: 32 rows x 64 h
        #pragma unroll
        for (int i = 0; i < 2; ++i) {
            int idx = tid + i*256;
            ((float4*)M_s)[idx] = ((const float4*)(Mb + kc*32*Hh))[idx];
        }
        __syncthreads();
        const float* xr0 = x_s + (2*pr)*36;
        const float* xr1 = xr0 + 36;
        #pragma unroll 4
        for (int c = 0; c < 32; ++c) {
            unsigned int xi0 = __float_as_uint(xr0[c]);
            unsigned int xi1 = __float_as_uint(xr1[c]);
            unsigned long long x0p, x1p;
            asm("mov.b64 %0, {%1,%1};" : "=l"(x0p) : "r"(xi0));
            asm("mov.b64 %0, {%1,%1};" : "=l"(x1p) : "r"(xi1));
            const ulonglong2* Mc = (const ulonglong2*)(M_s + c*Hh + h0);
            #pragma unroll
            for (int q = 0; q < 4; ++q) {
                ulonglong2 mp = Mc[q];
                acc0[2*q]   = ffma2(x0p, mp.x, acc0[2*q]);
                acc0[2*q+1] = ffma2(x0p, mp.y, acc0[2*q+1]);
                acc1[2*q]   = ffma2(x1p, mp.x, acc1[2*q]);
                acc1[2*q+1] = ffma2(x1p, mp.y, acc1[2*q+1]);
            }
        }
    }
    float* o0 = out + ((size_t)b*Nseq + tok0 + 2*pr)*Hh + h0;
    float* o1 = o0 + Hh;
    #pragma unroll
    for (int q = 0; q < 4; ++q) {
        float2 p0 = *(float2*)&acc0[2*q];
        float2 p1 = *(float2*)&acc0[2*q+1];
        float b0 = bias_s[h0+4*q], b1 = bias_s[h0+4*q+1];
        float b2 = bias_s[h0+4*q+2], b3 = bias_s[h0+4*q+3];
        float4 ov0 = make_float4(p0.x+b0, p0.y+b1, p1.x+b2, p1.y+b3);
        *(float4*)(o0 + 4*q) = ov0;
        float2 q0 = *(float2*)&acc1[2*q];
        float2 q1 = *(float2*)&acc1[2*q+1];
        float4 ov1 = make_float4(q0.x+b0, q0.y+b1, q1.x+b2, q1.y+b3);
        *(float4*)(o1 + 4*q) = ov1;
    }
}

extern "C" void kernel_launch(void* const* d_in, const int* in_sizes, int n_in,
                              void* d_out, int out_size) {
    const float* x  = (const float*)d_in[0];
    const float* Wq = (const float*)d_in[1];
    const float* bq = (const float*)d_in[2];
    const float* Wk = (const float*)d_in[3];
    const float* bk = (const float*)d_in[4];
    const float* qw = (const float*)d_in[5];
    const float* Wp = (const float*)d_in[6];
    const float* bp = (const float*)d_in[7];
    const float* Wo = (const float*)d_in[8];
    const float* bo = (const float*)d_in[9];
    float* out = (float*)d_out;
    (void)in_sizes; (void)n_in; (void)out_size;

    k_prep_small<<<33, 256>>>(Wq, bq, qw, bp, Wo, bo);
    k_w1_a<<<12, 256>>>(Wp, Wq, Wo);
    {
        dim3 g(64, 8);
        k_pass1<<<g, 256>>>(x);
    }
    {
        dim3 g(4, 8);
        k_aw<<<g, 128>>>(Wq, bq);
    }
    {
        dim3 g(5, 8);
        k_M<<<g, 256>>>(Wk, bk);
    }
    {
        dim3 g(128, 8);
        k_pass2<<<g, 256>>>(x, out);
    }
}

// round 2
// speedup vs baseline: 1.1257x; 1.1257x over previous
#include <cuda_runtime.h>

#define Bsz 8
#define Nseq 16384
#define CIN 256     // DIM
#define Dd 512      // D
#define Hh 64       // DIM_HEAD
#define SCALEF 0.125f

// scratch (device globals; no allocation allowed)
__device__ __align__(16) float g_v[CIN];
__device__ float g_s0;
__device__ float g_c0[Hh];
__device__ __align__(16) float g_W1[Dd*Hh];
__device__ __align__(16) float g_A[CIN*Hh];
__device__ float g_ypart[Bsz*64*CIN];
__device__ float g_Spart[Bsz*64];
__device__ __align__(16) float g_M[Bsz*CIN*Hh];
__device__ float g_bias[Bsz*Hh];

__device__ __forceinline__ unsigned long long ffma2(unsigned long long a,
                                                    unsigned long long b,
                                                    unsigned long long c) {
    unsigned long long d;
    asm("fma.rn.f32x2 %0, %1, %2, %3;" : "=l"(d) : "l"(a), "l"(b), "l"(c));
    return d;
}

// ---------------------------------------------------------------------------
// k_prep (grid 129):
//   blocks 0..31  : v = Wq@qw (8 rows per block, warp per row)
//   block  32     : s0 = bq.qw ; c0 = (bq+bp)@Wo + bo
//   blocks 33..96 : W1 = Wp@Wo   (8 rows per block)
//   blocks 97..128: A  = Wq@Wo   (8 rows per block)
// ---------------------------------------------------------------------------
__global__ void __launch_bounds__(256) k_prep(
        const float* __restrict__ Wq, const float* __restrict__ bq,
        const float* __restrict__ qw, const float* __restrict__ bp,
        const float* __restrict__ Wo, const float* __restrict__ bo,
        const float* __restrict__ Wp) {
    __shared__ float Ap[8*512];
    int tid = threadIdx.x;
    int lane = tid & 31;
    int bx = blockIdx.x;

    if (bx < 32) {
        int g = bx * 8 + (tid >> 5);
        const float* row = Wq + (size_t)g * Dd;
        float acc = 0.f;
        #pragma unroll
        for (int i = 0; i < 16; ++i) acc += row[lane + 32*i] * qw[lane + 32*i];
        #pragma unroll
        for (int o = 16; o; o >>= 1) acc += __shfl_xor_sync(0xffffffffu, acc, o);
        if (lane == 0) g_v[g] = acc;
        return;
    }
    if (bx == 32) {
        if (tid < 64) {
            float acc = bo[tid];
            #pragma unroll 8
            for (int d = 0; d < Dd; ++d) acc += (bq[d] + bp[d]) * Wo[d*Hh + tid];
            g_c0[tid] = acc;
        } else if (tid < 96) {
            float acc = 0.f;
            #pragma unroll
            for (int i = 0; i < 16; ++i) acc += bq[lane + 32*i] * qw[lane + 32*i];
            #pragma unroll
            for (int o = 16; o; o >>= 1) acc += __shfl_xor_sync(0xffffffffu, acc, o);
            if (lane == 0) g_s0 = acc;
        }
        return;
    }
    // 8-row x 64-col GEMM tile with K=512
    const float* Asrc;
    float* Cdst;
    if (bx < 97) {
        int r0 = (bx - 33) * 8;
        Asrc = Wp + (size_t)r0 * Dd;
        Cdst = g_W1 + (size_t)r0 * Hh;
    } else {
        int r0 = (bx - 97) * 8;
        Asrc = Wq + (size_t)r0 * Dd;
        Cdst = g_A + (size_t)r0 * Hh;
    }
    #pragma unroll
    for (int i = 0; i < 4; ++i)
        ((float4*)Ap)[tid + i*256] = ((const float4*)Asrc)[tid + i*256];
    __syncthreads();
    int c = tid & 63, rp = tid >> 6;
    const float* rowA = Ap + (2*rp) * 512;
    const float* rowB = rowA + 512;
    float acc0 = 0.f, acc1 = 0.f;
    #pragma unroll 8
    for (int k = 0; k < 512; ++k) {
        float w = Wo[k*Hh + c];
        acc0 += rowA[k] * w;
        acc1 += rowB[k] * w;
    }
    Cdst[(2*rp)*Hh + c]   = acc0;
    Cdst[(2*rp+1)*Hh + c] = acc1;
}

// ---------------------------------------------------------------------------
// pass 1: per block (tile of 256 tokens of batch b):
//   score_n = SCALE*(x_n . v + s0);  y += score_n * x_n;  S += score_n
// ---------------------------------------------------------------------------
__global__ void __launch_bounds__(256) k_pass1(const float* __restrict__ x) {
    __shared__ float y_sh[8][256];
    __shared__ float s_sh[8];
    int b = blockIdx.y;
    int tile = blockIdx.x;
    int warp = threadIdx.x >> 5, lane = threadIdx.x & 31;

    float4 v0 = *(const float4*)(g_v + 4*lane);
    float4 v1 = *(const float4*)(g_v + 128 + 4*lane);
    float s0 = g_s0;

    const float* xb = x + ((size_t)b*Nseq + (size_t)tile*256 + warp*32) * CIN;

    float y0[4] = {0,0,0,0}, y1[4] = {0,0,0,0};
    float Sacc = 0.f;
    for (int t = 0; t < 32; ++t) {
        const float* xr = xb + t*CIN;
        float4 a0 = *(const float4*)(xr + 4*lane);
        float4 a1 = *(const float4*)(xr + 128 + 4*lane);
        float p = a0.x*v0.x + a0.y*v0.y + a0.z*v0.z + a0.w*v0.w
                + a1.x*v1.x + a1.y*v1.y + a1.z*v1.z + a1.w*v1.w;
        #pragma unroll
        for (int o = 16; o; o >>= 1) p += __shfl_xor_sync(0xffffffffu, p, o);
        float score = (p + s0) * SCALEF;
        Sacc += score;
        y0[0] += score*a0.x; y0[1] += score*a0.y; y0[2] += score*a0.z; y0[3] += score*a0.w;
        y1[0] += score*a1.x; y1[1] += score*a1.y; y1[2] += score*a1.z; y1[3] += score*a1.w;
    }
    #pragma unroll
    for (int j = 0; j < 4; ++j) {
        y_sh[warp][4*lane + j]       = y0[j];
        y_sh[warp][128 + 4*lane + j] = y1[j];
    }
    if (lane == 0) s_sh[warp] = Sacc;
    __syncthreads();
    int c = threadIdx.x;
    float acc = 0.f;
    #pragma unroll
    for (int w = 0; w < 8; ++w) acc += y_sh[w][c];
    g_ypart[((size_t)b*64 + tile)*256 + c] = acc;
    if (threadIdx.x == 0) {
        float s = 0.f;
        for (int w = 0; w < 8; ++w) s += s_sh[w];
        g_Spart[b*64 + tile] = s;
    }
}

// ---------------------------------------------------------------------------
// k_mid (grid 72 = 8 batches x 9 parts):
//   every block: reduce ypart -> y_s, S; compute aw_s[512] (redundant, cheap)
//   parts 0..7: 32-row tile of M_b = Wk @ diag(aw_b) @ W1 + A
//   part  8   : bias_b = (aw_b ⊙ bk) @ W1 + c0
// ---------------------------------------------------------------------------
__global__ void __launch_bounds__(256) k_mid(
        const float* __restrict__ Wq, const float* __restrict__ bq,
        const float* __restrict__ Wk, const float* __restrict__ bk) {
    __shared__ float y_s[256];
    __shared__ float aw_s[512];
    __shared__ float s_tmp[64];
    __shared__ float Wks[32][33];
    __shared__ float W1s[32][64];
    __shared__ float red[4][64];

    int tid = threadIdx.x;
    int b = blockIdx.x / 9;
    int part = blockIdx.x % 9;

    // y reduce (deterministic fixed order)
    {
        const float* yp = g_ypart + (size_t)b*64*256 + tid;
        float acc = 0.f;
        #pragma unroll 8
        for (int p = 0; p < 64; ++p) acc += yp[p*256];
        y_s[tid] = acc;
    }
    if (tid < 64) s_tmp[tid] = g_Spart[b*64 + tid];
    __syncthreads();
    float S = 0.f;
    #pragma unroll
    for (int i = 0; i < 64; ++i) S += s_tmp[i];

    // aw (each thread 2 outputs)
    {
        float a0 = bq[tid] * S;
        float a1 = bq[tid + 256] * S;
        #pragma unroll 4
        for (int c = 0; c < 256; ++c) {
            float yc = y_s[c];
            a0 += yc * Wq[(size_t)c*Dd + tid];
            a1 += yc * Wq[(size_t)c*Dd + tid + 256];
        }
        aw_s[tid] = a0;
        aw_s[tid + 256] = a1;
    }
    __syncthreads();

    if (part == 8) {
        int h = tid & 63, seg = tid >> 6;
        float acc = 0.f;
        #pragma unroll 4
        for (int d = seg*128; d < seg*128 + 128; ++d)
            acc += aw_s[d] * bk[d] * g_W1[(size_t)d*Hh + h];
        red[seg][h] = acc;
        __syncthreads();
        if (tid < 64)
            g_bias[b*Hh + tid] = red[0][tid] + red[1][tid] + red[2][tid]
                               + red[3][tid] + g_c0[tid];
        return;
    }

    int r0 = part * 32;
    int tx = tid & 31, ty = tid >> 5;
    float accm[4][2] = {};
    for (int kc = 0; kc < Dd; kc += 32) {
        __syncthreads();
        #pragma unroll
        for (int i = 0; i < 4; ++i) {
            int idx = tid + i*256;
            int r = idx >> 5, k = idx & 31;
            Wks[r][k] = Wk[(size_t)(r0 + r)*Dd + kc + k];
        }
        #pragma unroll
        for (int i = 0; i < 8; ++i) {
            int idx = tid + i*256;
            int k = idx >> 6, h = idx & 63;
            W1s[k][h] = g_W1[(size_t)(kc + k)*Hh + h] * aw_s[kc + k];
        }
        __syncthreads();
        #pragma unroll
        for (int k = 0; k < 32; ++k) {
            float bv0 = W1s[k][2*tx], bv1 = W1s[k][2*tx + 1];
            #pragma unroll
            for (int i = 0; i < 4; ++i) {
                float av = Wks[ty*4 + i][k];
                accm[i][0] += av * bv0;
                accm[i][1] += av * bv1;
            }
        }
    }
    #pragma unroll
    for (int i = 0; i < 4; ++i) {
        int r = r0 + ty*4 + i;
        float* dst = g_M + ((size_t)b*CIN + r)*Hh + 2*tx;
        const float* addA = g_A + (size_t)r*Hh + 2*tx;
        dst[0] = accm[i][0] + addA[0];
        dst[1] = accm[i][1] + addA[1];
    }
}

// ---------------------------------------------------------------------------
// pass 2: out[b,n,:] = x[b,n,:] @ M_b + bias_b
// block: 128 tokens x 64 heads, 256 threads, K chunked by 32,
// packed fp32x2 FMA (sm_103a), smem-tiled.
// ---------------------------------------------------------------------------
__global__ void __launch_bounds__(256) k_pass2(const float* __restrict__ x,
                                               float* __restrict__ out) {
    __shared__ float x_s[128*36];
    __shared__ float M_s[32*64];
    __shared__ float bias_s[64];

    int b = blockIdx.y;
    int tok0 = blockIdx.x * 128;
    int tid = threadIdx.x;
    if (tid < 64) bias_s[tid] = g_bias[b*Hh + tid];

    int ht = tid & 3;
    int pr = tid >> 2;
    int h0 = ht * 16;

    unsigned long long acc0[8], acc1[8];
    #pragma unroll
    for (int j = 0; j < 8; ++j) { acc0[j] = 0ull; acc1[j] = 0ull; }

    const float* xb = x + ((size_t)b*Nseq + tok0) * CIN;
    const float* Mb = g_M + (size_t)b*CIN*Hh;

    for (int kc = 0; kc < 8; ++kc) {
        __syncthreads();
        #pragma unroll
        for (int i = 0; i < 4; ++i) {
            int idx = tid + i*256;
            int m = idx >> 3, k4 = idx & 7;
            float4 val = *(const float4*)(xb + (size_t)m*CIN + kc*32 + k4*4);
            *(float4*)(x_s + m*36 + k4*4) = val;
        }
        #pragma unroll
        for (int i = 0; i < 2; ++i) {
            int idx = tid + i*256;
            ((float4*)M_s)[idx] = ((const float4*)(Mb + kc*32*Hh))[idx];
        }
        __syncthreads();
        const float* xr0 = x_s + (2*pr)*36;
        const float* xr1 = xr0 + 36;
        #pragma unroll 4
        for (int c = 0; c < 32; ++c) {
            unsigned int xi0 = __float_as_uint(xr0[c]);
            unsigned int xi1 = __float_as_uint(xr1[c]);
            unsigned long long x0p, x1p;
            asm("mov.b64 %0, {%1,%1};" : "=l"(x0p) : "r"(xi0));
            asm("mov.b64 %0, {%1,%1};" : "=l"(x1p) : "r"(xi1));
            const ulonglong2* Mc = (const ulonglong2*)(M_s + c*Hh + h0);
            #pragma unroll
            for (int q = 0; q < 4; ++q) {
                ulonglong2 mp = Mc[q];
                acc0[2*q]   = ffma2(x0p, mp.x, acc0[2*q]);
                acc0[2*q+1] = ffma2(x0p, mp.y, acc0[2*q+1]);
                acc1[2*q]   = ffma2(x1p, mp.x, acc1[2*q]);
                acc1[2*q+1] = ffma2(x1p, mp.y, acc1[2*q+1]);
            }
        }
    }
    float* o0 = out + ((size_t)b*Nseq + tok0 + 2*pr)*Hh + h0;
    float* o1 = o0 + Hh;
    #pragma unroll
    for (int q = 0; q < 4; ++q) {
        float2 p0 = *(float2*)&acc0[2*q];
        float2 p1 = *(float2*)&acc0[2*q+1];
        float b0 = bias_s[h0+4*q], b1 = bias_s[h0+4*q+1];
        float b2 = bias_s[h0+4*q+2], b3 = bias_s[h0+4*q+3];
        float4 ov0 = make_float4(p0.x+b0, p0.y+b1, p1.x+b2, p1.y+b3);
        *(float4*)(o0 + 4*q) = ov0;
        float2 q0 = *(float2*)&acc1[2*q];
        float2 q1 = *(float2*)&acc1[2*q+1];
        float4 ov1 = make_float4(q0.x+b0, q0.y+b1, q1.x+b2, q1.y+b3);
        *(float4*)(o1 + 4*q) = ov1;
    }
}

extern "C" void kernel_launch(void* const* d_in, const int* in_sizes, int n_in,
                              void* d_out, int out_size) {
    const float* x  = (const float*)d_in[0];
    const float* Wq = (const float*)d_in[1];
    const float* bq = (const float*)d_in[2];
    const float* Wk = (const float*)d_in[3];
    const float* bk = (const float*)d_in[4];
    const float* qw = (const float*)d_in[5];
    const float* Wp = (const float*)d_in[6];
    const float* bp = (const float*)d_in[7];
    const float* Wo = (const float*)d_in[8];
    const float* bo = (const float*)d_in[9];
    float* out = (float*)d_out;
    (void)in_sizes; (void)n_in; (void)out_size;

    k_prep<<<129, 256>>>(Wq, bq, qw, bp, Wo, bo, Wp);
    {
        dim3 g(64, 8);
        k_pass1<<<g, 256>>>(x);
    }
    k_mid<<<72, 256>>>(Wq, bq, Wk, bk);
    {
        dim3 g(128, 8);
        k_pass2<<<g, 256>>>(x, out);
    }
}

// round 3
// speedup vs baseline: 1.9135x; 1.6998x over previous
#include <cuda_runtime.h>

#define Bsz 8
#define Nseq 16384
#define CIN 256     // DIM
#define Dd 512      // D
#define Hh 64       // DIM_HEAD
#define SCALEF 0.125f

// scratch (device globals; no allocation allowed)
__device__ __align__(16) float g_v[CIN];
__device__ float g_s0;
__device__ float g_c0[Hh];
__device__ __align__(16) float g_W1[Dd*Hh];
__device__ __align__(16) float g_A[CIN*Hh];
__device__ float g_ypart[Bsz*64*CIN];
__device__ float g_Spart[Bsz*64];
__device__ __align__(16) float g_M[Bsz*CIN*Hh];
__device__ float g_bias[Bsz*Hh];

__device__ __forceinline__ unsigned long long ffma2(unsigned long long a,
                                                    unsigned long long b,
                                                    unsigned long long c) {
    unsigned long long d;
    asm("fma.rn.f32x2 %0, %1, %2, %3;" : "=l"(d) : "l"(a), "l"(b), "l"(c));
    return d;
}

// ---------------------------------------------------------------------------
// k_prep (grid 129):
//   blocks 0..31  : v = Wq@qw
//   block  32     : s0 = bq.qw ; c0 = (bq+bp)@Wo + bo
//   blocks 33..96 : W1 = Wp@Wo   (8 rows per block)
//   blocks 97..128: A  = Wq@Wo   (8 rows per block)
// ---------------------------------------------------------------------------
__global__ void __launch_bounds__(256) k_prep(
        const float* __restrict__ Wq, const float* __restrict__ bq,
        const float* __restrict__ qw, const float* __restrict__ bp,
        const float* __restrict__ Wo, const float* __restrict__ bo,
        const float* __restrict__ Wp) {
    __shared__ float Ap[8*512];
    int tid = threadIdx.x;
    int lane = tid & 31;
    int bx = blockIdx.x;

    if (bx < 32) {
        int g = bx * 8 + (tid >> 5);
        const float* row = Wq + (size_t)g * Dd;
        float acc = 0.f;
        #pragma unroll
        for (int i = 0; i < 16; ++i) acc += row[lane + 32*i] * qw[lane + 32*i];
        #pragma unroll
        for (int o = 16; o; o >>= 1) acc += __shfl_xor_sync(0xffffffffu, acc, o);
        if (lane == 0) g_v[g] = acc;
        return;
    }
    if (bx == 32) {
        if (tid < 64) {
            float acc = bo[tid];
            #pragma unroll 8
            for (int d = 0; d < Dd; ++d) acc += (bq[d] + bp[d]) * Wo[d*Hh + tid];
            g_c0[tid] = acc;
        } else if (tid < 96) {
            float acc = 0.f;
            #pragma unroll
            for (int i = 0; i < 16; ++i) acc += bq[lane + 32*i] * qw[lane + 32*i];
            #pragma unroll
            for (int o = 16; o; o >>= 1) acc += __shfl_xor_sync(0xffffffffu, acc, o);
            if (lane == 0) g_s0 = acc;
        }
        return;
    }
    const float* Asrc;
    float* Cdst;
    if (bx < 97) {
        int r0 = (bx - 33) * 8;
        Asrc = Wp + (size_t)r0 * Dd;
        Cdst = g_W1 + (size_t)r0 * Hh;
    } else {
        int r0 = (bx - 97) * 8;
        Asrc = Wq + (size_t)r0 * Dd;
        Cdst = g_A + (size_t)r0 * Hh;
    }
    #pragma unroll
    for (int i = 0; i < 4; ++i)
        ((float4*)Ap)[tid + i*256] = ((const float4*)Asrc)[tid + i*256];
    __syncthreads();
    int c = tid & 63, rp = tid >> 6;
    const float* rowA = Ap + (2*rp) * 512;
    const float* rowB = rowA + 512;
    float acc0 = 0.f, acc1 = 0.f;
    #pragma unroll 8
    for (int k = 0; k < 512; ++k) {
        float w = Wo[k*Hh + c];
        acc0 += rowA[k] * w;
        acc1 += rowB[k] * w;
    }
    Cdst[(2*rp)*Hh + c]   = acc0;
    Cdst[(2*rp+1)*Hh + c] = acc1;
}

// ---------------------------------------------------------------------------
// pass 1: score_n = SCALE*(x_n.v + s0); y += score_n*x_n; S += score_n
// ---------------------------------------------------------------------------
__global__ void __launch_bounds__(256) k_pass1(const float* __restrict__ x) {
    __shared__ float y_sh[8][256];
    __shared__ float s_sh[8];
    int b = blockIdx.y;
    int tile = blockIdx.x;
    int warp = threadIdx.x >> 5, lane = threadIdx.x & 31;

    float4 v0 = *(const float4*)(g_v + 4*lane);
    float4 v1 = *(const float4*)(g_v + 128 + 4*lane);
    float s0 = g_s0;

    const float* xb = x + ((size_t)b*Nseq + (size_t)tile*256 + warp*32) * CIN;

    float y0[4] = {0,0,0,0}, y1[4] = {0,0,0,0};
    float Sacc = 0.f;
    #pragma unroll 4
    for (int t = 0; t < 32; ++t) {
        const float* xr = xb + t*CIN;
        float4 a0 = *(const float4*)(xr + 4*lane);
        float4 a1 = *(const float4*)(xr + 128 + 4*lane);
        float p = a0.x*v0.x + a0.y*v0.y + a0.z*v0.z + a0.w*v0.w
                + a1.x*v1.x + a1.y*v1.y + a1.z*v1.z + a1.w*v1.w;
        #pragma unroll
        for (int o = 16; o; o >>= 1) p += __shfl_xor_sync(0xffffffffu, p, o);
        float score = (p + s0) * SCALEF;
        Sacc += score;
        y0[0] += score*a0.x; y0[1] += score*a0.y; y0[2] += score*a0.z; y0[3] += score*a0.w;
        y1[0] += score*a1.x; y1[1] += score*a1.y; y1[2] += score*a1.z; y1[3] += score*a1.w;
    }
    #pragma unroll
    for (int j = 0; j < 4; ++j) {
        y_sh[warp][4*lane + j]       = y0[j];
        y_sh[warp][128 + 4*lane + j] = y1[j];
    }
    if (lane == 0) s_sh[warp] = Sacc;
    __syncthreads();
    int c = threadIdx.x;
    float acc = 0.f;
    #pragma unroll
    for (int w = 0; w < 8; ++w) acc += y_sh[w][c];
    g_ypart[((size_t)b*64 + tile)*256 + c] = acc;
    if (threadIdx.x == 0) {
        float s = 0.f;
        for (int w = 0; w < 8; ++w) s += s_sh[w];
        g_Spart[b*64 + tile] = s;
    }
}

// ---------------------------------------------------------------------------
// k_mid (grid 136 = 8 batches x 17 parts):
//   every block: reduce ypart -> y_s, S; compute aw_s[512] (redundant, cheap)
//   parts 0..15: 16-row tile of M_b = Wk @ diag(aw_b) @ W1 + A
//   part  16   : bias_b = (aw_b ⊙ bk) @ W1 + c0
// ---------------------------------------------------------------------------
__global__ void __launch_bounds__(256) k_mid(
        const float* __restrict__ Wq, const float* __restrict__ bq,
        const float* __restrict__ Wk, const float* __restrict__ bk) {
    __shared__ float y_s[256];
    __shared__ float aw_s[512];
    __shared__ float s_tmp[64];
    __shared__ float Wks[16][33];
    __shared__ float W1s[32][64];
    __shared__ float red[4][64];

    int tid = threadIdx.x;
    int b = blockIdx.x / 17;
    int part = blockIdx.x % 17;

    {
        const float* yp = g_ypart + (size_t)b*64*256 + tid;
        float acc = 0.f;
        #pragma unroll 8
        for (int p = 0; p < 64; ++p) acc += yp[p*256];
        y_s[tid] = acc;
    }
    if (tid < 64) s_tmp[tid] = g_Spart[b*64 + tid];
    __syncthreads();
    float S = 0.f;
    #pragma unroll
    for (int i = 0; i < 64; ++i) S += s_tmp[i];

    {
        float a0 = bq[tid] * S;
        float a1 = bq[tid + 256] * S;
        #pragma unroll 4
        for (int c = 0; c < 256; ++c) {
            float yc = y_s[c];
            a0 += yc * Wq[(size_t)c*Dd + tid];
            a1 += yc * Wq[(size_t)c*Dd + tid + 256];
        }
        aw_s[tid] = a0;
        aw_s[tid + 256] = a1;
    }
    __syncthreads();

    if (part == 16) {
        int h = tid & 63, seg = tid >> 6;
        float acc = 0.f;
        #pragma unroll 4
        for (int d = seg*128; d < seg*128 + 128; ++d)
            acc += aw_s[d] * bk[d] * g_W1[(size_t)d*Hh + h];
        red[seg][h] = acc;
        __syncthreads();
        if (tid < 64)
            g_bias[b*Hh + tid] = red[0][tid] + red[1][tid] + red[2][tid]
                               + red[3][tid] + g_c0[tid];
        return;
    }

    int r0 = part * 16;
    int tx = tid & 31, ty = tid >> 5;   // heads 2tx..2tx+1, rows 2ty..2ty+1
    float accm[2][2] = {};
    for (int kc = 0; kc < Dd; kc += 32) {
        __syncthreads();
        #pragma unroll
        for (int i = 0; i < 2; ++i) {
            int idx = tid + i*256;
            int r = idx >> 5, k = idx & 31;
            Wks[r][k] = Wk[(size_t)(r0 + r)*Dd + kc + k];
        }
        #pragma unroll
        for (int i = 0; i < 8; ++i) {
            int idx = tid + i*256;
            int k = idx >> 6, h = idx & 63;
            W1s[k][h] = g_W1[(size_t)(kc + k)*Hh + h] * aw_s[kc + k];
        }
        __syncthreads();
        #pragma unroll
        for (int k = 0; k < 32; ++k) {
            float bv0 = W1s[k][2*tx], bv1 = W1s[k][2*tx + 1];
            float a0 = Wks[2*ty][k], a1 = Wks[2*ty + 1][k];
            accm[0][0] += a0 * bv0;
            accm[0][1] += a0 * bv1;
            accm[1][0] += a1 * bv0;
            accm[1][1] += a1 * bv1;
        }
    }
    #pragma unroll
    for (int i = 0; i < 2; ++i) {
        int r = r0 + 2*ty + i;
        float* dst = g_M + ((size_t)b*CIN + r)*Hh + 2*tx;
        const float* addA = g_A + (size_t)r*Hh + 2*tx;
        dst[0] = accm[i][0] + addA[0];
        dst[1] = accm[i][1] + addA[1];
    }
}

// ---------------------------------------------------------------------------
// pass 2: out[b,n,:] = x[b,n,:] @ M_b + bias_b
// block: 256 tokens x 64 heads, 256 threads.
// thread: 2 tokens x 32 heads (register-resident acc, M broadcast from smem).
// x staged k-major (transposed) so the a-fragment is one conflict-free LDS.64.
// ---------------------------------------------------------------------------
#define XROW 260
__global__ void __launch_bounds__(256, 2) k_pass2(const float* __restrict__ x,
                                                  float* __restrict__ out) {
    __shared__ float x_s[16*XROW];   // 16 k-rows x 256 tokens (k-major)
    __shared__ float M_s[16*64];     // 16 k-rows x 64 heads
    __shared__ float bias_s[64];

    int tid = threadIdx.x;
    int b = blockIdx.y;
    int tok0 = blockIdx.x * 256;
    if (tid < 64) bias_s[tid] = g_bias[b*Hh + tid];

    int hc = tid >> 7;        // warp-uniform: warps 0-3 -> heads 0-31, warps 4-7 -> 32-63
    int tg = tid & 127;       // token pair: tokens 2tg, 2tg+1

    int tp = tid >> 2;        // staging: token-pair id 0..63
    int t4 = tid & 3;         // staging: k4 slot

    unsigned long long acc[32];
    #pragma unroll
    for (int i = 0; i < 32; ++i) acc[i] = 0ull;

    const float* xb = x + ((size_t)b*Nseq + tok0) * CIN;
    const float* Mb = g_M + (size_t)b*CIN*Hh;

    for (int kc = 0; kc < CIN; kc += 16) {
        __syncthreads();
        // stage x chunk transposed: x_s[k][tok], paired STS.64
        #pragma unroll
        for (int p = 0; p < 2; ++p) {
            int pair = tp + p*64;                       // 0..127
            const float* src = xb + (size_t)(2*pair)*CIN + kc + 4*t4;
            float4 va = *(const float4*)(src);
            float4 vb = *(const float4*)(src + CIN);
            *(float2*)(x_s + (4*t4+0)*XROW + 2*pair) = make_float2(va.x, vb.x);
            *(float2*)(x_s + (4*t4+1)*XROW + 2*pair) = make_float2(va.y, vb.y);
            *(float2*)(x_s + (4*t4+2)*XROW + 2*pair) = make_float2(va.z, vb.z);
            *(float2*)(x_s + (4*t4+3)*XROW + 2*pair) = make_float2(va.w, vb.w);
        }
        // stage M chunk: 16 x 64 floats = 256 float4
        ((float4*)M_s)[tid] = ((const float4*)(Mb + (size_t)kc*Hh))[tid];
        __syncthreads();
        #pragma unroll
        for (int k = 0; k < 16; ++k) {
            float2 a2 = *(const float2*)(x_s + k*XROW + 2*tg);
            unsigned long long x0p, x1p;
            asm("mov.b64 %0, {%1,%1};" : "=l"(x0p) : "r"(__float_as_uint(a2.x)));
            asm("mov.b64 %0, {%1,%1};" : "=l"(x1p) : "r"(__float_as_uint(a2.y)));
            const ulonglong2* Mc = (const ulonglong2*)(M_s + k*64 + hc*32);
            #pragma unroll
            for (int q = 0; q < 8; ++q) {
                ulonglong2 mp = Mc[q];                   // heads 4q..4q+3
                acc[2*q]      = ffma2(x0p, mp.x, acc[2*q]);
                acc[2*q+1]    = ffma2(x0p, mp.y, acc[2*q+1]);
                acc[16+2*q]   = ffma2(x1p, mp.x, acc[16+2*q]);
                acc[16+2*q+1] = ffma2(x1p, mp.y, acc[16+2*q+1]);
            }
        }
    }
    // epilogue: 2 tokens x 32 heads + bias
    float* o0 = out + ((size_t)b*Nseq + tok0 + 2*tg)*Hh + hc*32;
    float* o1 = o0 + Hh;
    #pragma unroll
    for (int q = 0; q < 8; ++q) {
        float b0 = bias_s[hc*32 + 4*q + 0];
        float b1 = bias_s[hc*32 + 4*q + 1];
        float b2 = bias_s[hc*32 + 4*q + 2];
        float b3 = bias_s[hc*32 + 4*q + 3];
        float2 p0 = *(float2*)&acc[2*q];
        float2 p1 = *(float2*)&acc[2*q+1];
        *(float4*)(o0 + 4*q) = make_float4(p0.x+b0, p0.y+b1, p1.x+b2, p1.y+b3);
        float2 q0 = *(float2*)&acc[16+2*q];
        float2 q1 = *(float2*)&acc[16+2*q+1];
        *(float4*)(o1 + 4*q) = make_float4(q0.x+b0, q0.y+b1, q1.x+b2, q1.y+b3);
    }
}

extern "C" void kernel_launch(void* const* d_in, const int* in_sizes, int n_in,
                              void* d_out, int out_size) {
    const float* x  = (const float*)d_in[0];
    const float* Wq = (const float*)d_in[1];
    const float* bq = (const float*)d_in[2];
    const float* Wk = (const float*)d_in[3];
    const float* bk = (const float*)d_in[4];
    const float* qw = (const float*)d_in[5];
    const float* Wp = (const float*)d_in[6];
    const float* bp = (const float*)d_in[7];
    const float* Wo = (const float*)d_in[8];
    const float* bo = (const float*)d_in[9];
    float* out = (float*)d_out;
    (void)in_sizes; (void)n_in; (void)out_size;

    k_prep<<<129, 256>>>(Wq, bq, qw, bp, Wo, bo, Wp);
    {
        dim3 g(64, 8);
        k_pass1<<<g, 256>>>(x);
    }
    k_mid<<<136, 256>>>(Wq, bq, Wk, bk);
    {
        dim3 g(64, 8);
        k_pass2<<<g, 256>>>(x, out);
    }
}

// round 5
// speedup vs baseline: 2.7139x; 1.4183x over previous
#include <cuda_runtime.h>
#include <cuda_bf16.h>
#include <cstdint>

#define Bsz 8
#define Nseq 16384
#define CIN 256     // DIM (= K of pass2 GEMM)
#define Dd 512      // D
#define Hh 64       // DIM_HEAD (= N of pass2 GEMM)
#define SCALEF 0.125f

// scratch (device globals; no allocation allowed)
__device__ __align__(16) float g_v[CIN];
__device__ float g_s0;
__device__ float g_c0[Hh];
__device__ __align__(16) float g_W1[Dd*Hh];
__device__ __align__(16) float g_A[CIN*Hh];
__device__ float g_ypart[Bsz*64*CIN];
__device__ float g_Spart[Bsz*64];
__device__ float g_bias[Bsz*Hh];
// B = M in mma.m16n8k16 b-fragment order: [b][kc(16)][j(8)][lane(32)][sel(2)] u32(bf16x2)
__device__ __align__(16) uint32_t g_BfH[Bsz*16*8*32*2];
__device__ __align__(16) uint32_t g_BfL[Bsz*16*8*32*2];

// pack two f32 -> bf16x2 (lo arg in low half)
__device__ __forceinline__ uint32_t pack2bf(float lo, float hi) {
    uint32_t r;
    asm("cvt.rn.bf16x2.f32 %0, %1, %2;" : "=r"(r) : "f"(hi), "f"(lo));
    return r;
}
__device__ __forceinline__ void mma16816(float* d, uint32_t a0, uint32_t a1,
                                         uint32_t a2, uint32_t a3,
                                         uint32_t b0, uint32_t b1) {
    asm volatile(
        "mma.sync.aligned.m16n8k16.row.col.f32.bf16.bf16.f32 "
        "{%0,%1,%2,%3}, {%4,%5,%6,%7}, {%8,%9}, {%0,%1,%2,%3};"
        : "+f"(d[0]), "+f"(d[1]), "+f"(d[2]), "+f"(d[3])
        : "r"(a0), "r"(a1), "r"(a2), "r"(a3), "r"(b0), "r"(b1));
}

// ---------------------------------------------------------------------------
// k_prep (grid 129): v = Wq@qw ; s0, c0 ; W1 = Wp@Wo ; A = Wq@Wo
// ---------------------------------------------------------------------------
__global__ void __launch_bounds__(256) k_prep(
        const float* __restrict__ Wq, const float* __restrict__ bq,
        const float* __restrict__ qw, const float* __restrict__ bp,
        const float* __restrict__ Wo, const float* __restrict__ bo,
        const float* __restrict__ Wp) {
    __shared__ float Ap[8*512];
    int tid = threadIdx.x;
    int lane = tid & 31;
    int bx = blockIdx.x;

    if (bx < 32) {
        int g = bx * 8 + (tid >> 5);
        const float* row = Wq + (size_t)g * Dd;
        float acc = 0.f;
        #pragma unroll
        for (int i = 0; i < 16; ++i) acc += row[lane + 32*i] * qw[lane + 32*i];
        #pragma unroll
        for (int o = 16; o; o >>= 1) acc += __shfl_xor_sync(0xffffffffu, acc, o);
        if (lane == 0) g_v[g] = acc;
        return;
    }
    if (bx == 32) {
        if (tid < 64) {
            float acc = bo[tid];
            #pragma unroll 8
            for (int d = 0; d < Dd; ++d) acc += (bq[d] + bp[d]) * Wo[d*Hh + tid];
            g_c0[tid] = acc;
        } else if (tid < 96) {
            float acc = 0.f;
            #pragma unroll
            for (int i = 0; i < 16; ++i) acc += bq[lane + 32*i] * qw[lane + 32*i];
            #pragma unroll
            for (int o = 16; o; o >>= 1) acc += __shfl_xor_sync(0xffffffffu, acc, o);
            if (lane == 0) g_s0 = acc;
        }
        return;
    }
    const float* Asrc;
    float* Cdst;
    if (bx < 97) {
        int r0 = (bx - 33) * 8;
        Asrc = Wp + (size_t)r0 * Dd;
        Cdst = g_W1 + (size_t)r0 * Hh;
    } else {
        int r0 = (bx - 97) * 8;
        Asrc = Wq + (size_t)r0 * Dd;
        Cdst = g_A + (size_t)r0 * Hh;
    }
    #pragma unroll
    for (int i = 0; i < 4; ++i)
        ((float4*)Ap)[tid + i*256] = ((const float4*)Asrc)[tid + i*256];
    __syncthreads();
    int c = tid & 63, rp = tid >> 6;
    const float* rowA = Ap + (2*rp) * 512;
    const float* rowB = rowA + 512;
    float acc0 = 0.f, acc1 = 0.f;
    #pragma unroll 8
    for (int k = 0; k < 512; ++k) {
        float w = Wo[k*Hh + c];
        acc0 += rowA[k] * w;
        acc1 += rowB[k] * w;
    }
    Cdst[(2*rp)*Hh + c]   = acc0;
    Cdst[(2*rp+1)*Hh + c] = acc1;
}

// ---------------------------------------------------------------------------
// pass 1: score_n = SCALE*(x_n.v + s0); y += score_n*x_n; S += score_n
// ---------------------------------------------------------------------------
__global__ void __launch_bounds__(256) k_pass1(const float* __restrict__ x) {
    __shared__ float y_sh[8][256];
    __shared__ float s_sh[8];
    int b = blockIdx.y;
    int tile = blockIdx.x;
    int warp = threadIdx.x >> 5, lane = threadIdx.x & 31;

    float4 v0 = *(const float4*)(g_v + 4*lane);
    float4 v1 = *(const float4*)(g_v + 128 + 4*lane);
    float s0 = g_s0;

    const float* xb = x + ((size_t)b*Nseq + (size_t)tile*256 + warp*32) * CIN;

    float y0[4] = {0,0,0,0}, y1[4] = {0,0,0,0};
    float Sacc = 0.f;
    #pragma unroll 4
    for (int t = 0; t < 32; ++t) {
        const float* xr = xb + t*CIN;
        float4 a0 = *(const float4*)(xr + 4*lane);
        float4 a1 = *(const float4*)(xr + 128 + 4*lane);
        float p = a0.x*v0.x + a0.y*v0.y + a0.z*v0.z + a0.w*v0.w
                + a1.x*v1.x + a1.y*v1.y + a1.z*v1.z + a1.w*v1.w;
        #pragma unroll
        for (int o = 16; o; o >>= 1) p += __shfl_xor_sync(0xffffffffu, p, o);
        float score = (p + s0) * SCALEF;
        Sacc += score;
        y0[0] += score*a0.x; y0[1] += score*a0.y; y0[2] += score*a0.z; y0[3] += score*a0.w;
        y1[0] += score*a1.x; y1[1] += score*a1.y; y1[2] += score*a1.z; y1[3] += score*a1.w;
    }
    #pragma unroll
    for (int j = 0; j < 4; ++j) {
        y_sh[warp][4*lane + j]       = y0[j];
        y_sh[warp][128 + 4*lane + j] = y1[j];
    }
    if (lane == 0) s_sh[warp] = Sacc;
    __syncthreads();
    int c = threadIdx.x;
    float acc = 0.f;
    #pragma unroll
    for (int w = 0; w < 8; ++w) acc += y_sh[w][c];
    g_ypart[((size_t)b*64 + tile)*256 + c] = acc;
    if (threadIdx.x == 0) {
        float s = 0.f;
        for (int w = 0; w < 8; ++w) s += s_sh[w];
        g_Spart[b*64 + tile] = s;
    }
}

// ---------------------------------------------------------------------------
// k_mid (grid 136 = 8 batches x 17 parts):
//   every block: reduce ypart -> y_s, S; compute aw_s[512]
//   parts 0..15: 16-row tile of M_b = Wk @ diag(aw_b) @ W1 + A,
//                emitted as bf16 hi/lo in mma b-fragment order (g_BfH/g_BfL)
//   part  16   : bias_b = (aw_b ⊙ bk) @ W1 + c0
// ---------------------------------------------------------------------------
__global__ void __launch_bounds__(256) k_mid(
        const float* __restrict__ Wq, const float* __restrict__ bq,
        const float* __restrict__ Wk, const float* __restrict__ bk) {
    __shared__ float y_s[256];
    __shared__ float aw_s[512];
    __shared__ float s_tmp[64];
    __shared__ float Wks[16][33];
    __shared__ float W1s[32][64];
    __shared__ float red[4][64];

    int tid = threadIdx.x;
    int b = blockIdx.x / 17;
    int part = blockIdx.x % 17;

    {
        const float* yp = g_ypart + (size_t)b*64*256 + tid;
        float acc = 0.f;
        #pragma unroll 8
        for (int p = 0; p < 64; ++p) acc += yp[p*256];
        y_s[tid] = acc;
    }
    if (tid < 64) s_tmp[tid] = g_Spart[b*64 + tid];
    __syncthreads();
    float S = 0.f;
    #pragma unroll
    for (int i = 0; i < 64; ++i) S += s_tmp[i];

    {
        float a0 = bq[tid] * S;
        float a1 = bq[tid + 256] * S;
        #pragma unroll 4
        for (int c = 0; c < 256; ++c) {
            float yc = y_s[c];
            a0 += yc * Wq[(size_t)c*Dd + tid];
            a1 += yc * Wq[(size_t)c*Dd + tid + 256];
        }
        aw_s[tid] = a0;
        aw_s[tid + 256] = a1;
    }
    __syncthreads();

    if (part == 16) {
        int h = tid & 63, seg = tid >> 6;
        float acc = 0.f;
        #pragma unroll 4
        for (int d = seg*128; d < seg*128 + 128; ++d)
            acc += aw_s[d] * bk[d] * g_W1[(size_t)d*Hh + h];
        red[seg][h] = acc;
        __syncthreads();
        if (tid < 64)
            g_bias[b*Hh + tid] = red[0][tid] + red[1][tid] + red[2][tid]
                               + red[3][tid] + g_c0[tid];
        return;
    }

    int r0 = part * 16;
    int tx = tid & 31, ty = tid >> 5;   // heads 2tx..2tx+1, k-rows 2ty..2ty+1
    float accm[2][2] = {};
    for (int kc = 0; kc < Dd; kc += 32) {
        __syncthreads();
        #pragma unroll
        for (int i = 0; i < 2; ++i) {
            int idx = tid + i*256;
            int r = idx >> 5, k = idx & 31;
            Wks[r][k] = Wk[(size_t)(r0 + r)*Dd + kc + k];
        }
        #pragma unroll
        for (int i = 0; i < 8; ++i) {
            int idx = tid + i*256;
            int k = idx >> 6, h = idx & 63;
            W1s[k][h] = g_W1[(size_t)(kc + k)*Hh + h] * aw_s[kc + k];
        }
        __syncthreads();
        #pragma unroll
        for (int k = 0; k < 32; ++k) {
            float bv0 = W1s[k][2*tx], bv1 = W1s[k][2*tx + 1];
            float a0 = Wks[2*ty][k], a1 = Wks[2*ty + 1][k];
            accm[0][0] += a0 * bv0;
            accm[0][1] += a0 * bv1;
            accm[1][0] += a1 * bv0;
            accm[1][1] += a1 * bv1;
        }
    }
    // emit b-fragments: thread holds k-pair (r, r+1) for heads h, h+1
    {
        int r = r0 + 2*ty;                  // even k index
        int kc16 = r >> 4;
        int kk = r & 15;
        int tig = (kk >> 1) & 3;
        int sel = kk >> 3;
        #pragma unroll
        for (int jj = 0; jj < 2; ++jj) {
            int h = 2*tx + jj;
            float m0 = accm[0][jj] + g_A[(size_t)r*Hh + h];
            float m1 = accm[1][jj] + g_A[(size_t)(r+1)*Hh + h];
            uint32_t hp = pack2bf(m0, m1);
            float l0 = m0 - __uint_as_float(hp << 16);
            float l1 = m1 - __uint_as_float(hp & 0xFFFF0000u);
            uint32_t lp = pack2bf(l0, l1);
            int lanef = (h & 7)*4 + tig;
            int j = h >> 3;
            size_t idx = ((((size_t)b*16 + kc16)*8 + j)*32 + lanef)*2 + sel;
            g_BfH[idx] = hp;
            g_BfL[idx] = lp;
        }
    }
}

// ---------------------------------------------------------------------------
// pass 2 (mma.sync m16n8k16 bf16, 3-term split): out = x @ M_b + bias_b
// CTA: 128 tokens x 64 heads, 8 warps; warp: 16 tokens x 64 heads.
// A fragments straight from gmem (fp32 -> bf16 hi/lo in regs, no smem);
// B fragments pre-packed by k_mid, staged in smem once per CTA.
// ---------------------------------------------------------------------------
#define P2_SMEM (65536 + 256)
__global__ void __launch_bounds__(256, 2) k_pass2(const float* __restrict__ x,
                                                  float* __restrict__ out) {
    extern __shared__ char sm[];
    uint32_t* BsH = (uint32_t*)sm;              // [kc][j][lane][sel] : 32 KB
    uint32_t* BsL = (uint32_t*)(sm + 32768);    // 32 KB
    float* bias_s = (float*)(sm + 65536);

    int tid = threadIdx.x;
    int w = tid >> 5, lane = tid & 31;
    int b = blockIdx.y;
    int tok0 = blockIdx.x * 128;

    // stage B fragments + bias
    {
        const uint4* srcH = (const uint4*)(g_BfH + (size_t)b*8192);
        const uint4* srcL = (const uint4*)(g_BfL + (size_t)b*8192);
        #pragma unroll
        for (int i = 0; i < 8; ++i) {
            ((uint4*)BsH)[tid + i*256] = srcH[tid + i*256];
            ((uint4*)BsL)[tid + i*256] = srcL[tid + i*256];
        }
        if (tid < 64) bias_s[tid] = g_bias[b*Hh + tid];
    }
    __syncthreads();

    int rrow = lane >> 2;           // 0..7
    int tig = lane & 3;
    const float* xr0 = x + ((size_t)b*Nseq + tok0 + w*16 + rrow)*CIN + tig*2;
    const float* xr8 = xr0 + 8*CIN;

    float acc[8][4];
    #pragma unroll
    for (int j = 0; j < 8; ++j)
        #pragma unroll
        for (int q = 0; q < 4; ++q) acc[j][q] = 0.f;

    #pragma unroll 2
    for (int kc = 0; kc < 16; ++kc) {
        int c0 = kc * 16;
        float2 v0 = *(const float2*)(xr0 + c0);        // (r,   c0..c0+1)
        float2 v1 = *(const float2*)(xr8 + c0);        // (r+8, c0..c0+1)
        float2 v2 = *(const float2*)(xr0 + c0 + 8);    // (r,   c0+8..9)
        float2 v3 = *(const float2*)(xr8 + c0 + 8);    // (r+8, c0+8..9)

        uint32_t aH0 = pack2bf(v0.x, v0.y);
        uint32_t aH1 = pack2bf(v1.x, v1.y);
        uint32_t aH2 = pack2bf(v2.x, v2.y);
        uint32_t aH3 = pack2bf(v3.x, v3.y);
        uint32_t aL0 = pack2bf(v0.x - __uint_as_float(aH0 << 16),
                               v0.y - __uint_as_float(aH0 & 0xFFFF0000u));
        uint32_t aL1 = pack2bf(v1.x - __uint_as_float(aH1 << 16),
                               v1.y - __uint_as_float(aH1 & 0xFFFF0000u));
        uint32_t aL2 = pack2bf(v2.x - __uint_as_float(aH2 << 16),
                               v2.y - __uint_as_float(aH2 & 0xFFFF0000u));
        uint32_t aL3 = pack2bf(v3.x - __uint_as_float(aH3 << 16),
                               v3.y - __uint_as_float(aH3 & 0xFFFF0000u));

        const uint32_t* bh = BsH + (kc*8*32 + lane)*2;
        const uint32_t* bl = BsL + (kc*8*32 + lane)*2;
        #pragma unroll
        for (int j = 0; j < 8; ++j) {
            uint2 bhj = *(const uint2*)(bh + j*64);
            uint2 blj = *(const uint2*)(bl + j*64);
            mma16816(acc[j], aH0, aH1, aH2, aH3, bhj.x, bhj.y);
            mma16816(acc[j], aL0, aL1, aL2, aL3, bhj.x, bhj.y);
            mma16816(acc[j], aH0, aH1, aH2, aH3, blj.x, blj.y);
        }
    }

    // epilogue: rows r=tok0+w*16+rrow (+8), cols (tig*2 + 8j, +1)
    float* o0 = out + ((size_t)b*Nseq + tok0 + w*16 + rrow)*Hh + tig*2;
    float* o8 = o0 + 8*Hh;
    #pragma unroll
    for (int j = 0; j < 8; ++j) {
        float2 bj = *(const float2*)(bias_s + tig*2 + 8*j);
        *(float2*)(o0 + 8*j) = make_float2(acc[j][0] + bj.x, acc[j][1] + bj.y);
        *(float2*)(o8 + 8*j) = make_float2(acc[j][2] + bj.x, acc[j][3] + bj.y);
    }
}

extern "C" void kernel_launch(void* const* d_in, const int* in_sizes, int n_in,
                              void* d_out, int out_size) {
    const float* x  = (const float*)d_in[0];
    const float* Wq = (const float*)d_in[1];
    const float* bq = (const float*)d_in[2];
    const float* Wk = (const float*)d_in[3];
    const float* bk = (const float*)d_in[4];
    const float* qw = (const float*)d_in[5];
    const float* Wp = (const float*)d_in[6];
    const float* bp = (const float*)d_in[7];
    const float* Wo = (const float*)d_in[8];
    const float* bo = (const float*)d_in[9];
    float* out = (float*)d_out;
    (void)in_sizes; (void)n_in; (void)out_size;

    cudaFuncSetAttribute(k_pass2, cudaFuncAttributeMaxDynamicSharedMemorySize, P2_SMEM);

    k_prep<<<129, 256>>>(Wq, bq, qw, bp, Wo, bo, Wp);
    {
        dim3 g(64, 8);
        k_pass1<<<g, 256>>>(x);
    }
    k_mid<<<136, 256>>>(Wq, bq, Wk, bk);
    {
        dim3 g(128, 8);
        k_pass2<<<g, 256, P2_SMEM>>>(x, out);
    }
}

// round 6
// speedup vs baseline: 2.7230x; 1.0034x over previous
#include <cuda_runtime.h>
#include <cuda_bf16.h>
#include <cstdint>

#define Bsz 8
#define Nseq 16384
#define CIN 256     // DIM (= K of pass2 GEMM)
#define Dd 512      // D
#define Hh 64       // DIM_HEAD (= N of pass2 GEMM)
#define SCALEF 0.125f

// scratch (device globals; no allocation allowed)
__device__ __align__(16) float g_v[CIN];
__device__ float g_s0;
__device__ float g_c0[Hh];
__device__ __align__(16) float g_W1[Dd*Hh];
__device__ __align__(16) float g_A[CIN*Hh];
__device__ float g_ypart[Bsz*128*CIN];
__device__ float g_Spart[Bsz*128];
__device__ float g_bias[Bsz*Hh];
// B = M in mma.m16n8k16 b-fragment order: [b][kc(16)][j(8)][lane(32)][sel(2)] u32(bf16x2)
__device__ __align__(16) uint32_t g_BfH[Bsz*16*8*32*2];
__device__ __align__(16) uint32_t g_BfL[Bsz*16*8*32*2];

// pack two f32 -> bf16x2 (lo arg in low half)
__device__ __forceinline__ uint32_t pack2bf(float lo, float hi) {
    uint32_t r;
    asm("cvt.rn.bf16x2.f32 %0, %1, %2;" : "=r"(r) : "f"(hi), "f"(lo));
    return r;
}
__device__ __forceinline__ void mma16816(float* d, uint32_t a0, uint32_t a1,
                                         uint32_t a2, uint32_t a3,
                                         uint32_t b0, uint32_t b1) {
    asm volatile(
        "mma.sync.aligned.m16n8k16.row.col.f32.bf16.bf16.f32 "
        "{%0,%1,%2,%3}, {%4,%5,%6,%7}, {%8,%9}, {%0,%1,%2,%3};"
        : "+f"(d[0]), "+f"(d[1]), "+f"(d[2]), "+f"(d[3])
        : "r"(a0), "r"(a1), "r"(a2), "r"(a3), "r"(b0), "r"(b1));
}

// ---------------------------------------------------------------------------
// k_prep (grid 225):
//   blocks 0..31   : v = Wq@qw (8 rows per block)
//   block  32      : s0 = bq.qw ; c0 = (bq+bp)@Wo + bo
//   blocks 33..160 : W1 = Wp@Wo, 4-row tiles (smem-staged Wo)
//   blocks 161..224: A  = Wq@Wo, 4-row tiles
// ---------------------------------------------------------------------------
__global__ void __launch_bounds__(256) k_prep(
        const float* __restrict__ Wq, const float* __restrict__ bq,
        const float* __restrict__ qw, const float* __restrict__ bp,
        const float* __restrict__ Wo, const float* __restrict__ bo,
        const float* __restrict__ Wp) {
    __shared__ float As4[4*512];   // 8 KB
    __shared__ float Wos[64*64];   // 16 KB
    int tid = threadIdx.x;
    int lane = tid & 31;
    int bx = blockIdx.x;

    if (bx < 32) {
        int g = bx * 8 + (tid >> 5);
        const float* row = Wq + (size_t)g * Dd;
        float acc = 0.f;
        #pragma unroll
        for (int i = 0; i < 16; ++i) acc += row[lane + 32*i] * qw[lane + 32*i];
        #pragma unroll
        for (int o = 16; o; o >>= 1) acc += __shfl_xor_sync(0xffffffffu, acc, o);
        if (lane == 0) g_v[g] = acc;
        return;
    }
    if (bx == 32) {
        if (tid < 64) {
            float acc = bo[tid];
            #pragma unroll 8
            for (int d = 0; d < Dd; ++d) acc += (bq[d] + bp[d]) * Wo[d*Hh + tid];
            g_c0[tid] = acc;
        } else if (tid < 96) {
            float acc = 0.f;
            #pragma unroll
            for (int i = 0; i < 16; ++i) acc += bq[lane + 32*i] * qw[lane + 32*i];
            #pragma unroll
            for (int o = 16; o; o >>= 1) acc += __shfl_xor_sync(0xffffffffu, acc, o);
            if (lane == 0) g_s0 = acc;
        }
        return;
    }
    const float* Asrc;
    float* Cdst;
    if (bx < 161) {
        int r0 = (bx - 33) * 4;
        Asrc = Wp + (size_t)r0 * Dd;
        Cdst = g_W1 + (size_t)r0 * Hh;
    } else {
        int r0 = (bx - 161) * 4;
        Asrc = Wq + (size_t)r0 * Dd;
        Cdst = g_A + (size_t)r0 * Hh;
    }
    #pragma unroll
    for (int i = 0; i < 2; ++i)
        ((float4*)As4)[tid + i*256] = ((const float4*)Asrc)[tid + i*256];

    int h = tid & 63, rp = tid >> 6;
    float acc = 0.f;
    for (int kc = 0; kc < 8; ++kc) {
        __syncthreads();
        const float4* src = (const float4*)(Wo + (size_t)(kc*64)*Hh);
        #pragma unroll
        for (int i = 0; i < 4; ++i)
            ((float4*)Wos)[tid + i*256] = src[tid + i*256];
        __syncthreads();
        const float* ar = As4 + rp*512 + kc*64;
        #pragma unroll 16
        for (int k = 0; k < 64; ++k)
            acc += ar[k] * Wos[k*64 + h];
    }
    Cdst[rp*Hh + h] = acc;
}

// ---------------------------------------------------------------------------
// pass 1 (grid (128, 8)): per block 128 tokens; warp = 16 tokens in 4 batches
// of 4 (interleaved butterfly reductions for ILP).
//   score_n = SCALE*(x_n.v + s0); y += score_n*x_n; S += score_n
// ---------------------------------------------------------------------------
__global__ void __launch_bounds__(256) k_pass1(const float* __restrict__ x) {
    __shared__ float y_sh[8][256];
    __shared__ float s_sh[8];
    int b = blockIdx.y;
    int tile = blockIdx.x;
    int warp = threadIdx.x >> 5, lane = threadIdx.x & 31;

    float4 v0 = *(const float4*)(g_v + 4*lane);
    float4 v1 = *(const float4*)(g_v + 128 + 4*lane);
    float s0 = g_s0;

    const float* xb = x + ((size_t)b*Nseq + (size_t)tile*128 + warp*16) * CIN;

    float y0[4] = {0,0,0,0}, y1[4] = {0,0,0,0};
    float Sacc = 0.f;
    #pragma unroll
    for (int g = 0; g < 4; ++g) {
        float4 A0[4], A1[4];
        #pragma unroll
        for (int u = 0; u < 4; ++u) {
            const float* xr = xb + (size_t)(g*4 + u)*CIN;
            A0[u] = *(const float4*)(xr + 4*lane);
            A1[u] = *(const float4*)(xr + 128 + 4*lane);
        }
        float p[4];
        #pragma unroll
        for (int u = 0; u < 4; ++u)
            p[u] = A0[u].x*v0.x + A0[u].y*v0.y + A0[u].z*v0.z + A0[u].w*v0.w
                 + A1[u].x*v1.x + A1[u].y*v1.y + A1[u].z*v1.z + A1[u].w*v1.w;
        #pragma unroll
        for (int o = 16; o; o >>= 1) {
            #pragma unroll
            for (int u = 0; u < 4; ++u)
                p[u] += __shfl_xor_sync(0xffffffffu, p[u], o);
        }
        #pragma unroll
        for (int u = 0; u < 4; ++u) {
            float score = (p[u] + s0) * SCALEF;
            Sacc += score;
            y0[0] += score*A0[u].x; y0[1] += score*A0[u].y;
            y0[2] += score*A0[u].z; y0[3] += score*A0[u].w;
            y1[0] += score*A1[u].x; y1[1] += score*A1[u].y;
            y1[2] += score*A1[u].z; y1[3] += score*A1[u].w;
        }
    }
    #pragma unroll
    for (int j = 0; j < 4; ++j) {
        y_sh[warp][4*lane + j]       = y0[j];
        y_sh[warp][128 + 4*lane + j] = y1[j];
    }
    if (lane == 0) s_sh[warp] = Sacc;
    __syncthreads();
    int c = threadIdx.x;
    float acc = 0.f;
    #pragma unroll
    for (int w = 0; w < 8; ++w) acc += y_sh[w][c];
    g_ypart[((size_t)b*128 + tile)*256 + c] = acc;
    if (threadIdx.x == 0) {
        float s = 0.f;
        for (int w = 0; w < 8; ++w) s += s_sh[w];
        g_Spart[b*128 + tile] = s;
    }
}

// ---------------------------------------------------------------------------
// k_mid (grid 264 = 8 batches x 33 parts):
//   every block: reduce ypart -> y_s, S; compute aw_s[512] (redundant)
//   parts 0..31: 8-row tile of M_b = Wk @ diag(aw_b) @ W1 + A, emitted as
//                bf16 hi/lo mma b-fragments (g_BfH/g_BfL)
//   part  32   : bias_b = (aw_b ⊙ bk) @ W1 + c0
// ---------------------------------------------------------------------------
__global__ void __launch_bounds__(256) k_mid(
        const float* __restrict__ Wq, const float* __restrict__ bq,
        const float* __restrict__ Wk, const float* __restrict__ bk) {
    __shared__ float y_s[256];
    __shared__ float aw_s[512];
    __shared__ float s_tmp[128];
    __shared__ float Wks[8][33];
    __shared__ float W1s[32][64];
    __shared__ float red[4][64];

    int tid = threadIdx.x;
    int b = blockIdx.x / 33;
    int part = blockIdx.x % 33;

    {
        const float* yp = g_ypart + (size_t)b*128*256 + tid;
        float acc = 0.f;
        #pragma unroll 8
        for (int p = 0; p < 128; ++p) acc += yp[(size_t)p*256];
        y_s[tid] = acc;
    }
    if (tid < 128) s_tmp[tid] = g_Spart[b*128 + tid];
    __syncthreads();
    float S = 0.f;
    #pragma unroll
    for (int i = 0; i < 128; ++i) S += s_tmp[i];

    {
        float a0 = bq[tid] * S;
        float a1 = bq[tid + 256] * S;
        #pragma unroll 4
        for (int c = 0; c < 256; ++c) {
            float yc = y_s[c];
            a0 += yc * Wq[(size_t)c*Dd + tid];
            a1 += yc * Wq[(size_t)c*Dd + tid + 256];
        }
        aw_s[tid] = a0;
        aw_s[tid + 256] = a1;
    }
    __syncthreads();

    if (part == 32) {
        int h = tid & 63, seg = tid >> 6;
        float acc = 0.f;
        #pragma unroll 4
        for (int d = seg*128; d < seg*128 + 128; ++d)
            acc += aw_s[d] * bk[d] * g_W1[(size_t)d*Hh + h];
        red[seg][h] = acc;
        __syncthreads();
        if (tid < 64)
            g_bias[b*Hh + tid] = red[0][tid] + red[1][tid] + red[2][tid]
                               + red[3][tid] + g_c0[tid];
        return;
    }

    int r0 = part * 8;                 // 8 k-rows of M
    int h = tid & 63;                  // head
    int pr = tid >> 6;                 // k-pair 0..3 -> rows 2pr, 2pr+1
    float acc0 = 0.f, acc1 = 0.f;
    for (int kc = 0; kc < Dd; kc += 32) {
        __syncthreads();
        {
            int r = tid >> 5, k = tid & 31;
            Wks[r][k] = Wk[(size_t)(r0 + r)*Dd + kc + k];
        }
        #pragma unroll
        for (int i = 0; i < 8; ++i) {
            int idx = tid + i*256;
            int k = idx >> 6, hh = idx & 63;
            W1s[k][hh] = g_W1[(size_t)(kc + k)*Hh + hh] * aw_s[kc + k];
        }
        __syncthreads();
        #pragma unroll
        for (int k = 0; k < 32; ++k) {
            float bv = W1s[k][h];
            acc0 += Wks[2*pr][k]     * bv;
            acc1 += Wks[2*pr + 1][k] * bv;
        }
    }
    // emit b-fragment pair for k-rows (r, r+1), head h
    {
        int r = r0 + 2*pr;                  // even global k index
        int kc16 = r >> 4;
        int kk = r & 15;
        int tig = (kk >> 1) & 3;
        int sel = kk >> 3;
        float m0 = acc0 + g_A[(size_t)r*Hh + h];
        float m1 = acc1 + g_A[(size_t)(r+1)*Hh + h];
        uint32_t hp = pack2bf(m0, m1);
        float l0 = m0 - __uint_as_float(hp << 16);
        float l1 = m1 - __uint_as_float(hp & 0xFFFF0000u);
        uint32_t lp = pack2bf(l0, l1);
        int lanef = (h & 7)*4 + tig;
        int j = h >> 3;
        size_t idx = ((((size_t)b*16 + kc16)*8 + j)*32 + lanef)*2 + sel;
        g_BfH[idx] = hp;
        g_BfL[idx] = lp;
    }
}

// ---------------------------------------------------------------------------
// pass 2 (mma.sync m16n8k16 bf16, 3-term split): out = x @ M_b + bias_b
// CTA: 128 tokens x 64 heads, 8 warps; warp: 16 tokens x 64 heads.
// A fragments straight from gmem with 1-chunk software prefetch;
// B fragments pre-packed by k_mid, staged in smem once per CTA.
// Tile order reversed so pass2 starts on the x region pass1 left hot in L2.
// ---------------------------------------------------------------------------
#define P2_SMEM (65536 + 256)
__global__ void __launch_bounds__(256, 2) k_pass2(const float* __restrict__ x,
                                                  float* __restrict__ out) {
    extern __shared__ char sm[];
    uint32_t* BsH = (uint32_t*)sm;              // [kc][j][lane][sel] : 32 KB
    uint32_t* BsL = (uint32_t*)(sm + 32768);    // 32 KB
    float* bias_s = (float*)(sm + 65536);

    int tid = threadIdx.x;
    int w = tid >> 5, lane = tid & 31;
    int b = blockIdx.y;
    int tile = gridDim.x - 1 - blockIdx.x;      // reversed for L2 reuse
    int tok0 = tile * 128;

    // stage B fragments + bias
    {
        const uint4* srcH = (const uint4*)(g_BfH + (size_t)b*8192);
        const uint4* srcL = (const uint4*)(g_BfL + (size_t)b*8192);
        #pragma unroll
        for (int i = 0; i < 8; ++i) {
            ((uint4*)BsH)[tid + i*256] = srcH[tid + i*256];
            ((uint4*)BsL)[tid + i*256] = srcL[tid + i*256];
        }
        if (tid < 64) bias_s[tid] = g_bias[b*Hh + tid];
    }
    __syncthreads();

    int rrow = lane >> 2;           // 0..7
    int tig = lane & 3;
    const float* xr0 = x + ((size_t)b*Nseq + tok0 + w*16 + rrow)*CIN + tig*2;
    const float* xr8 = xr0 + 8*CIN;

    float acc[8][4];
    #pragma unroll
    for (int j = 0; j < 8; ++j)
        #pragma unroll
        for (int q = 0; q < 4; ++q) acc[j][q] = 0.f;

    // prologue loads (kc = 0)
    float2 v0 = *(const float2*)(xr0);
    float2 v1 = *(const float2*)(xr8);
    float2 v2 = *(const float2*)(xr0 + 8);
    float2 v3 = *(const float2*)(xr8 + 8);

    #pragma unroll 4
    for (int kc = 0; kc < 16; ++kc) {
        float2 n0, n1, n2, n3;
        if (kc < 15) {
            int c1 = (kc + 1) * 16;
            n0 = *(const float2*)(xr0 + c1);
            n1 = *(const float2*)(xr8 + c1);
            n2 = *(const float2*)(xr0 + c1 + 8);
            n3 = *(const float2*)(xr8 + c1 + 8);
        }
        uint32_t aH0 = pack2bf(v0.x, v0.y);
        uint32_t aH1 = pack2bf(v1.x, v1.y);
        uint32_t aH2 = pack2bf(v2.x, v2.y);
        uint32_t aH3 = pack2bf(v3.x, v3.y);
        uint32_t aL0 = pack2bf(v0.x - __uint_as_float(aH0 << 16),
                               v0.y - __uint_as_float(aH0 & 0xFFFF0000u));
        uint32_t aL1 = pack2bf(v1.x - __uint_as_float(aH1 << 16),
                               v1.y - __uint_as_float(aH1 & 0xFFFF0000u));
        uint32_t aL2 = pack2bf(v2.x - __uint_as_float(aH2 << 16),
                               v2.y - __uint_as_float(aH2 & 0xFFFF0000u));
        uint32_t aL3 = pack2bf(v3.x - __uint_as_float(aH3 << 16),
                               v3.y - __uint_as_float(aH3 & 0xFFFF0000u));

        const uint32_t* bh = BsH + (kc*8*32 + lane)*2;
        const uint32_t* bl = BsL + (kc*8*32 + lane)*2;
        #pragma unroll
        for (int j = 0; j < 8; ++j) {
            uint2 bhj = *(const uint2*)(bh + j*64);
            uint2 blj = *(const uint2*)(bl + j*64);
            mma16816(acc[j], aH0, aH1, aH2, aH3, bhj.x, bhj.y);
            mma16816(acc[j], aL0, aL1, aL2, aL3, bhj.x, bhj.y);
            mma16816(acc[j], aH0, aH1, aH2, aH3, blj.x, blj.y);
        }
        v0 = n0; v1 = n1; v2 = n2; v3 = n3;
    }

    // epilogue: rows r=tok0+w*16+rrow (+8), cols (tig*2 + 8j, +1)
    float* o0 = out + ((size_t)b*Nseq + tok0 + w*16 + rrow)*Hh + tig*2;
    float* o8 = o0 + 8*Hh;
    #pragma unroll
    for (int j = 0; j < 8; ++j) {
        float2 bj = *(const float2*)(bias_s + tig*2 + 8*j);
        *(float2*)(o0 + 8*j) = make_float2(acc[j][0] + bj.x, acc[j][1] + bj.y);
        *(float2*)(o8 + 8*j) = make_float2(acc[j][2] + bj.x, acc[j][3] + bj.y);
    }
}

extern "C" void kernel_launch(void* const* d_in, const int* in_sizes, int n_in,
                              void* d_out, int out_size) {
    const float* x  = (const float*)d_in[0];
    const float* Wq = (const float*)d_in[1];
    const float* bq = (const float*)d_in[2];
    const float* Wk = (const float*)d_in[3];
    const float* bk = (const float*)d_in[4];
    const float* qw = (const float*)d_in[5];
    const float* Wp = (const float*)d_in[6];
    const float* bp = (const float*)d_in[7];
    const float* Wo = (const float*)d_in[8];
    const float* bo = (const float*)d_in[9];
    float* out = (float*)d_out;
    (void)in_sizes; (void)n_in; (void)out_size;

    cudaFuncSetAttribute(k_pass2, cudaFuncAttributeMaxDynamicSharedMemorySize, P2_SMEM);

    k_prep<<<225, 256>>>(Wq, bq, qw, bp, Wo, bo, Wp);
    {
        dim3 g(128, 8);
        k_pass1<<<g, 256>>>(x);
    }
    k_mid<<<264, 256>>>(Wq, bq, Wk, bk);
    {
        dim3 g(128, 8);
        k_pass2<<<g, 256, P2_SMEM>>>(x, out);
    }
}

// round 7
// speedup vs baseline: 2.9717x; 1.0913x over previous
#include <cuda_runtime.h>
#include <cuda_bf16.h>
#include <cstdint>

#define Bsz 8
#define Nseq 16384
#define CIN 256     // DIM (= K of pass2 GEMM)
#define Dd 512      // D
#define Hh 64       // DIM_HEAD (= N of pass2 GEMM)
#define SCALEF 0.125f

// scratch (device globals; no allocation allowed)
__device__ __align__(16) float g_v[CIN];
__device__ float g_s0;
__device__ float g_c0[Hh];
__device__ __align__(16) float g_W1[Dd*Hh];
__device__ __align__(16) float g_A[CIN*Hh];
__device__ float g_ypart[Bsz*128*CIN];
__device__ float g_Spart[Bsz*128];
__device__ __align__(16) float g_aw[Bsz*Dd];
__device__ float g_bias[Bsz*Hh];
// B = M in mma.m16n8k16 b-fragment order: [b][kc(16)][j(8)][lane(32)][sel(2)] u32(bf16x2)
__device__ __align__(16) uint32_t g_BfH[Bsz*16*8*32*2];
__device__ __align__(16) uint32_t g_BfL[Bsz*16*8*32*2];

// pack two f32 -> bf16x2 (lo arg in low half)
__device__ __forceinline__ uint32_t pack2bf(float lo, float hi) {
    uint32_t r;
    asm("cvt.rn.bf16x2.f32 %0, %1, %2;" : "=r"(r) : "f"(hi), "f"(lo));
    return r;
}
__device__ __forceinline__ void mma16816(float* d, uint32_t a0, uint32_t a1,
                                         uint32_t a2, uint32_t a3,
                                         uint32_t b0, uint32_t b1) {
    asm volatile(
        "mma.sync.aligned.m16n8k16.row.col.f32.bf16.bf16.f32 "
        "{%0,%1,%2,%3}, {%4,%5,%6,%7}, {%8,%9}, {%0,%1,%2,%3};"
        : "+f"(d[0]), "+f"(d[1]), "+f"(d[2]), "+f"(d[3])
        : "r"(a0), "r"(a1), "r"(a2), "r"(a3), "r"(b0), "r"(b1));
}

// ---------------------------------------------------------------------------
// k_prep (grid 225):
//   blocks 0..31   : v = Wq@qw (8 rows per block)
//   block  32      : s0 = bq.qw ; c0 = (bq+bp)@Wo + bo
//   blocks 33..160 : W1 = Wp@Wo, 4-row tiles (smem-staged Wo)
//   blocks 161..224: A  = Wq@Wo, 4-row tiles
// ---------------------------------------------------------------------------
__global__ void __launch_bounds__(256) k_prep(
        const float* __restrict__ Wq, const float* __restrict__ bq,
        const float* __restrict__ qw, const float* __restrict__ bp,
        const float* __restrict__ Wo, const float* __restrict__ bo,
        const float* __restrict__ Wp) {
    __shared__ float As4[4*512];   // 8 KB
    __shared__ float Wos[64*64];   // 16 KB
    int tid = threadIdx.x;
    int lane = tid & 31;
    int bx = blockIdx.x;

    if (bx < 32) {
        int g = bx * 8 + (tid >> 5);
        const float* row = Wq + (size_t)g * Dd;
        float acc = 0.f;
        #pragma unroll
        for (int i = 0; i < 16; ++i) acc += row[lane + 32*i] * qw[lane + 32*i];
        #pragma unroll
        for (int o = 16; o; o >>= 1) acc += __shfl_xor_sync(0xffffffffu, acc, o);
        if (lane == 0) g_v[g] = acc;
        return;
    }
    if (bx == 32) {
        if (tid < 64) {
            float acc = bo[tid];
            #pragma unroll 8
            for (int d = 0; d < Dd; ++d) acc += (bq[d] + bp[d]) * Wo[d*Hh + tid];
            g_c0[tid] = acc;
        } else if (tid < 96) {
            float acc = 0.f;
            #pragma unroll
            for (int i = 0; i < 16; ++i) acc += bq[lane + 32*i] * qw[lane + 32*i];
            #pragma unroll
            for (int o = 16; o; o >>= 1) acc += __shfl_xor_sync(0xffffffffu, acc, o);
            if (lane == 0) g_s0 = acc;
        }
        return;
    }
    const float* Asrc;
    float* Cdst;
    if (bx < 161) {
        int r0 = (bx - 33) * 4;
        Asrc = Wp + (size_t)r0 * Dd;
        Cdst = g_W1 + (size_t)r0 * Hh;
    } else {
        int r0 = (bx - 161) * 4;
        Asrc = Wq + (size_t)r0 * Dd;
        Cdst = g_A + (size_t)r0 * Hh;
    }
    #pragma unroll
    for (int i = 0; i < 2; ++i)
        ((float4*)As4)[tid + i*256] = ((const float4*)Asrc)[tid + i*256];

    int h = tid & 63, rp = tid >> 6;
    float acc = 0.f;
    for (int kc = 0; kc < 8; ++kc) {
        __syncthreads();
        const float4* src = (const float4*)(Wo + (size_t)(kc*64)*Hh);
        #pragma unroll
        for (int i = 0; i < 4; ++i)
            ((float4*)Wos)[tid + i*256] = src[tid + i*256];
        __syncthreads();
        const float* ar = As4 + rp*512 + kc*64;
        #pragma unroll 16
        for (int k = 0; k < 64; ++k)
            acc += ar[k] * Wos[k*64 + h];
    }
    Cdst[rp*Hh + h] = acc;
}

// ---------------------------------------------------------------------------
// pass 1 (grid (128, 8)): per block 128 tokens; warp = 16 tokens in 4 batches
// of 4 (interleaved butterfly reductions for ILP).
//   score_n = SCALE*(x_n.v + s0); y += score_n*x_n; S += score_n
// ---------------------------------------------------------------------------
__global__ void __launch_bounds__(256) k_pass1(const float* __restrict__ x) {
    __shared__ float y_sh[8][256];
    __shared__ float s_sh[8];
    int b = blockIdx.y;
    int tile = blockIdx.x;
    int warp = threadIdx.x >> 5, lane = threadIdx.x & 31;

    float4 v0 = *(const float4*)(g_v + 4*lane);
    float4 v1 = *(const float4*)(g_v + 128 + 4*lane);
    float s0 = g_s0;

    const float* xb = x + ((size_t)b*Nseq + (size_t)tile*128 + warp*16) * CIN;

    float y0[4] = {0,0,0,0}, y1[4] = {0,0,0,0};
    float Sacc = 0.f;
    #pragma unroll
    for (int g = 0; g < 4; ++g) {
        float4 A0[4], A1[4];
        #pragma unroll
        for (int u = 0; u < 4; ++u) {
            const float* xr = xb + (size_t)(g*4 + u)*CIN;
            A0[u] = *(const float4*)(xr + 4*lane);
            A1[u] = *(const float4*)(xr + 128 + 4*lane);
        }
        float p[4];
        #pragma unroll
        for (int u = 0; u < 4; ++u)
            p[u] = A0[u].x*v0.x + A0[u].y*v0.y + A0[u].z*v0.z + A0[u].w*v0.w
                 + A1[u].x*v1.x + A1[u].y*v1.y + A1[u].z*v1.z + A1[u].w*v1.w;
        #pragma unroll
        for (int o = 16; o; o >>= 1) {
            #pragma unroll
            for (int u = 0; u < 4; ++u)
                p[u] += __shfl_xor_sync(0xffffffffu, p[u], o);
        }
        #pragma unroll
        for (int u = 0; u < 4; ++u) {
            float score = (p[u] + s0) * SCALEF;
            Sacc += score;
            y0[0] += score*A0[u].x; y0[1] += score*A0[u].y;
            y0[2] += score*A0[u].z; y0[3] += score*A0[u].w;
            y1[0] += score*A1[u].x; y1[1] += score*A1[u].y;
            y1[2] += score*A1[u].z; y1[3] += score*A1[u].w;
        }
    }
    #pragma unroll
    for (int j = 0; j < 4; ++j) {
        y_sh[warp][4*lane + j]       = y0[j];
        y_sh[warp][128 + 4*lane + j] = y1[j];
    }
    if (lane == 0) s_sh[warp] = Sacc;
    __syncthreads();
    int c = threadIdx.x;
    float acc = 0.f;
    #pragma unroll
    for (int w = 0; w < 8; ++w) acc += y_sh[w][c];
    g_ypart[((size_t)b*128 + tile)*256 + c] = acc;
    if (threadIdx.x == 0) {
        float s = 0.f;
        for (int w = 0; w < 8; ++w) s += s_sh[w];
        g_Spart[b*128 + tile] = s;
    }
}

// ---------------------------------------------------------------------------
// k_aw (grid 16 = 8 batches x 2 halves): computes aw ONCE per batch.
//   y_s = reduce(ypart); S = reduce(Spart); aw[d] = y.Wq[:,d] + bq[d]*S
// ---------------------------------------------------------------------------
__global__ void __launch_bounds__(256) k_aw(const float* __restrict__ Wq,
                                            const float* __restrict__ bq) {
    __shared__ float y_s[256];
    __shared__ float s_tmp[128];
    int tid = threadIdx.x;
    int b = blockIdx.x >> 1;
    int half = blockIdx.x & 1;

    {
        const float* yp = g_ypart + (size_t)b*128*256 + tid;
        float acc = 0.f;
        #pragma unroll 8
        for (int p = 0; p < 128; ++p) acc += yp[(size_t)p*256];
        y_s[tid] = acc;
    }
    if (tid < 128) s_tmp[tid] = g_Spart[b*128 + tid];
    __syncthreads();
    float S = 0.f;
    #pragma unroll
    for (int i = 0; i < 128; ++i) S += s_tmp[i];

    int d = half*256 + tid;
    float acc = bq[d] * S;
    #pragma unroll 8
    for (int c = 0; c < 256; ++c)
        acc += y_s[c] * Wq[(size_t)c*Dd + d];
    g_aw[b*Dd + d] = acc;
}

// ---------------------------------------------------------------------------
// k_mid (grid 264 = 8 batches x 33 parts): reads precomputed g_aw.
//   parts 0..31: 8-row tile of M_b = Wk @ diag(aw_b) @ W1 + A, emitted as
//                bf16 hi/lo mma b-fragments (g_BfH/g_BfL)
//   part  32   : bias_b = (aw_b ⊙ bk) @ W1 + c0
// ---------------------------------------------------------------------------
__global__ void __launch_bounds__(256) k_mid(const float* __restrict__ Wk,
                                             const float* __restrict__ bk) {
    __shared__ float aw_s[512];
    __shared__ float Wks[8][33];
    __shared__ float W1s[32][64];
    __shared__ float red[4][64];

    int tid = threadIdx.x;
    int b = blockIdx.x / 33;
    int part = blockIdx.x % 33;

    aw_s[tid]       = g_aw[b*Dd + tid];
    aw_s[tid + 256] = g_aw[b*Dd + tid + 256];
    __syncthreads();

    if (part == 32) {
        int h = tid & 63, seg = tid >> 6;
        float acc = 0.f;
        #pragma unroll 4
        for (int d = seg*128; d < seg*128 + 128; ++d)
            acc += aw_s[d] * bk[d] * g_W1[(size_t)d*Hh + h];
        red[seg][h] = acc;
        __syncthreads();
        if (tid < 64)
            g_bias[b*Hh + tid] = red[0][tid] + red[1][tid] + red[2][tid]
                               + red[3][tid] + g_c0[tid];
        return;
    }

    int r0 = part * 8;                 // 8 k-rows of M
    int h = tid & 63;                  // head
    int pr = tid >> 6;                 // k-pair 0..3 -> rows 2pr, 2pr+1
    float acc0 = 0.f, acc1 = 0.f;
    for (int kc = 0; kc < Dd; kc += 32) {
        __syncthreads();
        {
            int r = tid >> 5, k = tid & 31;
            Wks[r][k] = Wk[(size_t)(r0 + r)*Dd + kc + k];
        }
        #pragma unroll
        for (int i = 0; i < 8; ++i) {
            int idx = tid + i*256;
            int k = idx >> 6, hh = idx & 63;
            W1s[k][hh] = g_W1[(size_t)(kc + k)*Hh + hh] * aw_s[kc + k];
        }
        __syncthreads();
        #pragma unroll
        for (int k = 0; k < 32; ++k) {
            float bv = W1s[k][h];
            acc0 += Wks[2*pr][k]     * bv;
            acc1 += Wks[2*pr + 1][k] * bv;
        }
    }
    // emit b-fragment pair for k-rows (r, r+1), head h
    {
        int r = r0 + 2*pr;                  // even global k index
        int kc16 = r >> 4;
        int kk = r & 15;
        int tig = (kk >> 1) & 3;
        int sel = kk >> 3;
        float m0 = acc0 + g_A[(size_t)r*Hh + h];
        float m1 = acc1 + g_A[(size_t)(r+1)*Hh + h];
        uint32_t hp = pack2bf(m0, m1);
        float l0 = m0 - __uint_as_float(hp << 16);
        float l1 = m1 - __uint_as_float(hp & 0xFFFF0000u);
        uint32_t lp = pack2bf(l0, l1);
        int lanef = (h & 7)*4 + tig;
        int j = h >> 3;
        size_t idx = ((((size_t)b*16 + kc16)*8 + j)*32 + lanef)*2 + sel;
        g_BfH[idx] = hp;
        g_BfL[idx] = lp;
    }
}

// ---------------------------------------------------------------------------
// pass 2 (mma.sync m16n8k16 bf16, 3-term split): out = x @ M_b + bias_b
// CTA: 128 tokens x 64 heads, 8 warps; warp: 16 tokens x 64 heads.
// launch_bounds(256,3): cap regs at 85 -> 3 CTAs/SM (smem 3x64.25KB fits).
// ---------------------------------------------------------------------------
#define P2_SMEM (65536 + 256)
__global__ void __launch_bounds__(256, 3) k_pass2(const float* __restrict__ x,
                                                  float* __restrict__ out) {
    extern __shared__ char sm[];
    uint32_t* BsH = (uint32_t*)sm;              // [kc][j][lane][sel] : 32 KB
    uint32_t* BsL = (uint32_t*)(sm + 32768);    // 32 KB
    float* bias_s = (float*)(sm + 65536);

    int tid = threadIdx.x;
    int w = tid >> 5, lane = tid & 31;
    int b = blockIdx.y;
    int tile = gridDim.x - 1 - blockIdx.x;      // reversed for L2 reuse
    int tok0 = tile * 128;

    // stage B fragments + bias
    {
        const uint4* srcH = (const uint4*)(g_BfH + (size_t)b*8192);
        const uint4* srcL = (const uint4*)(g_BfL + (size_t)b*8192);
        #pragma unroll
        for (int i = 0; i < 8; ++i) {
            ((uint4*)BsH)[tid + i*256] = srcH[tid + i*256];
            ((uint4*)BsL)[tid + i*256] = srcL[tid + i*256];
        }
        if (tid < 64) bias_s[tid] = g_bias[b*Hh + tid];
    }
    __syncthreads();

    int rrow = lane >> 2;           // 0..7
    int tig = lane & 3;
    const float* xr0 = x + ((size_t)b*Nseq + tok0 + w*16 + rrow)*CIN + tig*2;
    const float* xr8 = xr0 + 8*CIN;

    float acc[8][4];
    #pragma unroll
    for (int j = 0; j < 8; ++j)
        #pragma unroll
        for (int q = 0; q < 4; ++q) acc[j][q] = 0.f;

    // prologue loads (kc = 0)
    float2 v0 = *(const float2*)(xr0);
    float2 v1 = *(const float2*)(xr8);
    float2 v2 = *(const float2*)(xr0 + 8);
    float2 v3 = *(const float2*)(xr8 + 8);

    #pragma unroll 4
    for (int kc = 0; kc < 16; ++kc) {
        float2 n0, n1, n2, n3;
        if (kc < 15) {
            int c1 = (kc + 1) * 16;
            n0 = *(const float2*)(xr0 + c1);
            n1 = *(const float2*)(xr8 + c1);
            n2 = *(const float2*)(xr0 + c1 + 8);
            n3 = *(const float2*)(xr8 + c1 + 8);
        }
        uint32_t aH0 = pack2bf(v0.x, v0.y);
        uint32_t aH1 = pack2bf(v1.x, v1.y);
        uint32_t aH2 = pack2bf(v2.x, v2.y);
        uint32_t aH3 = pack2bf(v3.x, v3.y);
        uint32_t aL0 = pack2bf(v0.x - __uint_as_float(aH0 << 16),
                               v0.y - __uint_as_float(aH0 & 0xFFFF0000u));
        uint32_t aL1 = pack2bf(v1.x - __uint_as_float(aH1 << 16),
                               v1.y - __uint_as_float(aH1 & 0xFFFF0000u));
        uint32_t aL2 = pack2bf(v2.x - __uint_as_float(aH2 << 16),
                               v2.y - __uint_as_float(aH2 & 0xFFFF0000u));
        uint32_t aL3 = pack2bf(v3.x - __uint_as_float(aH3 << 16),
                               v3.y - __uint_as_float(aH3 & 0xFFFF0000u));

        const uint32_t* bh = BsH + (kc*8*32 + lane)*2;
        const uint32_t* bl = BsL + (kc*8*32 + lane)*2;
        #pragma unroll
        for (int j = 0; j < 8; ++j) {
            uint2 bhj = *(const uint2*)(bh + j*64);
            uint2 blj = *(const uint2*)(bl + j*64);
            mma16816(acc[j], aH0, aH1, aH2, aH3, bhj.x, bhj.y);
            mma16816(acc[j], aL0, aL1, aL2, aL3, bhj.x, bhj.y);
            mma16816(acc[j], aH0, aH1, aH2, aH3, blj.x, blj.y);
        }
        v0 = n0; v1 = n1; v2 = n2; v3 = n3;
    }

    // epilogue: rows r=tok0+w*16+rrow (+8), cols (tig*2 + 8j, +1)
    float* o0 = out + ((size_t)b*Nseq + tok0 + w*16 + rrow)*Hh + tig*2;
    float* o8 = o0 + 8*Hh;
    #pragma unroll
    for (int j = 0; j < 8; ++j) {
        float2 bj = *(const float2*)(bias_s + tig*2 + 8*j);
        *(float2*)(o0 + 8*j) = make_float2(acc[j][0] + bj.x, acc[j][1] + bj.y);
        *(float2*)(o8 + 8*j) = make_float2(acc[j][2] + bj.x, acc[j][3] + bj.y);
    }
}

extern "C" void kernel_launch(void* const* d_in, const int* in_sizes, int n_in,
                              void* d_out, int out_size) {
    const float* x  = (const float*)d_in[0];
    const float* Wq = (const float*)d_in[1];
    const float* bq = (const float*)d_in[2];
    const float* Wk = (const float*)d_in[3];
    const float* bk = (const float*)d_in[4];
    const float* qw = (const float*)d_in[5];
    const float* Wp = (const float*)d_in[6];
    const float* bp = (const float*)d_in[7];
    const float* Wo = (const float*)d_in[8];
    const float* bo = (const float*)d_in[9];
    float* out = (float*)d_out;
    (void)in_sizes; (void)n_in; (void)out_size;

    cudaFuncSetAttribute(k_pass2, cudaFuncAttributeMaxDynamicSharedMemorySize, P2_SMEM);

    k_prep<<<225, 256>>>(Wq, bq, qw, bp, Wo, bo, Wp);
    {
        dim3 g(128, 8);
        k_pass1<<<g, 256>>>(x);
    }
    k_aw<<<16, 256>>>(Wq, bq);
    k_mid<<<264, 256>>>(Wk, bk);
    {
        dim3 g(128, 8);
        k_pass2<<<g, 256, P2_SMEM>>>(x, out);
    }
}

// round 8
// speedup vs baseline: 3.1157x; 1.0484x over previous
#include <cuda_runtime.h>
#include <cuda_bf16.h>
#include <cstdint>

#define Bsz 8
#define Nseq 16384
#define CIN 256     // DIM (= K of pass2 GEMM)
#define Dd 512      // D
#define Hh 64       // DIM_HEAD (= N of pass2 GEMM)
#define SCALEF 0.125f

// scratch (device globals; no allocation allowed)
__device__ __align__(16) float g_v[CIN];
__device__ float g_s0;
__device__ float g_c0[Hh];
__device__ __align__(16) float g_W1[Dd*Hh];
__device__ __align__(16) float g_A[CIN*Hh];
__device__ float g_ypart[Bsz*128*CIN];
__device__ float g_Spart[Bsz*128];
__device__ __align__(16) float g_aw[Bsz*Dd];
__device__ float g_bias[Bsz*Hh];
// B = M in mma.m16n8k16 b-fragment order: [b][kc(16)][j(8)][lane(32)][sel(2)] u32(bf16x2)
__device__ __align__(16) uint32_t g_BfH[Bsz*16*8*32*2];
__device__ __align__(16) uint32_t g_BfL[Bsz*16*8*32*2];

// pack two f32 -> bf16x2 (lo arg in low half)
__device__ __forceinline__ uint32_t pack2bf(float lo, float hi) {
    uint32_t r;
    asm("cvt.rn.bf16x2.f32 %0, %1, %2;" : "=r"(r) : "f"(hi), "f"(lo));
    return r;
}
__device__ __forceinline__ void mma16816(float* d, uint32_t a0, uint32_t a1,
                                         uint32_t a2, uint32_t a3,
                                         uint32_t b0, uint32_t b1) {
    asm volatile(
        "mma.sync.aligned.m16n8k16.row.col.f32.bf16.bf16.f32 "
        "{%0,%1,%2,%3}, {%4,%5,%6,%7}, {%8,%9}, {%0,%1,%2,%3};"
        : "+f"(d[0]), "+f"(d[1]), "+f"(d[2]), "+f"(d[3])
        : "r"(a0), "r"(a1), "r"(a2), "r"(a3), "r"(b0), "r"(b1));
}

// ---------------------------------------------------------------------------
// k_prep (grid 225):
//   blocks 0..31   : v = Wq@qw (8 rows per block)
//   block  32      : s0 = bq.qw ; c0 = (bq+bp)@Wo + bo
//   blocks 33..160 : W1 = Wp@Wo, 4-row tiles (smem-staged Wo)
//   blocks 161..224: A  = Wq@Wo, 4-row tiles
// ---------------------------------------------------------------------------
__global__ void __launch_bounds__(256) k_prep(
        const float* __restrict__ Wq, const float* __restrict__ bq,
        const float* __restrict__ qw, const float* __restrict__ bp,
        const float* __restrict__ Wo, const float* __restrict__ bo,
        const float* __restrict__ Wp) {
    __shared__ float As4[4*512];   // 8 KB
    __shared__ float Wos[64*64];   // 16 KB
    int tid = threadIdx.x;
    int lane = tid & 31;
    int bx = blockIdx.x;

    if (bx < 32) {
        int g = bx * 8 + (tid >> 5);
        const float* row = Wq + (size_t)g * Dd;
        float acc = 0.f;
        #pragma unroll
        for (int i = 0; i < 16; ++i) acc += row[lane + 32*i] * qw[lane + 32*i];
        #pragma unroll
        for (int o = 16; o; o >>= 1) acc += __shfl_xor_sync(0xffffffffu, acc, o);
        if (lane == 0) g_v[g] = acc;
        return;
    }
    if (bx == 32) {
        if (tid < 64) {
            float acc = bo[tid];
            #pragma unroll 8
            for (int d = 0; d < Dd; ++d) acc += (bq[d] + bp[d]) * Wo[d*Hh + tid];
            g_c0[tid] = acc;
        } else if (tid < 96) {
            float acc = 0.f;
            #pragma unroll
            for (int i = 0; i < 16; ++i) acc += bq[lane + 32*i] * qw[lane + 32*i];
            #pragma unroll
            for (int o = 16; o; o >>= 1) acc += __shfl_xor_sync(0xffffffffu, acc, o);
            if (lane == 0) g_s0 = acc;
        }
        return;
    }
    const float* Asrc;
    float* Cdst;
    if (bx < 161) {
        int r0 = (bx - 33) * 4;
        Asrc = Wp + (size_t)r0 * Dd;
        Cdst = g_W1 + (size_t)r0 * Hh;
    } else {
        int r0 = (bx - 161) * 4;
        Asrc = Wq + (size_t)r0 * Dd;
        Cdst = g_A + (size_t)r0 * Hh;
    }
    #pragma unroll
    for (int i = 0; i < 2; ++i)
        ((float4*)As4)[tid + i*256] = ((const float4*)Asrc)[tid + i*256];

    int h = tid & 63, rp = tid >> 6;
    float acc = 0.f;
    for (int kc = 0; kc < 8; ++kc) {
        __syncthreads();
        const float4* src = (const float4*)(Wo + (size_t)(kc*64)*Hh);
        #pragma unroll
        for (int i = 0; i < 4; ++i)
            ((float4*)Wos)[tid + i*256] = src[tid + i*256];
        __syncthreads();
        const float* ar = As4 + rp*512 + kc*64;
        #pragma unroll 16
        for (int k = 0; k < 64; ++k)
            acc += ar[k] * Wos[k*64 + h];
    }
    Cdst[rp*Hh + h] = acc;
}

// ---------------------------------------------------------------------------
// pass 1 (grid (128, 8)): per block 128 tokens; warp = 16 tokens in 4 batches
// of 4. Double-buffered loads keep 8 LDG.128 in flight during the shfl chain.
//   score_n = SCALE*(x_n.v + s0); y += score_n*x_n; S += score_n
// ---------------------------------------------------------------------------
__global__ void __launch_bounds__(256) k_pass1(const float* __restrict__ x) {
    __shared__ float y_sh[8][256];
    __shared__ float s_sh[8];
    int b = blockIdx.y;
    int tile = blockIdx.x;
    int warp = threadIdx.x >> 5, lane = threadIdx.x & 31;

    float4 v0 = *(const float4*)(g_v + 4*lane);
    float4 v1 = *(const float4*)(g_v + 128 + 4*lane);
    float s0 = g_s0;

    const float* xb = x + ((size_t)b*Nseq + (size_t)tile*128 + warp*16) * CIN;

    float y0[4] = {0,0,0,0}, y1[4] = {0,0,0,0};
    float Sacc = 0.f;

    float4 A0[2][4], A1[2][4];
    #pragma unroll
    for (int u = 0; u < 4; ++u) {
        const float* xr = xb + (size_t)u*CIN;
        A0[0][u] = *(const float4*)(xr + 4*lane);
        A1[0][u] = *(const float4*)(xr + 128 + 4*lane);
    }
    #pragma unroll
    for (int g = 0; g < 4; ++g) {
        int cur = g & 1, nxt = cur ^ 1;
        if (g < 3) {
            #pragma unroll
            for (int u = 0; u < 4; ++u) {
                const float* xr = xb + (size_t)((g+1)*4 + u)*CIN;
                A0[nxt][u] = *(const float4*)(xr + 4*lane);
                A1[nxt][u] = *(const float4*)(xr + 128 + 4*lane);
            }
        }
        float p[4];
        #pragma unroll
        for (int u = 0; u < 4; ++u)
            p[u] = A0[cur][u].x*v0.x + A0[cur][u].y*v0.y + A0[cur][u].z*v0.z + A0[cur][u].w*v0.w
                 + A1[cur][u].x*v1.x + A1[cur][u].y*v1.y + A1[cur][u].z*v1.z + A1[cur][u].w*v1.w;
        #pragma unroll
        for (int o = 16; o; o >>= 1) {
            #pragma unroll
            for (int u = 0; u < 4; ++u)
                p[u] += __shfl_xor_sync(0xffffffffu, p[u], o);
        }
        #pragma unroll
        for (int u = 0; u < 4; ++u) {
            float score = (p[u] + s0) * SCALEF;
            Sacc += score;
            y0[0] += score*A0[cur][u].x; y0[1] += score*A0[cur][u].y;
            y0[2] += score*A0[cur][u].z; y0[3] += score*A0[cur][u].w;
            y1[0] += score*A1[cur][u].x; y1[1] += score*A1[cur][u].y;
            y1[2] += score*A1[cur][u].z; y1[3] += score*A1[cur][u].w;
        }
    }
    #pragma unroll
    for (int j = 0; j < 4; ++j) {
        y_sh[warp][4*lane + j]       = y0[j];
        y_sh[warp][128 + 4*lane + j] = y1[j];
    }
    if (lane == 0) s_sh[warp] = Sacc;
    __syncthreads();
    int c = threadIdx.x;
    float acc = 0.f;
    #pragma unroll
    for (int w = 0; w < 8; ++w) acc += y_sh[w][c];
    g_ypart[((size_t)b*128 + tile)*256 + c] = acc;
    if (threadIdx.x == 0) {
        float s = 0.f;
        for (int w = 0; w < 8; ++w) s += s_sh[w];
        g_Spart[b*128 + tile] = s;
    }
}

// ---------------------------------------------------------------------------
// k_aw (grid 16 = 8 batches x 2 halves): computes aw ONCE per batch.
// ---------------------------------------------------------------------------
__global__ void __launch_bounds__(256) k_aw(const float* __restrict__ Wq,
                                            const float* __restrict__ bq) {
    __shared__ float y_s[256];
    __shared__ float s_tmp[128];
    int tid = threadIdx.x;
    int b = blockIdx.x >> 1;
    int half = blockIdx.x & 1;

    {
        const float* yp = g_ypart + (size_t)b*128*256 + tid;
        float acc = 0.f;
        #pragma unroll 8
        for (int p = 0; p < 128; ++p) acc += yp[(size_t)p*256];
        y_s[tid] = acc;
    }
    if (tid < 128) s_tmp[tid] = g_Spart[b*128 + tid];
    __syncthreads();
    float S = 0.f;
    #pragma unroll
    for (int i = 0; i < 128; ++i) S += s_tmp[i];

    int d = half*256 + tid;
    float acc = bq[d] * S;
    #pragma unroll 8
    for (int c = 0; c < 256; ++c)
        acc += y_s[c] * Wq[(size_t)c*Dd + d];
    g_aw[b*Dd + d] = acc;
}

// ---------------------------------------------------------------------------
// k_mid (grid 136 = 8 batches x 17 parts): reads precomputed g_aw.
//   parts 0..15: 16-row tile of M_b = Wk @ diag(aw_b) @ W1 + A.
//     k chunks of 128 (4 iterations, 8 barriers total); thread = 2 rows x
//     2 heads (warp-uniform rows -> broadcast LDS); aw fused into W1 staging.
//   part  16   : bias_b = (aw_b ⊙ bk) @ W1 + c0
// ---------------------------------------------------------------------------
__global__ void __launch_bounds__(256) k_mid(const float* __restrict__ Wk,
                                             const float* __restrict__ bk) {
    __shared__ float aw_s[512];
    __shared__ float Wks[16*128];     // 8 KB
    __shared__ float W1s[128*64];     // 32 KB
    __shared__ float red[4][64];

    int tid = threadIdx.x;
    int b = blockIdx.x / 17;
    int part = blockIdx.x % 17;

    aw_s[tid]       = g_aw[b*Dd + tid];
    aw_s[tid + 256] = g_aw[b*Dd + tid + 256];
    __syncthreads();

    if (part == 16) {
        int h = tid & 63, seg = tid >> 6;
        float acc = 0.f;
        #pragma unroll 4
        for (int d = seg*128; d < seg*128 + 128; ++d)
            acc += aw_s[d] * bk[d] * g_W1[(size_t)d*Hh + h];
        red[seg][h] = acc;
        __syncthreads();
        if (tid < 64)
            g_bias[b*Hh + tid] = red[0][tid] + red[1][tid] + red[2][tid]
                               + red[3][tid] + g_c0[tid];
        return;
    }

    int r0 = part * 16;
    int pr = tid >> 5;            // warp id 0..7 -> rows 2pr, 2pr+1 (warp-uniform)
    int h2 = tid & 31;            // heads h2, h2+32
    float acc[2][2] = {};
    for (int kc = 0; kc < Dd; kc += 128) {
        __syncthreads();
        // stage Wk chunk: 16 rows x 128 k = 512 float4
        #pragma unroll
        for (int i = 0; i < 2; ++i) {
            int idx = tid + i*256;
            int r = idx >> 5, kq = (idx & 31) * 4;
            *(float4*)(Wks + r*128 + kq) =
                *(const float4*)(Wk + (size_t)(r0 + r)*Dd + kc + kq);
        }
        // stage W1 chunk * aw: 128 k x 64 h = 2048 float4
        #pragma unroll
        for (int i = 0; i < 8; ++i) {
            int idx = tid + i*256;
            int k = idx >> 4, h4 = (idx & 15) * 4;
            float4 wv = *(const float4*)(g_W1 + (size_t)(kc + k)*Hh + h4);
            float a = aw_s[kc + k];
            wv.x *= a; wv.y *= a; wv.z *= a; wv.w *= a;
            *(float4*)(W1s + k*64 + h4) = wv;
        }
        __syncthreads();
        const float* wr0 = Wks + (2*pr)*128;
        const float* wr1 = wr0 + 128;
        #pragma unroll 8
        for (int k = 0; k < 128; ++k) {
            float bv0 = W1s[k*64 + h2];
            float bv1 = W1s[k*64 + h2 + 32];
            float a0 = wr0[k], a1 = wr1[k];
            acc[0][0] += a0*bv0; acc[0][1] += a0*bv1;
            acc[1][0] += a1*bv0; acc[1][1] += a1*bv1;
        }
    }
    // emit b-fragment pairs for k-rows (r, r+1), heads h2 and h2+32
    {
        int r = r0 + 2*pr;                  // even global k index
        int kc16 = r >> 4;
        int kk = r & 15;
        int tig = (kk >> 1) & 3;
        int sel = kk >> 3;
        #pragma unroll
        for (int jj = 0; jj < 2; ++jj) {
            int h = h2 + jj*32;
            float m0 = acc[0][jj] + g_A[(size_t)r*Hh + h];
            float m1 = acc[1][jj] + g_A[(size_t)(r+1)*Hh + h];
            uint32_t hp = pack2bf(m0, m1);
            float l0 = m0 - __uint_as_float(hp << 16);
            float l1 = m1 - __uint_as_float(hp & 0xFFFF0000u);
            uint32_t lp = pack2bf(l0, l1);
            int lanef = (h & 7)*4 + tig;
            int j = h >> 3;
            size_t idx = ((((size_t)b*16 + kc16)*8 + j)*32 + lanef)*2 + sel;
            g_BfH[idx] = hp;
            g_BfL[idx] = lp;
        }
    }
}

// ---------------------------------------------------------------------------
// pass 2 (mma.sync m16n8k16 bf16, 3-term split): out = x @ M_b + bias_b
// CTA: 128 tokens x 64 heads, 8 warps; warp: 16 tokens x 64 heads.
// launch_bounds(256,3): 3 CTAs/SM.
// ---------------------------------------------------------------------------
#define P2_SMEM (65536 + 256)
__global__ void __launch_bounds__(256, 3) k_pass2(const float* __restrict__ x,
                                                  float* __restrict__ out) {
    extern __shared__ char sm[];
    uint32_t* BsH = (uint32_t*)sm;              // [kc][j][lane][sel] : 32 KB
    uint32_t* BsL = (uint32_t*)(sm + 32768);    // 32 KB
    float* bias_s = (float*)(sm + 65536);

    int tid = threadIdx.x;
    int w = tid >> 5, lane = tid & 31;
    int b = blockIdx.y;
    int tile = gridDim.x - 1 - blockIdx.x;      // reversed for L2 reuse
    int tok0 = tile * 128;

    // stage B fragments + bias
    {
        const uint4* srcH = (const uint4*)(g_BfH + (size_t)b*8192);
        const uint4* srcL = (const uint4*)(g_BfL + (size_t)b*8192);
        #pragma unroll
        for (int i = 0; i < 8; ++i) {
            ((uint4*)BsH)[tid + i*256] = srcH[tid + i*256];
            ((uint4*)BsL)[tid + i*256] = srcL[tid + i*256];
        }
        if (tid < 64) bias_s[tid] = g_bias[b*Hh + tid];
    }
    __syncthreads();

    int rrow = lane >> 2;           // 0..7
    int tig = lane & 3;
    const float* xr0 = x + ((size_t)b*Nseq + tok0 + w*16 + rrow)*CIN + tig*2;
    const float* xr8 = xr0 + 8*CIN;

    float acc[8][4];
    #pragma unroll
    for (int j = 0; j < 8; ++j)
        #pragma unroll
        for (int q = 0; q < 4; ++q) acc[j][q] = 0.f;

    // prologue loads (kc = 0)
    float2 v0 = *(const float2*)(xr0);
    float2 v1 = *(const float2*)(xr8);
    float2 v2 = *(const float2*)(xr0 + 8);
    float2 v3 = *(const float2*)(xr8 + 8);

    #pragma unroll 4
    for (int kc = 0; kc < 16; ++kc) {
        float2 n0, n1, n2, n3;
        if (kc < 15) {
            int c1 = (kc + 1) * 16;
            n0 = *(const float2*)(xr0 + c1);
            n1 = *(const float2*)(xr8 + c1);
            n2 = *(const float2*)(xr0 + c1 + 8);
            n3 = *(const float2*)(xr8 + c1 + 8);
        }
        uint32_t aH0 = pack2bf(v0.x, v0.y);
        uint32_t aH1 = pack2bf(v1.x, v1.y);
        uint32_t aH2 = pack2bf(v2.x, v2.y);
        uint32_t aH3 = pack2bf(v3.x, v3.y);
        uint32_t aL0 = pack2bf(v0.x - __uint_as_float(aH0 << 16),
                               v0.y - __uint_as_float(aH0 & 0xFFFF0000u));
        uint32_t aL1 = pack2bf(v1.x - __uint_as_float(aH1 << 16),
                               v1.y - __uint_as_float(aH1 & 0xFFFF0000u));
        uint32_t aL2 = pack2bf(v2.x - __uint_as_float(aH2 << 16),
                               v2.y - __uint_as_float(aH2 & 0xFFFF0000u));
        uint32_t aL3 = pack2bf(v3.x - __uint_as_float(aH3 << 16),
                               v3.y - __uint_as_float(aH3 & 0xFFFF0000u));

        const uint32_t* bh = BsH + (kc*8*32 + lane)*2;
        const uint32_t* bl = BsL + (kc*8*32 + lane)*2;
        #pragma unroll
        for (int j = 0; j < 8; ++j) {
            uint2 bhj = *(const uint2*)(bh + j*64);
            uint2 blj = *(const uint2*)(bl + j*64);
            mma16816(acc[j], aH0, aH1, aH2, aH3, bhj.x, bhj.y);
            mma16816(acc[j], aL0, aL1, aL2, aL3, bhj.x, bhj.y);
            mma16816(acc[j], aH0, aH1, aH2, aH3, blj.x, blj.y);
        }
        v0 = n0; v1 = n1; v2 = n2; v3 = n3;
    }

    // epilogue: rows r=tok0+w*16+rrow (+8), cols (tig*2 + 8j, +1)
    float* o0 = out + ((size_t)b*Nseq + tok0 + w*16 + rrow)*Hh + tig*2;
    float* o8 = o0 + 8*Hh;
    #pragma unroll
    for (int j = 0; j < 8; ++j) {
        float2 bj = *(const float2*)(bias_s + tig*2 + 8*j);
        *(float2*)(o0 + 8*j) = make_float2(acc[j][0] + bj.x, acc[j][1] + bj.y);
        *(float2*)(o8 + 8*j) = make_float2(acc[j][2] + bj.x, acc[j][3] + bj.y);
    }
}

extern "C" void kernel_launch(void* const* d_in, const int* in_sizes, int n_in,
                              void* d_out, int out_size) {
    const float* x  = (const float*)d_in[0];
    const float* Wq = (const float*)d_in[1];
    const float* bq = (const float*)d_in[2];
    const float* Wk = (const float*)d_in[3];
    const float* bk = (const float*)d_in[4];
    const float* qw = (const float*)d_in[5];
    const float* Wp = (const float*)d_in[6];
    const float* bp = (const float*)d_in[7];
    const float* Wo = (const float*)d_in[8];
    const float* bo = (const float*)d_in[9];
    float* out = (float*)d_out;
    (void)in_sizes; (void)n_in; (void)out_size;

    cudaFuncSetAttribute(k_pass2, cudaFuncAttributeMaxDynamicSharedMemorySize, P2_SMEM);

    k_prep<<<225, 256>>>(Wq, bq, qw, bp, Wo, bo, Wp);
    {
        dim3 g(128, 8);
        k_pass1<<<g, 256>>>(x);
    }
    k_aw<<<16, 256>>>(Wq, bq);
    k_mid<<<136, 256>>>(Wk, bk);
    {
        dim3 g(128, 8);
        k_pass2<<<g, 256, P2_SMEM>>>(x, out);
    }
}

// round 9
// speedup vs baseline: 3.4483x; 1.1067x over previous
#include <cuda_runtime.h>
#include <cuda_bf16.h>
#include <cstdint>

#define Bsz 8
#define Nseq 16384
#define CIN 256     // DIM (= K of pass2 GEMM)
#define Dd 512      // D
#define Hh 64       // DIM_HEAD (= N of pass2 GEMM)
#define SCALEF 0.125f

// scratch (device globals; no allocation allowed)
__device__ __align__(16) float g_v[CIN];
__device__ float g_s0;
__device__ float g_c0[Hh];
__device__ __align__(16) float g_W1[Dd*Hh];
__device__ __align__(16) float g_A[CIN*Hh];
__device__ float g_ypart[Bsz*128*CIN];
__device__ float g_Spart[Bsz*128];
__device__ __align__(16) float g_aw[Bsz*Dd];
__device__ float g_bias[Bsz*Hh];
// B = M in mma.m16n8k16 b-fragment order: [b][kc(16)][j(8)][lane(32)][sel(2)] u32(bf16x2)
__device__ __align__(16) uint32_t g_BfH[Bsz*16*8*32*2];
__device__ __align__(16) uint32_t g_BfL[Bsz*16*8*32*2];

// pack two f32 -> bf16x2 (lo arg in low half)
__device__ __forceinline__ uint32_t pack2bf(float lo, float hi) {
    uint32_t r;
    asm("cvt.rn.bf16x2.f32 %0, %1, %2;" : "=r"(r) : "f"(hi), "f"(lo));
    return r;
}
__device__ __forceinline__ void mma16816(float* d, uint32_t a0, uint32_t a1,
                                         uint32_t a2, uint32_t a3,
                                         uint32_t b0, uint32_t b1) {
    asm volatile(
        "mma.sync.aligned.m16n8k16.row.col.f32.bf16.bf16.f32 "
        "{%0,%1,%2,%3}, {%4,%5,%6,%7}, {%8,%9}, {%0,%1,%2,%3};"
        : "+f"(d[0]), "+f"(d[1]), "+f"(d[2]), "+f"(d[3])
        : "r"(a0), "r"(a1), "r"(a2), "r"(a3), "r"(b0), "r"(b1));
}

// ---------------------------------------------------------------------------
// k_prep (grid 225):
//   blocks 0..31   : v = Wq@qw (8 rows per block)
//   block  32      : s0 = bq.qw ; c0 = (bq+bp)@Wo + bo (parallel + reduce)
//   blocks 33..160 : W1 = Wp@Wo, 4-row tiles (smem-staged Wo)
//   blocks 161..224: A  = Wq@Wo, 4-row tiles
// ---------------------------------------------------------------------------
__global__ void __launch_bounds__(256) k_prep(
        const float* __restrict__ Wq, const float* __restrict__ bq,
        const float* __restrict__ qw, const float* __restrict__ bp,
        const float* __restrict__ Wo, const float* __restrict__ bo,
        const float* __restrict__ Wp) {
    __shared__ float As4[4*512];   // 8 KB
    __shared__ float Wos[64*64];   // 16 KB
    int tid = threadIdx.x;
    int lane = tid & 31;
    int bx = blockIdx.x;

    if (bx < 32) {
        int g = bx * 8 + (tid >> 5);
        const float* row = Wq + (size_t)g * Dd;
        float acc = 0.f;
        #pragma unroll
        for (int i = 0; i < 16; ++i) acc += row[lane + 32*i] * qw[lane + 32*i];
        #pragma unroll
        for (int o = 16; o; o >>= 1) acc += __shfl_xor_sync(0xffffffffu, acc, o);
        if (lane == 0) g_v[g] = acc;
        return;
    }
    if (bx == 32) {
        float* red2 = As4;   // reuse static smem
        int h = tid & 63, seg = tid >> 6;
        float acc = (seg == 0) ? bo[h] : 0.f;
        #pragma unroll 8
        for (int d = seg*128; d < seg*128 + 128; ++d)
            acc += (bq[d] + bp[d]) * Wo[d*Hh + h];
        red2[seg*64 + h] = acc;
        __syncthreads();
        if (tid < 64)
            g_c0[tid] = red2[tid] + red2[64 + tid] + red2[128 + tid] + red2[192 + tid];
        else if (tid >= 64 && tid < 96) {
            float a = 0.f;
            #pragma unroll
            for (int i = 0; i < 16; ++i) a += bq[lane + 32*i] * qw[lane + 32*i];
            #pragma unroll
            for (int o = 16; o; o >>= 1) a += __shfl_xor_sync(0xffffffffu, a, o);
            if (lane == 0) g_s0 = a;
        }
        return;
    }
    const float* Asrc;
    float* Cdst;
    if (bx < 161) {
        int r0 = (bx - 33) * 4;
        Asrc = Wp + (size_t)r0 * Dd;
        Cdst = g_W1 + (size_t)r0 * Hh;
    } else {
        int r0 = (bx - 161) * 4;
        Asrc = Wq + (size_t)r0 * Dd;
        Cdst = g_A + (size_t)r0 * Hh;
    }
    #pragma unroll
    for (int i = 0; i < 2; ++i)
        ((float4*)As4)[tid + i*256] = ((const float4*)Asrc)[tid + i*256];

    int h = tid & 63, rp = tid >> 6;
    float acc = 0.f;
    for (int kc = 0; kc < 8; ++kc) {
        __syncthreads();
        const float4* src = (const float4*)(Wo + (size_t)(kc*64)*Hh);
        #pragma unroll
        for (int i = 0; i < 4; ++i)
            ((float4*)Wos)[tid + i*256] = src[tid + i*256];
        __syncthreads();
        const float* ar = As4 + rp*512 + kc*64;
        #pragma unroll 16
        for (int k = 0; k < 64; ++k)
            acc += ar[k] * Wos[k*64 + h];
    }
    Cdst[rp*Hh + h] = acc;
}

// ---------------------------------------------------------------------------
// pass 1 (grid (128, 8)): per block 128 tokens; warp = 16 tokens in 4 batches
// of 4. Double-buffered loads keep 8 LDG.128 in flight during the shfl chain.
// ---------------------------------------------------------------------------
__global__ void __launch_bounds__(256) k_pass1(const float* __restrict__ x) {
    __shared__ float y_sh[8][256];
    __shared__ float s_sh[8];
    int b = blockIdx.y;
    int tile = blockIdx.x;
    int warp = threadIdx.x >> 5, lane = threadIdx.x & 31;

    float4 v0 = *(const float4*)(g_v + 4*lane);
    float4 v1 = *(const float4*)(g_v + 128 + 4*lane);
    float s0 = g_s0;

    const float* xb = x + ((size_t)b*Nseq + (size_t)tile*128 + warp*16) * CIN;

    float y0[4] = {0,0,0,0}, y1[4] = {0,0,0,0};
    float Sacc = 0.f;

    float4 A0[2][4], A1[2][4];
    #pragma unroll
    for (int u = 0; u < 4; ++u) {
        const float* xr = xb + (size_t)u*CIN;
        A0[0][u] = *(const float4*)(xr + 4*lane);
        A1[0][u] = *(const float4*)(xr + 128 + 4*lane);
    }
    #pragma unroll
    for (int g = 0; g < 4; ++g) {
        int cur = g & 1, nxt = cur ^ 1;
        if (g < 3) {
            #pragma unroll
            for (int u = 0; u < 4; ++u) {
                const float* xr = xb + (size_t)((g+1)*4 + u)*CIN;
                A0[nxt][u] = *(const float4*)(xr + 4*lane);
                A1[nxt][u] = *(const float4*)(xr + 128 + 4*lane);
            }
        }
        float p[4];
        #pragma unroll
        for (int u = 0; u < 4; ++u)
            p[u] = A0[cur][u].x*v0.x + A0[cur][u].y*v0.y + A0[cur][u].z*v0.z + A0[cur][u].w*v0.w
                 + A1[cur][u].x*v1.x + A1[cur][u].y*v1.y + A1[cur][u].z*v1.z + A1[cur][u].w*v1.w;
        #pragma unroll
        for (int o = 16; o; o >>= 1) {
            #pragma unroll
            for (int u = 0; u < 4; ++u)
                p[u] += __shfl_xor_sync(0xffffffffu, p[u], o);
        }
        #pragma unroll
        for (int u = 0; u < 4; ++u) {
            float score = (p[u] + s0) * SCALEF;
            Sacc += score;
            y0[0] += score*A0[cur][u].x; y0[1] += score*A0[cur][u].y;
            y0[2] += score*A0[cur][u].z; y0[3] += score*A0[cur][u].w;
            y1[0] += score*A1[cur][u].x; y1[1] += score*A1[cur][u].y;
            y1[2] += score*A1[cur][u].z; y1[3] += score*A1[cur][u].w;
        }
    }
    #pragma unroll
    for (int j = 0; j < 4; ++j) {
        y_sh[warp][4*lane + j]       = y0[j];
        y_sh[warp][128 + 4*lane + j] = y1[j];
    }
    if (lane == 0) s_sh[warp] = Sacc;
    __syncthreads();
    int c = threadIdx.x;
    float acc = 0.f;
    #pragma unroll
    for (int w = 0; w < 8; ++w) acc += y_sh[w][c];
    g_ypart[((size_t)b*128 + tile)*256 + c] = acc;
    if (threadIdx.x == 0) {
        float s = 0.f;
        for (int w = 0; w < 8; ++w) s += s_sh[w];
        g_Spart[b*128 + tile] = s;
    }
}

// ---------------------------------------------------------------------------
// k_aw (grid 16 = 8 batches x 2 halves): computes aw ONCE per batch.
// ---------------------------------------------------------------------------
__global__ void __launch_bounds__(256) k_aw(const float* __restrict__ Wq,
                                            const float* __restrict__ bq) {
    __shared__ float y_s[256];
    __shared__ float s_tmp[128];
    int tid = threadIdx.x;
    int b = blockIdx.x >> 1;
    int half = blockIdx.x & 1;

    {
        const float* yp = g_ypart + (size_t)b*128*256 + tid;
        float acc = 0.f;
        #pragma unroll 8
        for (int p = 0; p < 128; ++p) acc += yp[(size_t)p*256];
        y_s[tid] = acc;
    }
    if (tid < 128) s_tmp[tid] = g_Spart[b*128 + tid];
    __syncthreads();
    float S = 0.f;
    #pragma unroll
    for (int i = 0; i < 128; ++i) S += s_tmp[i];

    int d = half*256 + tid;
    float acc = bq[d] * S;
    #pragma unroll 8
    for (int c = 0; c < 256; ++c)
        acc += y_s[c] * Wq[(size_t)c*Dd + d];
    g_aw[b*Dd + d] = acc;
}

// ---------------------------------------------------------------------------
// k_mid (grid 136 = 8 batches x 17 parts): reads precomputed g_aw.
//   parts 0..15: 16-row tile of M_b = Wk @ diag(aw_b) @ W1 + A.
//     2 k-chunks of 256 (4 barriers); thread = 1 row x 4 heads: per k-step
//     1 LDS.128 (W1 quad) + 1 broadcast LDS.32 (Wk) + 4 FFMA. A folded into
//     acc init. Fragments emitted via 4 KB smem round-trip of M.
//   part  16   : bias_b = (aw_b ⊙ bk) @ W1 + c0
// ---------------------------------------------------------------------------
#define MID_SMEM ((512 + 16*256 + 256*64) * 4)   // 83968 B
__global__ void __launch_bounds__(256) k_mid(const float* __restrict__ Wk,
                                             const float* __restrict__ bk) {
    extern __shared__ float smd[];
    float* aw_s = smd;                 // 512 floats
    float* Wks  = smd + 512;           // 16 x 256
    float* W1s  = smd + 512 + 4096;    // 256 x 64
    float* red  = Wks;                 // alias (bias path)
    float* Ms   = Wks;                 // alias (emission staging)

    int tid = threadIdx.x;
    int b = blockIdx.x / 17;
    int part = blockIdx.x % 17;

    aw_s[tid]       = g_aw[b*Dd + tid];
    aw_s[tid + 256] = g_aw[b*Dd + tid + 256];
    __syncthreads();

    if (part == 16) {
        int h = tid & 63, seg = tid >> 6;
        float acc = 0.f;
        #pragma unroll 4
        for (int d = seg*128; d < seg*128 + 128; ++d)
            acc += aw_s[d] * bk[d] * g_W1[(size_t)d*Hh + h];
        red[seg*64 + h] = acc;
        __syncthreads();
        if (tid < 64)
            g_bias[b*Hh + tid] = red[tid] + red[64 + tid] + red[128 + tid]
                               + red[192 + tid] + g_c0[tid];
        return;
    }

    int r0 = part * 16;
    int pr = tid >> 4;            // row 0..15
    int hq = tid & 15;            // head quad
    int h0 = hq * 4;

    float4 acc = *(const float4*)(g_A + (size_t)(r0 + pr)*Hh + h0);

    for (int kc = 0; kc < Dd; kc += 256) {
        __syncthreads();
        // stage Wk chunk: 16 rows x 256 k = 1024 float4
        #pragma unroll
        for (int i = 0; i < 4; ++i) {
            int idx = tid + i*256;
            int r = idx >> 6, kq = (idx & 63) * 4;
            *(float4*)(Wks + r*256 + kq) =
                *(const float4*)(Wk + (size_t)(r0 + r)*Dd + kc + kq);
        }
        // stage W1 chunk * aw: 256 k x 64 h = 4096 float4
        #pragma unroll
        for (int i = 0; i < 16; ++i) {
            int idx = tid + i*256;
            int k = idx >> 4, h4 = (idx & 15) * 4;
            float4 wv = *(const float4*)(g_W1 + (size_t)(kc + k)*Hh + h4);
            float a = aw_s[kc + k];
            wv.x *= a; wv.y *= a; wv.z *= a; wv.w *= a;
            *(float4*)(W1s + k*64 + h4) = wv;
        }
        __syncthreads();
        const float* wr = Wks + pr*256;
        #pragma unroll 8
        for (int k = 0; k < 256; ++k) {
            float a = wr[k];
            float4 bv = *(const float4*)(W1s + k*64 + h0);
            acc.x += a*bv.x; acc.y += a*bv.y; acc.z += a*bv.z; acc.w += a*bv.w;
        }
    }
    __syncthreads();
    *(float4*)(Ms + pr*64 + h0) = acc;      // M tile (16 x 64) into smem
    __syncthreads();
    // emission: 512 pair-entries = (row-pair 0..7) x (head 0..63); 2 per thread
    #pragma unroll
    for (int e = 0; e < 2; ++e) {
        int idx2 = tid + e*256;
        int rp = idx2 >> 6;
        int h = idx2 & 63;
        float m0 = Ms[(2*rp)*64 + h];
        float m1 = Ms[(2*rp + 1)*64 + h];
        int r = r0 + 2*rp;                  // even global k index
        int kc16 = r >> 4;
        int kk = r & 15;
        int tig = (kk >> 1) & 3;
        int sel = kk >> 3;
        uint32_t hp = pack2bf(m0, m1);
        float l0 = m0 - __uint_as_float(hp << 16);
        float l1 = m1 - __uint_as_float(hp & 0xFFFF0000u);
        uint32_t lp = pack2bf(l0, l1);
        int lanef = (h & 7)*4 + tig;
        int j = h >> 3;
        size_t idx = ((((size_t)b*16 + kc16)*8 + j)*32 + lanef)*2 + sel;
        g_BfH[idx] = hp;
        g_BfL[idx] = lp;
    }
}

// ---------------------------------------------------------------------------
// pass 2 (mma.sync m16n8k16 bf16, 3-term split): out = x @ M_b + bias_b
// CTA: 128 tokens x 64 heads, 8 warps; warp: 16 tokens x 64 heads.
// ---------------------------------------------------------------------------
#define P2_SMEM (65536 + 256)
__global__ void __launch_bounds__(256, 3) k_pass2(const float* __restrict__ x,
                                                  float* __restrict__ out) {
    extern __shared__ char sm[];
    uint32_t* BsH = (uint32_t*)sm;              // [kc][j][lane][sel] : 32 KB
    uint32_t* BsL = (uint32_t*)(sm + 32768);    // 32 KB
    float* bias_s = (float*)(sm + 65536);

    int tid = threadIdx.x;
    int w = tid >> 5, lane = tid & 31;
    int b = blockIdx.y;
    int tile = gridDim.x - 1 - blockIdx.x;      // reversed for L2 reuse
    int tok0 = tile * 128;

    {
        const uint4* srcH = (const uint4*)(g_BfH + (size_t)b*8192);
        const uint4* srcL = (const uint4*)(g_BfL + (size_t)b*8192);
        #pragma unroll
        for (int i = 0; i < 8; ++i) {
            ((uint4*)BsH)[tid + i*256] = srcH[tid + i*256];
            ((uint4*)BsL)[tid + i*256] = srcL[tid + i*256];
        }
        if (tid < 64) bias_s[tid] = g_bias[b*Hh + tid];
    }
    __syncthreads();

    int rrow = lane >> 2;
    int tig = lane & 3;
    const float* xr0 = x + ((size_t)b*Nseq + tok0 + w*16 + rrow)*CIN + tig*2;
    const float* xr8 = xr0 + 8*CIN;

    float acc[8][4];
    #pragma unroll
    for (int j = 0; j < 8; ++j)
        #pragma unroll
        for (int q = 0; q < 4; ++q) acc[j][q] = 0.f;

    float2 v0 = *(const float2*)(xr0);
    float2 v1 = *(const float2*)(xr8);
    float2 v2 = *(const float2*)(xr0 + 8);
    float2 v3 = *(const float2*)(xr8 + 8);

    #pragma unroll 4
    for (int kc = 0; kc < 16; ++kc) {
        float2 n0, n1, n2, n3;
        if (kc < 15) {
            int c1 = (kc + 1) * 16;
            n0 = *(const float2*)(xr0 + c1);
            n1 = *(const float2*)(xr8 + c1);
            n2 = *(const float2*)(xr0 + c1 + 8);
            n3 = *(const float2*)(xr8 + c1 + 8);
        }
        uint32_t aH0 = pack2bf(v0.x, v0.y);
        uint32_t aH1 = pack2bf(v1.x, v1.y);
        uint32_t aH2 = pack2bf(v2.x, v2.y);
        uint32_t aH3 = pack2bf(v3.x, v3.y);
        uint32_t aL0 = pack2bf(v0.x - __uint_as_float(aH0 << 16),
                               v0.y - __uint_as_float(aH0 & 0xFFFF0000u));
        uint32_t aL1 = pack2bf(v1.x - __uint_as_float(aH1 << 16),
                               v1.y - __uint_as_float(aH1 & 0xFFFF0000u));
        uint32_t aL2 = pack2bf(v2.x - __uint_as_float(aH2 << 16),
                               v2.y - __uint_as_float(aH2 & 0xFFFF0000u));
        uint32_t aL3 = pack2bf(v3.x - __uint_as_float(aH3 << 16),
                               v3.y - __uint_as_float(aH3 & 0xFFFF0000u));

        const uint32_t* bh = BsH + (kc*8*32 + lane)*2;
        const uint32_t* bl = BsL + (kc*8*32 + lane)*2;
        #pragma unroll
        for (int j = 0; j < 8; ++j) {
            uint2 bhj = *(const uint2*)(bh + j*64);
            uint2 blj = *(const uint2*)(bl + j*64);
            mma16816(acc[j], aH0, aH1, aH2, aH3, bhj.x, bhj.y);
            mma16816(acc[j], aL0, aL1, aL2, aL3, bhj.x, bhj.y);
            mma16816(acc[j], aH0, aH1, aH2, aH3, blj.x, blj.y);
        }
        v0 = n0; v1 = n1; v2 = n2; v3 = n3;
    }

    float* o0 = out + ((size_t)b*Nseq + tok0 + w*16 + rrow)*Hh + tig*2;
    float* o8 = o0 + 8*Hh;
    #pragma unroll
    for (int j = 0; j < 8; ++j) {
        float2 bj = *(const float2*)(bias_s + tig*2 + 8*j);
        *(float2*)(o0 + 8*j) = make_float2(acc[j][0] + bj.x, acc[j][1] + bj.y);
        *(float2*)(o8 + 8*j) = make_float2(acc[j][2] + bj.x, acc[j][3] + bj.y);
    }
}

extern "C" void kernel_launch(void* const* d_in, const int* in_sizes, int n_in,
                              void* d_out, int out_size) {
    const float* x  = (const float*)d_in[0];
    const float* Wq = (const float*)d_in[1];
    const float* bq = (const float*)d_in[2];
    const float* Wk = (const float*)d_in[3];
    const float* bk = (const float*)d_in[4];
    const float* qw = (const float*)d_in[5];
    const float* Wp = (const float*)d_in[6];
    const float* bp = (const float*)d_in[7];
    const float* Wo = (const float*)d_in[8];
    const float* bo = (const float*)d_in[9];
    float* out = (float*)d_out;
    (void)in_sizes; (void)n_in; (void)out_size;

    cudaFuncSetAttribute(k_pass2, cudaFuncAttributeMaxDynamicSharedMemorySize, P2_SMEM);
    cudaFuncSetAttribute(k_mid, cudaFuncAttributeMaxDynamicSharedMemorySize, MID_SMEM);

    k_prep<<<225, 256>>>(Wq, bq, qw, bp, Wo, bo, Wp);
    {
        dim3 g(128, 8);
        k_pass1<<<g, 256>>>(x);
    }
    k_aw<<<16, 256>>>(Wq, bq);
    k_mid<<<136, 256, MID_SMEM>>>(Wk, bk);
    {
        dim3 g(128, 8);
        k_pass2<<<g, 256, P2_SMEM>>>(x, out);
    }
}

// round 11
// speedup vs baseline: 4.1167x; 1.1938x over previous
#include <cuda_runtime.h>
#include <cuda_bf16.h>
#include <cstdint>

#define Bsz 8
#define Nseq 16384
#define CIN 256     // DIM (= K of pass2 GEMM)
#define Dd 512      // D
#define Hh 64       // DIM_HEAD (= N of pass2 GEMM)
#define SCALEF 0.125f

// scratch (device globals; no allocation allowed)
__device__ __align__(16) float g_v[CIN];
__device__ float g_s0;
__device__ float g_c0[Hh];
__device__ __align__(16) float g_W1[Dd*Hh];
__device__ __align__(16) float g_A[CIN*Hh];
__device__ float g_ypart[Bsz*128*CIN];
__device__ float g_Spart[Bsz*128];
__device__ __align__(16) float g_aw[Bsz*Dd];
__device__ float g_bias[Bsz*Hh];
// B = M in mma.m16n8k16 b-fragment order: [b][kc(16)][j(8)][lane(32)][sel(2)] u32(bf16x2)
__device__ __align__(16) uint32_t g_BfH[Bsz*16*8*32*2];
__device__ __align__(16) uint32_t g_BfL[Bsz*16*8*32*2];

// pack two f32 -> bf16x2 (lo arg in low half)
__device__ __forceinline__ uint32_t pack2bf(float lo, float hi) {
    uint32_t r;
    asm("cvt.rn.bf16x2.f32 %0, %1, %2;" : "=r"(r) : "f"(hi), "f"(lo));
    return r;
}
__device__ __forceinline__ void mma16816(float* d, uint32_t a0, uint32_t a1,
                                         uint32_t a2, uint32_t a3,
                                         uint32_t b0, uint32_t b1) {
    asm volatile(
        "mma.sync.aligned.m16n8k16.row.col.f32.bf16.bf16.f32 "
        "{%0,%1,%2,%3}, {%4,%5,%6,%7}, {%8,%9}, {%0,%1,%2,%3};"
        : "+f"(d[0]), "+f"(d[1]), "+f"(d[2]), "+f"(d[3])
        : "r"(a0), "r"(a1), "r"(a2), "r"(a3), "r"(b0), "r"(b1));
}

// ---------------------------------------------------------------------------
// k_prep_small (grid 33): only what pass1 needs.
//   blocks 0..31: v = Wq@qw (8 rows per block); block 32: s0 = bq.qw
// ---------------------------------------------------------------------------
__global__ void __launch_bounds__(256) k_prep_small(
        const float* __restrict__ Wq, const float* __restrict__ bq,
        const float* __restrict__ qw) {
    int tid = threadIdx.x;
    int lane = tid & 31;
    int bx = blockIdx.x;
    if (bx < 32) {
        int g = bx * 8 + (tid >> 5);
        const float* row = Wq + (size_t)g * Dd;
        float acc = 0.f;
        #pragma unroll
        for (int i = 0; i < 16; ++i) acc += row[lane + 32*i] * qw[lane + 32*i];
        #pragma unroll
        for (int o = 16; o; o >>= 1) acc += __shfl_xor_sync(0xffffffffu, acc, o);
        if (lane == 0) g_v[g] = acc;
    } else if (tid < 32) {
        float a = 0.f;
        #pragma unroll
        for (int i = 0; i < 16; ++i) a += bq[lane + 32*i] * qw[lane + 32*i];
        #pragma unroll
        for (int o = 16; o; o >>= 1) a += __shfl_xor_sync(0xffffffffu, a, o);
        if (lane == 0) g_s0 = a;
    }
}

// ---------------------------------------------------------------------------
// pass 1 (grid (128, 8)): per block 128 tokens; warp = 16 tokens in 4 batches
// of 4. Double-buffered loads keep 8 LDG.128 in flight during the shfl chain.
// ---------------------------------------------------------------------------
__global__ void __launch_bounds__(256) k_pass1(const float* __restrict__ x) {
    __shared__ float y_sh[8][256];
    __shared__ float s_sh[8];
    int b = blockIdx.y;
    int tile = blockIdx.x;
    int warp = threadIdx.x >> 5, lane = threadIdx.x & 31;

    float4 v0 = *(const float4*)(g_v + 4*lane);
    float4 v1 = *(const float4*)(g_v + 128 + 4*lane);
    float s0 = g_s0;

    const float* xb = x + ((size_t)b*Nseq + (size_t)tile*128 + warp*16) * CIN;

    float y0[4] = {0,0,0,0}, y1[4] = {0,0,0,0};
    float Sacc = 0.f;

    float4 A0[2][4], A1[2][4];
    #pragma unroll
    for (int u = 0; u < 4; ++u) {
        const float* xr = xb + (size_t)u*CIN;
        A0[0][u] = *(const float4*)(xr + 4*lane);
        A1[0][u] = *(const float4*)(xr + 128 + 4*lane);
    }
    #pragma unroll
    for (int g = 0; g < 4; ++g) {
        int cur = g & 1, nxt = cur ^ 1;
        if (g < 3) {
            #pragma unroll
            for (int u = 0; u < 4; ++u) {
                const float* xr = xb + (size_t)((g+1)*4 + u)*CIN;
                A0[nxt][u] = *(const float4*)(xr + 4*lane);
                A1[nxt][u] = *(const float4*)(xr + 128 + 4*lane);
            }
        }
        float p[4];
        #pragma unroll
        for (int u = 0; u < 4; ++u)
            p[u] = A0[cur][u].x*v0.x + A0[cur][u].y*v0.y + A0[cur][u].z*v0.z + A0[cur][u].w*v0.w
                 + A1[cur][u].x*v1.x + A1[cur][u].y*v1.y + A1[cur][u].z*v1.z + A1[cur][u].w*v1.w;
        #pragma unroll
        for (int o = 16; o; o >>= 1) {
            #pragma unroll
            for (int u = 0; u < 4; ++u)
                p[u] += __shfl_xor_sync(0xffffffffu, p[u], o);
        }
        #pragma unroll
        for (int u = 0; u < 4; ++u) {
            float score = (p[u] + s0) * SCALEF;
            Sacc += score;
            y0[0] += score*A0[cur][u].x; y0[1] += score*A0[cur][u].y;
            y0[2] += score*A0[cur][u].z; y0[3] += score*A0[cur][u].w;
            y1[0] += score*A1[cur][u].x; y1[1] += score*A1[cur][u].y;
            y1[2] += score*A1[cur][u].z; y1[3] += score*A1[cur][u].w;
        }
    }
    #pragma unroll
    for (int j = 0; j < 4; ++j) {
        y_sh[warp][4*lane + j]       = y0[j];
        y_sh[warp][128 + 4*lane + j] = y1[j];
    }
    if (lane == 0) s_sh[warp] = Sacc;
    __syncthreads();
    int c = threadIdx.x;
    float acc = 0.f;
    #pragma unroll
    for (int w = 0; w < 8; ++w) acc += y_sh[w][c];
    g_ypart[((size_t)b*128 + tile)*256 + c] = acc;
    if (threadIdx.x == 0) {
        float s = 0.f;
        for (int w = 0; w < 8; ++w) s += s_sh[w];
        g_Spart[b*128 + tile] = s;
    }
}

// ---------------------------------------------------------------------------
// k_aw_prep (grid 209): aw (needs pass1) runs in parallel with the weight
// GEMMs (independent of pass1):
//   blocks 0..15  : aw per batch-half
//   block  16     : c0 = (bq+bp)@Wo + bo
//   blocks 17..144: W1 = Wp@Wo, 4-row tiles
//   blocks 145..208: A = Wq@Wo, 4-row tiles
// ---------------------------------------------------------------------------
__global__ void __launch_bounds__(256) k_aw_prep(
        const float* __restrict__ Wq, const float* __restrict__ bq,
        const float* __restrict__ qw, const float* __restrict__ bp,
        const float* __restrict__ Wo, const float* __restrict__ bo,
        const float* __restrict__ Wp) {
    __shared__ float As4[4*512];   // 8 KB (aliased as reduce buf)
    __shared__ float Wos[64*64];   // 16 KB
    int tid = threadIdx.x;
    int bx = blockIdx.x;

    if (bx < 16) {
        __shared__ float y_s[256];
        __shared__ float s_tmp[128];
        int b = bx >> 1;
        int half = bx & 1;
        {
            const float* yp = g_ypart + (size_t)b*128*256 + tid;
            float acc = 0.f;
            #pragma unroll 8
            for (int p = 0; p < 128; ++p) acc += yp[(size_t)p*256];
            y_s[tid] = acc;
        }
        if (tid < 128) s_tmp[tid] = g_Spart[b*128 + tid];
        __syncthreads();
        float S = 0.f;
        #pragma unroll
        for (int i = 0; i < 128; ++i) S += s_tmp[i];
        int d = half*256 + tid;
        float acc = bq[d] * S;
        #pragma unroll 8
        for (int c = 0; c < 256; ++c)
            acc += y_s[c] * Wq[(size_t)c*Dd + d];
        g_aw[b*Dd + d] = acc;
        return;
    }
    if (bx == 16) {
        float* redc = As4;
        int h = tid & 63, seg = tid >> 6;
        float acc = (seg == 0) ? bo[h] : 0.f;
        #pragma unroll 8
        for (int d = seg*128; d < seg*128 + 128; ++d)
            acc += (bq[d] + bp[d]) * Wo[d*Hh + h];
        redc[seg*64 + h] = acc;
        __syncthreads();
        if (tid < 64)
            g_c0[tid] = redc[tid] + redc[64 + tid] + redc[128 + tid] + redc[192 + tid];
        return;
    }
    const float* Asrc;
    float* Cdst;
    if (bx < 145) {
        int r0 = (bx - 17) * 4;
        Asrc = Wp + (size_t)r0 * Dd;
        Cdst = g_W1 + (size_t)r0 * Hh;
    } else {
        int r0 = (bx - 145) * 4;
        Asrc = Wq + (size_t)r0 * Dd;
        Cdst = g_A + (size_t)r0 * Hh;
    }
    #pragma unroll
    for (int i = 0; i < 2; ++i)
        ((float4*)As4)[tid + i*256] = ((const float4*)Asrc)[tid + i*256];

    int h = tid & 63, rp = tid >> 6;
    float acc = 0.f;
    for (int kc = 0; kc < 8; ++kc) {
        __syncthreads();
        const float4* src = (const float4*)(Wo + (size_t)(kc*64)*Hh);
        #pragma unroll
        for (int i = 0; i < 4; ++i)
            ((float4*)Wos)[tid + i*256] = src[tid + i*256];
        __syncthreads();
        const float* ar = As4 + rp*512 + kc*64;
        #pragma unroll 16
        for (int k = 0; k < 64; ++k)
            acc += ar[k] * Wos[k*64 + h];
    }
    Cdst[rp*Hh + h] = acc;
}

// ---------------------------------------------------------------------------
// k_mid (grid 136 x 512 threads): reads precomputed g_aw.
//   parts 0..15: 16-row tile of M_b = Wk @ diag(aw_b) @ W1 + A.
//     Single staging pass (162 KB smem, 1 barrier); thread = (ks, row, head
//     quad): K split in halves per thread -> 16 warps hide LDS latency;
//     deterministic 2-way smem combine, then fragment emission.
//   part  16   : bias_b = (aw_b ⊙ bk) @ W1 + c0
// ---------------------------------------------------------------------------
#define MID_SMEM ((512 + 16*512 + 512*64) * 4)   // 165888 B
__global__ void __launch_bounds__(512) k_mid(const float* __restrict__ Wk,
                                             const float* __restrict__ bk) {
    extern __shared__ float smd[];
    float* aw_s = smd;                 // 512
    float* Wks  = smd + 512;           // 16 x 512
    float* W1s  = smd + 512 + 8192;    // 512 x 64
    float* red  = Wks;                 // alias (bias path: 8x64)
    float* Cp   = Wks;                 // alias (combine: 16x64)
    float* Ms   = Wks + 1024;          // alias (M tile: 16x64)

    int tid = threadIdx.x;             // 0..511
    int b = blockIdx.x / 17;
    int part = blockIdx.x % 17;

    aw_s[tid] = g_aw[b*Dd + tid];
    __syncthreads();

    if (part == 16) {
        int h = tid & 63, seg = tid >> 6;   // 8 segs of 64 k
        float acc = 0.f;
        #pragma unroll 4
        for (int d = seg*64; d < seg*64 + 64; ++d)
            acc += aw_s[d] * bk[d] * g_W1[(size_t)d*Hh + h];
        red[seg*64 + h] = acc;
        __syncthreads();
        if (tid < 64) {
            float s = g_c0[tid];
            #pragma unroll
            for (int sg = 0; sg < 8; ++sg) s += red[sg*64 + tid];
            g_bias[b*Hh + tid] = s;
        }
        return;
    }

    int r0 = part * 16;
    int ks = tid >> 8;            // K half 0/1
    int r  = (tid >> 4) & 15;     // row 0..15
    int h0 = (tid & 15) * 4;      // head quad

    // stage Wk tile: 16 rows x 512 k = 2048 float4
    #pragma unroll
    for (int i = 0; i < 4; ++i) {
        int idx = tid + i*512;
        int row = idx >> 7, q = (idx & 127) * 4;
        *(float4*)(Wks + row*512 + q) =
            *(const float4*)(Wk + (size_t)(r0 + row)*Dd + q);
    }
    // stage W1 * aw: 512 k x 64 h = 8192 float4
    #pragma unroll
    for (int i = 0; i < 16; ++i) {
        int idx = tid + i*512;
        int k = idx >> 4, h4 = (idx & 15) * 4;
        float4 wv = *(const float4*)(g_W1 + (size_t)k*Hh + h4);
        float a = aw_s[k];
        wv.x *= a; wv.y *= a; wv.z *= a; wv.w *= a;
        *(float4*)(W1s + k*64 + h4) = wv;
    }
    __syncthreads();

    float4 acc;
    if (ks == 0) acc = *(const float4*)(g_A + (size_t)(r0 + r)*Hh + h0);
    else         acc = make_float4(0.f, 0.f, 0.f, 0.f);

    const float* wr = Wks + r*512 + ks*256;
    const float* w1b = W1s + (size_t)(ks*256)*64 + h0;
    #pragma unroll 8
    for (int k = 0; k < 256; ++k) {
        float a = wr[k];
        float4 bv = *(const float4*)(w1b + k*64);
        acc.x += a*bv.x; acc.y += a*bv.y; acc.z += a*bv.z; acc.w += a*bv.w;
    }
    __syncthreads();
    if (ks == 1) *(float4*)(Cp + r*64 + h0) = acc;
    __syncthreads();
    if (ks == 0) {
        float4 o = *(const float4*)(Cp + r*64 + h0);
        acc.x += o.x; acc.y += o.y; acc.z += o.z; acc.w += o.w;
        *(float4*)(Ms + r*64 + h0) = acc;
    }
    __syncthreads();
    // emission: 512 pair-entries = (row-pair 0..7) x (head 0..63); 1 per thread
    {
        int rp = tid >> 6;
        int h = tid & 63;
        float m0 = Ms[(2*rp)*64 + h];
        float m1 = Ms[(2*rp + 1)*64 + h];
        int rr = r0 + 2*rp;                 // even global k index
        int kc16 = rr >> 4;
        int kk = rr & 15;
        int tig = (kk >> 1) & 3;
        int sel = kk >> 3;
        uint32_t hp = pack2bf(m0, m1);
        float l0 = m0 - __uint_as_float(hp << 16);
        float l1 = m1 - __uint_as_float(hp & 0xFFFF0000u);
        uint32_t lp = pack2bf(l0, l1);
        int lanef = (h & 7)*4 + tig;
        int j = h >> 3;
        size_t idx = ((((size_t)b*16 + kc16)*8 + j)*32 + lanef)*2 + sel;
        g_BfH[idx] = hp;
        g_BfL[idx] = lp;
    }
}

// ---------------------------------------------------------------------------
// pass 2 (mma.sync m16n8k16 bf16, 3-term split): out = x @ M_b + bias_b
// CTA: 128 tokens x 64 heads, 8 warps; warp: 16 tokens x 64 heads.
// ---------------------------------------------------------------------------
#define P2_SMEM (65536 + 256)
__global__ void __launch_bounds__(256, 3) k_pass2(const float* __restrict__ x,
                                                  float* __restrict__ out) {
    extern __shared__ char sm[];
    uint32_t* BsH = (uint32_t*)sm;              // [kc][j][lane][sel] : 32 KB
    uint32_t* BsL = (uint32_t*)(sm + 32768);    // 32 KB
    float* bias_s = (float*)(sm + 65536);

    int tid = threadIdx.x;
    int w = tid >> 5, lane = tid & 31;
    int b = blockIdx.y;
    int tile = gridDim.x - 1 - blockIdx.x;      // reversed for L2 reuse
    int tok0 = tile * 128;

    {
        const uint4* srcH = (const uint4*)(g_BfH + (size_t)b*8192);
        const uint4* srcL = (const uint4*)(g_BfL + (size_t)b*8192);
        #pragma unroll
        for (int i = 0; i < 8; ++i) {
            ((uint4*)BsH)[tid + i*256] = srcH[tid + i*256];
            ((uint4*)BsL)[tid + i*256] = srcL[tid + i*256];
        }
        if (tid < 64) bias_s[tid] = g_bias[b*Hh + tid];
    }
    __syncthreads();

    int rrow = lane >> 2;
    int tig = lane & 3;
    const float* xr0 = x + ((size_t)b*Nseq + tok0 + w*16 + rrow)*CIN + tig*2;
    const float* xr8 = xr0 + 8*CIN;

    float acc[8][4];
    #pragma unroll
    for (int j = 0; j < 8; ++j)
        #pragma unroll
        for (int q = 0; q < 4; ++q) acc[j][q] = 0.f;

    float2 v0 = *(const float2*)(xr0);
    float2 v1 = *(const float2*)(xr8);
    float2 v2 = *(const float2*)(xr0 + 8);
    float2 v3 = *(const float2*)(xr8 + 8);

    #pragma unroll 4
    for (int kc = 0; kc < 16; ++kc) {
        float2 n0, n1, n2, n3;
        if (kc < 15) {
            int c1 = (kc + 1) * 16;
            n0 = *(const float2*)(xr0 + c1);
            n1 = *(const float2*)(xr8 + c1);
            n2 = *(const float2*)(xr0 + c1 + 8);
            n3 = *(const float2*)(xr8 + c1 + 8);
        }
        uint32_t aH0 = pack2bf(v0.x, v0.y);
        uint32_t aH1 = pack2bf(v1.x, v1.y);
        uint32_t aH2 = pack2bf(v2.x, v2.y);
        uint32_t aH3 = pack2bf(v3.x, v3.y);
        uint32_t aL0 = pack2bf(v0.x - __uint_as_float(aH0 << 16),
                               v0.y - __uint_as_float(aH0 & 0xFFFF0000u));
        uint32_t aL1 = pack2bf(v1.x - __uint_as_float(aH1 << 16),
                               v1.y - __uint_as_float(aH1 & 0xFFFF0000u));
        uint32_t aL2 = pack2bf(v2.x - __uint_as_float(aH2 << 16),
                               v2.y - __uint_as_float(aH2 & 0xFFFF0000u));
        uint32_t aL3 = pack2bf(v3.x - __uint_as_float(aH3 << 16),
                               v3.y - __uint_as_float(aH3 & 0xFFFF0000u));

        const uint32_t* bh = BsH + (kc*8*32 + lane)*2;
        const uint32_t* bl = BsL + (kc*8*32 + lane)*2;
        #pragma unroll
        for (int j = 0; j < 8; ++j) {
            uint2 bhj = *(const uint2*)(bh + j*64);
            uint2 blj = *(const uint2*)(bl + j*64);
            mma16816(acc[j], aH0, aH1, aH2, aH3, bhj.x, bhj.y);
            mma16816(acc[j], aL0, aL1, aL2, aL3, bhj.x, bhj.y);
            mma16816(acc[j], aH0, aH1, aH2, aH3, blj.x, blj.y);
        }
        v0 = n0; v1 = n1; v2 = n2; v3 = n3;
    }

    float* o0 = out + ((size_t)b*Nseq + tok0 + w*16 + rrow)*Hh + tig*2;
    float* o8 = o0 + 8*Hh;
    #pragma unroll
    for (int j = 0; j < 8; ++j) {
        float2 bj = *(const float2*)(bias_s + tig*2 + 8*j);
        *(float2*)(o0 + 8*j) = make_float2(acc[j][0] + bj.x, acc[j][1] + bj.y);
        *(float2*)(o8 + 8*j) = make_float2(acc[j][2] + bj.x, acc[j][3] + bj.y);
    }
}

extern "C" void kernel_launch(void* const* d_in, const int* in_sizes, int n_in,
                              void* d_out, int out_size) {
    const float* x  = (const float*)d_in[0];
    const float* Wq = (const float*)d_in[1];
    const float* bq = (const float*)d_in[2];
    const float* Wk = (const float*)d_in[3];
    const float* bk = (const float*)d_in[4];
    const float* qw = (const float*)d_in[5];
    const float* Wp = (const float*)d_in[6];
    const float* bp = (const float*)d_in[7];
    const float* Wo = (const float*)d_in[8];
    const float* bo = (const float*)d_in[9];
    float* out = (float*)d_out;
    (void)in_sizes; (void)n_in; (void)out_size;

    cudaFuncSetAttribute(k_pass2, cudaFuncAttributeMaxDynamicSharedMemorySize, P2_SMEM);
    cudaFuncSetAttribute(k_mid, cudaFuncAttributeMaxDynamicSharedMemorySize, MID_SMEM);

    k_prep_small<<<33, 256>>>(Wq, bq, qw);
    {
        dim3 g(128, 8);
        k_pass1<<<g, 256>>>(x);
    }
    k_aw_prep<<<209, 256>>>(Wq, bq, qw, bp, Wo, bo, Wp);
    k_mid<<<136, 512, MID_SMEM>>>(Wk, bk);
    {
        dim3 g(128, 8);
        k_pass2<<<g, 256, P2_SMEM>>>(x, out);
    }
}

// round 13
// speedup vs baseline: 4.2686x; 1.0369x over previous
#include <cuda_runtime.h>
#include <cuda_bf16.h>
#include <cstdint>

#define Bsz 8
#define Nseq 16384
#define CIN 256     // DIM (= K of pass2 GEMM)
#define Dd 512      // D
#define Hh 64       // DIM_HEAD (= N of pass2 GEMM)
#define SCALEF 0.125f

// scratch (device globals; no allocation allowed)
__device__ __align__(16) float g_v[CIN];
__device__ float g_s0;
__device__ float g_c0[Hh];
__device__ __align__(16) float g_W1[Dd*Hh];
__device__ __align__(16) float g_A[CIN*Hh];
__device__ float g_ypart[Bsz*128*CIN];
__device__ float g_Spart[Bsz*128];
__device__ __align__(16) float g_aw[Bsz*Dd];
__device__ float g_bias[Bsz*Hh];
// B = M in mma.m16n8k16 b-fragment order: [b][kc(16)][j(8)][lane(32)][sel(2)] u32(bf16x2)
__device__ __align__(16) uint32_t g_BfH[Bsz*16*8*32*2];
__device__ __align__(16) uint32_t g_BfL[Bsz*16*8*32*2];

// pack two f32 -> bf16x2 (lo arg in low half)
__device__ __forceinline__ uint32_t pack2bf(float lo, float hi) {
    uint32_t r;
    asm("cvt.rn.bf16x2.f32 %0, %1, %2;" : "=r"(r) : "f"(hi), "f"(lo));
    return r;
}
__device__ __forceinline__ void mma16816(float* d, uint32_t a0, uint32_t a1,
                                         uint32_t a2, uint32_t a3,
                                         uint32_t b0, uint32_t b1) {
    asm volatile(
        "mma.sync.aligned.m16n8k16.row.col.f32.bf16.bf16.f32 "
        "{%0,%1,%2,%3}, {%4,%5,%6,%7}, {%8,%9}, {%0,%1,%2,%3};"
        : "+f"(d[0]), "+f"(d[1]), "+f"(d[2]), "+f"(d[3])
        : "r"(a0), "r"(a1), "r"(a2), "r"(a3), "r"(b0), "r"(b1));
}

// ---------------------------------------------------------------------------
// k_prep_small (grid 33): only what pass1 needs.
//   blocks 0..31: v = Wq@qw (8 rows per block); block 32: s0 = bq.qw
// ---------------------------------------------------------------------------
__global__ void __launch_bounds__(256) k_prep_small(
        const float* __restrict__ Wq, const float* __restrict__ bq,
        const float* __restrict__ qw) {
    int tid = threadIdx.x;
    int lane = tid & 31;
    int bx = blockIdx.x;
    if (bx < 32) {
        int g = bx * 8 + (tid >> 5);
        const float* row = Wq + (size_t)g * Dd;
        float acc = 0.f;
        #pragma unroll
        for (int i = 0; i < 16; ++i) acc += row[lane + 32*i] * qw[lane + 32*i];
        #pragma unroll
        for (int o = 16; o; o >>= 1) acc += __shfl_xor_sync(0xffffffffu, acc, o);
        if (lane == 0) g_v[g] = acc;
    } else if (tid < 32) {
        float a = 0.f;
        #pragma unroll
        for (int i = 0; i < 16; ++i) a += bq[lane + 32*i] * qw[lane + 32*i];
        #pragma unroll
        for (int o = 16; o; o >>= 1) a += __shfl_xor_sync(0xffffffffu, a, o);
        if (lane == 0) g_s0 = a;
    }
}

// ---------------------------------------------------------------------------
// pass 1 (grid (128, 8)): per block 128 tokens; warp = 16 tokens in 4 batches
// of 4. Double-buffered loads keep 8 LDG.128 in flight during the shfl chain.
// ---------------------------------------------------------------------------
__global__ void __launch_bounds__(256) k_pass1(const float* __restrict__ x) {
    __shared__ float y_sh[8][256];
    __shared__ float s_sh[8];
    int b = blockIdx.y;
    int tile = blockIdx.x;
    int warp = threadIdx.x >> 5, lane = threadIdx.x & 31;

    float4 v0 = *(const float4*)(g_v + 4*lane);
    float4 v1 = *(const float4*)(g_v + 128 + 4*lane);
    float s0 = g_s0;

    const float* xb = x + ((size_t)b*Nseq + (size_t)tile*128 + warp*16) * CIN;

    float y0[4] = {0,0,0,0}, y1[4] = {0,0,0,0};
    float Sacc = 0.f;

    float4 A0[2][4], A1[2][4];
    #pragma unroll
    for (int u = 0; u < 4; ++u) {
        const float* xr = xb + (size_t)u*CIN;
        A0[0][u] = *(const float4*)(xr + 4*lane);
        A1[0][u] = *(const float4*)(xr + 128 + 4*lane);
    }
    #pragma unroll
    for (int g = 0; g < 4; ++g) {
        int cur = g & 1, nxt = cur ^ 1;
        if (g < 3) {
            #pragma unroll
            for (int u = 0; u < 4; ++u) {
                const float* xr = xb + (size_t)((g+1)*4 + u)*CIN;
                A0[nxt][u] = *(const float4*)(xr + 4*lane);
                A1[nxt][u] = *(const float4*)(xr + 128 + 4*lane);
            }
        }
        float p[4];
        #pragma unroll
        for (int u = 0; u < 4; ++u)
            p[u] = A0[cur][u].x*v0.x + A0[cur][u].y*v0.y + A0[cur][u].z*v0.z + A0[cur][u].w*v0.w
                 + A1[cur][u].x*v1.x + A1[cur][u].y*v1.y + A1[cur][u].z*v1.z + A1[cur][u].w*v1.w;
        #pragma unroll
        for (int o = 16; o; o >>= 1) {
            #pragma unroll
            for (int u = 0; u < 4; ++u)
                p[u] += __shfl_xor_sync(0xffffffffu, p[u], o);
        }
        #pragma unroll
        for (int u = 0; u < 4; ++u) {
            float score = (p[u] + s0) * SCALEF;
            Sacc += score;
            y0[0] += score*A0[cur][u].x; y0[1] += score*A0[cur][u].y;
            y0[2] += score*A0[cur][u].z; y0[3] += score*A0[cur][u].w;
            y1[0] += score*A1[cur][u].x; y1[1] += score*A1[cur][u].y;
            y1[2] += score*A1[cur][u].z; y1[3] += score*A1[cur][u].w;
        }
    }
    #pragma unroll
    for (int j = 0; j < 4; ++j) {
        y_sh[warp][4*lane + j]       = y0[j];
        y_sh[warp][128 + 4*lane + j] = y1[j];
    }
    if (lane == 0) s_sh[warp] = Sacc;
    __syncthreads();
    int c = threadIdx.x;
    float acc = 0.f;
    #pragma unroll
    for (int w = 0; w < 8; ++w) acc += y_sh[w][c];
    g_ypart[((size_t)b*128 + tile)*256 + c] = acc;
    if (threadIdx.x == 0) {
        float s = 0.f;
        for (int w = 0; w < 8; ++w) s += s_sh[w];
        g_Spart[b*128 + tile] = s;
    }
}

// ---------------------------------------------------------------------------
// k_aw_prep (grid 209): aw (needs pass1) runs in parallel with the weight
// GEMMs (independent of pass1):
//   blocks 0..15  : aw per batch-half
//   block  16     : c0 = (bq+bp)@Wo + bo
//   blocks 17..144: W1 = Wp@Wo, 4-row tiles
//   blocks 145..208: A = Wq@Wo, 4-row tiles
// ---------------------------------------------------------------------------
__global__ void __launch_bounds__(256) k_aw_prep(
        const float* __restrict__ Wq, const float* __restrict__ bq,
        const float* __restrict__ qw, const float* __restrict__ bp,
        const float* __restrict__ Wo, const float* __restrict__ bo,
        const float* __restrict__ Wp) {
    __shared__ float As4[4*512];   // 8 KB (aliased as reduce buf)
    __shared__ float Wos[64*64];   // 16 KB
    int tid = threadIdx.x;
    int bx = blockIdx.x;

    if (bx < 16) {
        __shared__ float y_s[256];
        __shared__ float s_tmp[128];
        int b = bx >> 1;
        int half = bx & 1;
        {
            const float* yp = g_ypart + (size_t)b*128*256 + tid;
            float acc = 0.f;
            #pragma unroll 8
            for (int p = 0; p < 128; ++p) acc += yp[(size_t)p*256];
            y_s[tid] = acc;
        }
        if (tid < 128) s_tmp[tid] = g_Spart[b*128 + tid];
        __syncthreads();
        float S = 0.f;
        #pragma unroll
        for (int i = 0; i < 128; ++i) S += s_tmp[i];
        int d = half*256 + tid;
        float acc = bq[d] * S;
        #pragma unroll 8
        for (int c = 0; c < 256; ++c)
            acc += y_s[c] * Wq[(size_t)c*Dd + d];
        g_aw[b*Dd + d] = acc;
        return;
    }
    if (bx == 16) {
        float* redc = As4;
        int h = tid & 63, seg = tid >> 6;
        float acc = (seg == 0) ? bo[h] : 0.f;
        #pragma unroll 8
        for (int d = seg*128; d < seg*128 + 128; ++d)
            acc += (bq[d] + bp[d]) * Wo[d*Hh + h];
        redc[seg*64 + h] = acc;
        __syncthreads();
        if (tid < 64)
            g_c0[tid] = redc[tid] + redc[64 + tid] + redc[128 + tid] + redc[192 + tid];
        return;
    }
    const float* Asrc;
    float* Cdst;
    if (bx < 145) {
        int r0 = (bx - 17) * 4;
        Asrc = Wp + (size_t)r0 * Dd;
        Cdst = g_W1 + (size_t)r0 * Hh;
    } else {
        int r0 = (bx - 145) * 4;
        Asrc = Wq + (size_t)r0 * Dd;
        Cdst = g_A + (size_t)r0 * Hh;
    }
    #pragma unroll
    for (int i = 0; i < 2; ++i)
        ((float4*)As4)[tid + i*256] = ((const float4*)Asrc)[tid + i*256];

    int h = tid & 63, rp = tid >> 6;
    float acc = 0.f;
    for (int kc = 0; kc < 8; ++kc) {
        __syncthreads();
        const float4* src = (const float4*)(Wo + (size_t)(kc*64)*Hh);
        #pragma unroll
        for (int i = 0; i < 4; ++i)
            ((float4*)Wos)[tid + i*256] = src[tid + i*256];
        __syncthreads();
        const float* ar = As4 + rp*512 + kc*64;
        #pragma unroll 16
        for (int k = 0; k < 64; ++k)
            acc += ar[k] * Wos[k*64 + h];
    }
    Cdst[rp*Hh + h] = acc;
}

// ---------------------------------------------------------------------------
// k_mid (grid 136 x 512 threads), FFMA-bound layout:
//   parts 0..15: 16-row tile of M_b = Wk @ diag(aw_b) @ W1 + A.
//     thread = (ks: 64-k slice) x (rg: 4 rows) x (hq: 4 heads) — per k-step
//     1 LDS.128 (W1 quad) + 4 broadcast LDS.32 (Wk) feed 16 FFMA.
//     8-way K partials combined deterministically via smem, then emission.
//   part  16   : bias_b = (aw_b ⊙ bk) @ W1 + c0
// smem: aw[512] | Wks[16][516] | W1s[512][64]  (aliases: Cp=W1s, Ms=Wks)
// ---------------------------------------------------------------------------
#define WKP 516
#define MID_SMEM ((512 + 16*WKP + 512*64) * 4)   // 166144 B
__global__ void __launch_bounds__(512) k_mid(const float* __restrict__ Wk,
                                             const float* __restrict__ bk) {
    extern __shared__ float smd[];
    float* aw_s = smd;                       // 512
    float* Wks  = smd + 512;                 // 16 x 516 (padded)
    float* W1s  = smd + 512 + 16*WKP;        // 512 x 64
    float* red  = Wks;                       // alias (bias path: 8x64)
    float* Cp   = W1s;                       // alias (combine: 8x16x64)
    float* Ms   = Wks;                       // alias (M tile: 16x64)

    int tid = threadIdx.x;                   // 0..511
    int b = blockIdx.x / 17;
    int part = blockIdx.x % 17;

    aw_s[tid] = g_aw[b*Dd + tid];
    __syncthreads();

    if (part == 16) {
        int h = tid & 63, seg = tid >> 6;    // 8 segs of 64 k
        float acc = 0.f;
        #pragma unroll 4
        for (int d = seg*64; d < seg*64 + 64; ++d)
            acc += aw_s[d] * bk[d] * g_W1[(size_t)d*Hh + h];
        red[seg*64 + h] = acc;
        __syncthreads();
        if (tid < 64) {
            float s = g_c0[tid];
            #pragma unroll
            for (int sg = 0; sg < 8; ++sg) s += red[sg*64 + tid];
            g_bias[b*Hh + tid] = s;
        }
        return;
    }

    int r0 = part * 16;
    int ks = tid >> 6;            // K slice 0..7 (64 k each)
    int rg = (tid >> 4) & 3;      // row group: rows 4rg..4rg+3
    int hq = tid & 15;            // head quad
    int h0 = hq * 4;

    // stage Wk tile: 16 rows x 512 k (padded rows)
    #pragma unroll
    for (int i = 0; i < 4; ++i) {
        int idx = tid + i*512;
        int row = idx >> 7, q = (idx & 127) * 4;
        *(float4*)(Wks + row*WKP + q) =
            *(const float4*)(Wk + (size_t)(r0 + row)*Dd + q);
    }
    // stage W1 * aw: 512 k x 64 h = 8192 float4
    #pragma unroll
    for (int i = 0; i < 16; ++i) {
        int idx = tid + i*512;
        int k = idx >> 4, h4 = (idx & 15) * 4;
        float4 wv = *(const float4*)(g_W1 + (size_t)k*Hh + h4);
        float a = aw_s[k];
        wv.x *= a; wv.y *= a; wv.z *= a; wv.w *= a;
        *(float4*)(W1s + k*64 + h4) = wv;
    }
    __syncthreads();

    float4 acc0 = make_float4(0.f,0.f,0.f,0.f);
    float4 acc1 = acc0, acc2 = acc0, acc3 = acc0;
    {
        const float* w1b = W1s + (size_t)(ks*64)*64 + h0;
        const float* wk0 = Wks + (4*rg + 0)*WKP + ks*64;
        const float* wk1 = Wks + (4*rg + 1)*WKP + ks*64;
        const float* wk2 = Wks + (4*rg + 2)*WKP + ks*64;
        const float* wk3 = Wks + (4*rg + 3)*WKP + ks*64;
        #pragma unroll 8
        for (int k = 0; k < 64; ++k) {
            float4 bv = *(const float4*)(w1b + k*64);
            float a0 = wk0[k], a1 = wk1[k], a2 = wk2[k], a3 = wk3[k];
            acc0.x += a0*bv.x; acc0.y += a0*bv.y; acc0.z += a0*bv.z; acc0.w += a0*bv.w;
            acc1.x += a1*bv.x; acc1.y += a1*bv.y; acc1.z += a1*bv.z; acc1.w += a1*bv.w;
            acc2.x += a2*bv.x; acc2.y += a2*bv.y; acc2.z += a2*bv.z; acc2.w += a2*bv.w;
            acc3.x += a3*bv.x; acc3.y += a3*bv.y; acc3.z += a3*bv.z; acc3.w += a3*bv.w;
        }
    }
    __syncthreads();
    // park partials: Cp[ks][row][h] (aliases W1s, safe after barrier)
    *(float4*)(Cp + (ks*16 + 4*rg + 0)*64 + h0) = acc0;
    *(float4*)(Cp + (ks*16 + 4*rg + 1)*64 + h0) = acc1;
    *(float4*)(Cp + (ks*16 + 4*rg + 2)*64 + h0) = acc2;
    *(float4*)(Cp + (ks*16 + 4*rg + 3)*64 + h0) = acc3;
    __syncthreads();
    // combine 8 K-slices deterministically + add A; write Ms (aliases Wks)
    #pragma unroll
    for (int e = 0; e < 2; ++e) {
        int entry = tid + e*512;           // 0..1023 = r*64 + h
        int r = entry >> 6, h = entry & 63;
        float s = g_A[(size_t)(r0 + r)*Hh + h];
        #pragma unroll
        for (int sg = 0; sg < 8; ++sg) s += Cp[(sg*16 + r)*64 + h];
        Ms[entry] = s;
    }
    __syncthreads();
    // emission: 512 pair-entries = (row-pair 0..7) x (head 0..63); 1 per thread
    {
        int rp = tid >> 6;
        int h = tid & 63;
        float m0 = Ms[(2*rp)*64 + h];
        float m1 = Ms[(2*rp + 1)*64 + h];
        int rr = r0 + 2*rp;                 // even global k index
        int kc16 = rr >> 4;
        int kk = rr & 15;
        int tig = (kk >> 1) & 3;
        int sel = kk >> 3;
        uint32_t hp = pack2bf(m0, m1);
        float l0 = m0 - __uint_as_float(hp << 16);
        float l1 = m1 - __uint_as_float(hp & 0xFFFF0000u);
        uint32_t lp = pack2bf(l0, l1);
        int lanef = (h & 7)*4 + tig;
        int j = h >> 3;
        size_t idx = ((((size_t)b*16 + kc16)*8 + j)*32 + lanef)*2 + sel;
        g_BfH[idx] = hp;
        g_BfL[idx] = lp;
    }
}

// ---------------------------------------------------------------------------
// pass 2 (mma.sync m16n8k16 bf16, 3-term split): out = x @ M_b + bias_b
// CTA: 128 tokens x 64 heads, 8 warps; warp: 16 tokens x 64 heads.
// ---------------------------------------------------------------------------
#define P2_SMEM (65536 + 256)
__global__ void __launch_bounds__(256, 3) k_pass2(const float* __restrict__ x,
                                                  float* __restrict__ out) {
    extern __shared__ char sm[];
    uint32_t* BsH = (uint32_t*)sm;              // [kc][j][lane][sel] : 32 KB
    uint32_t* BsL = (uint32_t*)(sm + 32768);    // 32 KB
    float* bias_s = (float*)(sm + 65536);

    int tid = threadIdx.x;
    int w = tid >> 5, lane = tid & 31;
    int b = blockIdx.y;
    int tile = gridDim.x - 1 - blockIdx.x;      // reversed for L2 reuse
    int tok0 = tile * 128;

    {
        const uint4* srcH = (const uint4*)(g_BfH + (size_t)b*8192);
        const uint4* srcL = (const uint4*)(g_BfL + (size_t)b*8192);
        #pragma unroll
        for (int i = 0; i < 8; ++i) {
            ((uint4*)BsH)[tid + i*256] = srcH[tid + i*256];
            ((uint4*)BsL)[tid + i*256] = srcL[tid + i*256];
        }
        if (tid < 64) bias_s[tid] = g_bias[b*Hh + tid];
    }
    __syncthreads();

    int rrow = lane >> 2;
    int tig = lane & 3;
    const float* xr0 = x + ((size_t)b*Nseq + tok0 + w*16 + rrow)*CIN + tig*2;
    const float* xr8 = xr0 + 8*CIN;

    float acc[8][4];
    #pragma unroll
    for (int j = 0; j < 8; ++j)
        #pragma unroll
        for (int q = 0; q < 4; ++q) acc[j][q] = 0.f;

    float2 v0 = *(const float2*)(xr0);
    float2 v1 = *(const float2*)(xr8);
    float2 v2 = *(const float2*)(xr0 + 8);
    float2 v3 = *(const float2*)(xr8 + 8);

    #pragma unroll 4
    for (int kc = 0; kc < 16; ++kc) {
        float2 n0, n1, n2, n3;
        if (kc < 15) {
            int c1 = (kc + 1) * 16;
            n0 = *(const float2*)(xr0 + c1);
            n1 = *(const float2*)(xr8 + c1);
            n2 = *(const float2*)(xr0 + c1 + 8);
            n3 = *(const float2*)(xr8 + c1 + 8);
        }
        uint32_t aH0 = pack2bf(v0.x, v0.y);
        uint32_t aH1 = pack2bf(v1.x, v1.y);
        uint32_t aH2 = pack2bf(v2.x, v2.y);
        uint32_t aH3 = pack2bf(v3.x, v3.y);
        uint32_t aL0 = pack2bf(v0.x - __uint_as_float(aH0 << 16),
                               v0.y - __uint_as_float(aH0 & 0xFFFF0000u));
        uint32_t aL1 = pack2bf(v1.x - __uint_as_float(aH1 << 16),
                               v1.y - __uint_as_float(aH1 & 0xFFFF0000u));
        uint32_t aL2 = pack2bf(v2.x - __uint_as_float(aH2 << 16),
                               v2.y - __uint_as_float(aH2 & 0xFFFF0000u));
        uint32_t aL3 = pack2bf(v3.x - __uint_as_float(aH3 << 16),
                               v3.y - __uint_as_float(aH3 & 0xFFFF0000u));

        const uint32_t* bh = BsH + (kc*8*32 + lane)*2;
        const uint32_t* bl = BsL + (kc*8*32 + lane)*2;
        #pragma unroll
        for (int j = 0; j < 8; ++j) {
            uint2 bhj = *(const uint2*)(bh + j*64);
            uint2 blj = *(const uint2*)(bl + j*64);
            mma16816(acc[j], aH0, aH1, aH2, aH3, bhj.x, bhj.y);
            mma16816(acc[j], aL0, aL1, aL2, aL3, bhj.x, bhj.y);
            mma16816(acc[j], aH0, aH1, aH2, aH3, blj.x, blj.y);
        }
        v0 = n0; v1 = n1; v2 = n2; v3 = n3;
    }

    float* o0 = out + ((size_t)b*Nseq + tok0 + w*16 + rrow)*Hh + tig*2;
    float* o8 = o0 + 8*Hh;
    #pragma unroll
    for (int j = 0; j < 8; ++j) {
        float2 bj = *(const float2*)(bias_s + tig*2 + 8*j);
        *(float2*)(o0 + 8*j) = make_float2(acc[j][0] + bj.x, acc[j][1] + bj.y);
        *(float2*)(o8 + 8*j) = make_float2(acc[j][2] + bj.x, acc[j][3] + bj.y);
    }
}

extern "C" void kernel_launch(void* const* d_in, const int* in_sizes, int n_in,
                              void* d_out, int out_size) {
    const float* x  = (const float*)d_in[0];
    const float* Wq = (const float*)d_in[1];
    const float* bq = (const float*)d_in[2];
    const float* Wk = (const float*)d_in[3];
    const float* bk = (const float*)d_in[4];
    const float* qw = (const float*)d_in[5];
    const float* Wp = (const float*)d_in[6];
    const float* bp = (const float*)d_in[7];
    const float* Wo = (const float*)d_in[8];
    const float* bo = (const float*)d_in[9];
    float* out = (float*)d_out;
    (void)in_sizes; (void)n_in; (void)out_size;

    cudaFuncSetAttribute(k_pass2, cudaFuncAttributeMaxDynamicSharedMemorySize, P2_SMEM);
    cudaFuncSetAttribute(k_mid, cudaFuncAttributeMaxDynamicSharedMemorySize, MID_SMEM);

    k_prep_small<<<33, 256>>>(Wq, bq, qw);
    {
        dim3 g(128, 8);
        k_pass1<<<g, 256>>>(x);
    }
    k_aw_prep<<<209, 256>>>(Wq, bq, qw, bp, Wo, bo, Wp);
    k_mid<<<136, 512, MID_SMEM>>>(Wk, bk);
    {
        dim3 g(128, 8);
        k_pass2<<<g, 256, P2_SMEM>>>(x, out);
    }
}

// round 17
// speedup vs baseline: 4.5721x; 1.0711x over previous
#include <cuda_runtime.h>
#include <cuda_bf16.h>
#include <cstdint>

#define Bsz 8
#define Nseq 16384
#define CIN 256     // DIM (= K of pass2 GEMM)
#define Dd 512      // D
#define Hh 64       // DIM_HEAD (= N of pass2 GEMM)
#define SCALEF 0.125f

// scratch (device globals; no allocation allowed)
__device__ __align__(16) float g_v[CIN];
__device__ float g_s0;
__device__ float g_c0[Hh];
__device__ __align__(16) float g_W1[Dd*Hh];
__device__ __align__(16) float g_A[CIN*Hh];
__device__ float g_ypart[Bsz*128*CIN];
__device__ float g_Spart[Bsz*128];
__device__ __align__(16) float g_aw[Bsz*Dd];
__device__ float g_bias[Bsz*Hh];
// B = M in mma.m16n8k16 b-fragment order: [b][kc(16)][j(8)][lane(32)][sel(2)] u32(bf16x2)
__device__ __align__(16) uint32_t g_BfH[Bsz*16*8*32*2];
__device__ __align__(16) uint32_t g_BfL[Bsz*16*8*32*2];

// pack two f32 -> bf16x2 (lo arg in low half)
__device__ __forceinline__ uint32_t pack2bf(float lo, float hi) {
    uint32_t r;
    asm("cvt.rn.bf16x2.f32 %0, %1, %2;" : "=r"(r) : "f"(hi), "f"(lo));
    return r;
}
__device__ __forceinline__ void mma16816(float* d, uint32_t a0, uint32_t a1,
                                         uint32_t a2, uint32_t a3,
                                         uint32_t b0, uint32_t b1) {
    asm volatile(
        "mma.sync.aligned.m16n8k16.row.col.f32.bf16.bf16.f32 "
        "{%0,%1,%2,%3}, {%4,%5,%6,%7}, {%8,%9}, {%0,%1,%2,%3};"
        : "+f"(d[0]), "+f"(d[1]), "+f"(d[2]), "+f"(d[3])
        : "r"(a0), "r"(a1), "r"(a2), "r"(a3), "r"(b0), "r"(b1));
}
__device__ __forceinline__ uint32_t smem_u32(const void* p) {
    uint32_t a;
    asm("{ .reg .u64 t; cvta.to.shared.u64 t, %1; cvt.u32.u64 %0, t; }" : "=r"(a) : "l"(p));
    return a;
}
__device__ __forceinline__ void cpa16(uint32_t d, const float* s) {
    asm volatile("cp.async.cg.shared.global [%0], [%1], 16;" :: "r"(d), "l"(s));
}
#define CP_COMMIT() asm volatile("cp.async.commit_group;" ::: "memory")

// ---------------------------------------------------------------------------
// k_prep_small (grid 33): only what pass1 needs.
// ---------------------------------------------------------------------------
__global__ void __launch_bounds__(256) k_prep_small(
        const float* __restrict__ Wq, const float* __restrict__ bq,
        const float* __restrict__ qw) {
    int tid = threadIdx.x;
    int lane = tid & 31;
    int bx = blockIdx.x;
    if (bx < 32) {
        int g = bx * 8 + (tid >> 5);
        const float* row = Wq + (size_t)g * Dd;
        float acc = 0.f;
        #pragma unroll
        for (int i = 0; i < 16; ++i) acc += row[lane + 32*i] * qw[lane + 32*i];
        #pragma unroll
        for (int o = 16; o; o >>= 1) acc += __shfl_xor_sync(0xffffffffu, acc, o);
        if (lane == 0) g_v[g] = acc;
    } else if (tid < 32) {
        float a = 0.f;
        #pragma unroll
        for (int i = 0; i < 16; ++i) a += bq[lane + 32*i] * qw[lane + 32*i];
        #pragma unroll
        for (int o = 16; o; o >>= 1) a += __shfl_xor_sync(0xffffffffu, a, o);
        if (lane == 0) g_s0 = a;
    }
}

// ---------------------------------------------------------------------------
// pass 1 (grid (128, 8)): unchanged from round 13.
// ---------------------------------------------------------------------------
__global__ void __launch_bounds__(256) k_pass1(const float* __restrict__ x) {
    __shared__ float y_sh[8][256];
    __shared__ float s_sh[8];
    int b = blockIdx.y;
    int tile = blockIdx.x;
    int warp = threadIdx.x >> 5, lane = threadIdx.x & 31;

    float4 v0 = *(const float4*)(g_v + 4*lane);
    float4 v1 = *(const float4*)(g_v + 128 + 4*lane);
    float s0 = g_s0;

    const float* xb = x + ((size_t)b*Nseq + (size_t)tile*128 + warp*16) * CIN;

    float y0[4] = {0,0,0,0}, y1[4] = {0,0,0,0};
    float Sacc = 0.f;

    float4 A0[2][4], A1[2][4];
    #pragma unroll
    for (int u = 0; u < 4; ++u) {
        const float* xr = xb + (size_t)u*CIN;
        A0[0][u] = *(const float4*)(xr + 4*lane);
        A1[0][u] = *(const float4*)(xr + 128 + 4*lane);
    }
    #pragma unroll
    for (int g = 0; g < 4; ++g) {
        int cur = g & 1, nxt = cur ^ 1;
        if (g < 3) {
            #pragma unroll
            for (int u = 0; u < 4; ++u) {
                const float* xr = xb + (size_t)((g+1)*4 + u)*CIN;
                A0[nxt][u] = *(const float4*)(xr + 4*lane);
                A1[nxt][u] = *(const float4*)(xr + 128 + 4*lane);
            }
        }
        float p[4];
        #pragma unroll
        for (int u = 0; u < 4; ++u)
            p[u] = A0[cur][u].x*v0.x + A0[cur][u].y*v0.y + A0[cur][u].z*v0.z + A0[cur][u].w*v0.w
                 + A1[cur][u].x*v1.x + A1[cur][u].y*v1.y + A1[cur][u].z*v1.z + A1[cur][u].w*v1.w;
        #pragma unroll
        for (int o = 16; o; o >>= 1) {
            #pragma unroll
            for (int u = 0; u < 4; ++u)
                p[u] += __shfl_xor_sync(0xffffffffu, p[u], o);
        }
        #pragma unroll
        for (int u = 0; u < 4; ++u) {
            float score = (p[u] + s0) * SCALEF;
            Sacc += score;
            y0[0] += score*A0[cur][u].x; y0[1] += score*A0[cur][u].y;
            y0[2] += score*A0[cur][u].z; y0[3] += score*A0[cur][u].w;
            y1[0] += score*A1[cur][u].x; y1[1] += score*A1[cur][u].y;
            y1[2] += score*A1[cur][u].z; y1[3] += score*A1[cur][u].w;
        }
    }
    #pragma unroll
    for (int j = 0; j < 4; ++j) {
        y_sh[warp][4*lane + j]       = y0[j];
        y_sh[warp][128 + 4*lane + j] = y1[j];
    }
    if (lane == 0) s_sh[warp] = Sacc;
    __syncthreads();
    int c = threadIdx.x;
    float acc = 0.f;
    #pragma unroll
    for (int w = 0; w < 8; ++w) acc += y_sh[w][c];
    g_ypart[((size_t)b*128 + tile)*256 + c] = acc;
    if (threadIdx.x == 0) {
        float s = 0.f;
        for (int w = 0; w < 8; ++w) s += s_sh[w];
        g_Spart[b*128 + tile] = s;
    }
}

// ---------------------------------------------------------------------------
// k_aw_prep (grid 209): unchanged from round 13.
// ---------------------------------------------------------------------------
__global__ void __launch_bounds__(256) k_aw_prep(
        const float* __restrict__ Wq, const float* __restrict__ bq,
        const float* __restrict__ qw, const float* __restrict__ bp,
        const float* __restrict__ Wo, const float* __restrict__ bo,
        const float* __restrict__ Wp) {
    __shared__ float As4[4*512];   // 8 KB (aliased as reduce buf)
    __shared__ float Wos[64*64];   // 16 KB
    int tid = threadIdx.x;
    int bx = blockIdx.x;

    if (bx < 16) {
        __shared__ float y_s[256];
        __shared__ float s_tmp[128];
        int b = bx >> 1;
        int half = bx & 1;
        {
            const float* yp = g_ypart + (size_t)b*128*256 + tid;
            float acc = 0.f;
            #pragma unroll 8
            for (int p = 0; p < 128; ++p) acc += yp[(size_t)p*256];
            y_s[tid] = acc;
        }
        if (tid < 128) s_tmp[tid] = g_Spart[b*128 + tid];
        __syncthreads();
        float S = 0.f;
        #pragma unroll
        for (int i = 0; i < 128; ++i) S += s_tmp[i];
        int d = half*256 + tid;
        float acc = bq[d] * S;
        #pragma unroll 8
        for (int c = 0; c < 256; ++c)
            acc += y_s[c] * Wq[(size_t)c*Dd + d];
        g_aw[b*Dd + d] = acc;
        return;
    }
    if (bx == 16) {
        float* redc = As4;
        int h = tid & 63, seg = tid >> 6;
        float acc = (seg == 0) ? bo[h] : 0.f;
        #pragma unroll 8
        for (int d = seg*128; d < seg*128 + 128; ++d)
            acc += (bq[d] + bp[d]) * Wo[d*Hh + h];
        redc[seg*64 + h] = acc;
        __syncthreads();
        if (tid < 64)
            g_c0[tid] = redc[tid] + redc[64 + tid] + redc[128 + tid] + redc[192 + tid];
        return;
    }
    const float* Asrc;
    float* Cdst;
    if (bx < 145) {
        int r0 = (bx - 17) * 4;
        Asrc = Wp + (size_t)r0 * Dd;
        Cdst = g_W1 + (size_t)r0 * Hh;
    } else {
        int r0 = (bx - 145) * 4;
        Asrc = Wq + (size_t)r0 * Dd;
        Cdst = g_A + (size_t)r0 * Hh;
    }
    #pragma unroll
    for (int i = 0; i < 2; ++i)
        ((float4*)As4)[tid + i*256] = ((const float4*)Asrc)[tid + i*256];

    int h = tid & 63, rp = tid >> 6;
    float acc = 0.f;
    for (int kc = 0; kc < 8; ++kc) {
        __syncthreads();
        const float4* src = (const float4*)(Wo + (size_t)(kc*64)*Hh);
        #pragma unroll
        for (int i = 0; i < 4; ++i)
            ((float4*)Wos)[tid + i*256] = src[tid + i*256];
        __syncthreads();
        const float* ar = As4 + rp*512 + kc*64;
        #pragma unroll 16
        for (int k = 0; k < 64; ++k)
            acc += ar[k] * Wos[k*64 + h];
    }
    Cdst[rp*Hh + h] = acc;
}

// ---------------------------------------------------------------------------
// k_mid (grid 136 x 512 threads): unchanged from round 13.
// ---------------------------------------------------------------------------
#define WKP 516
#define MID_SMEM ((512 + 16*WKP + 512*64) * 4)   // 166144 B
__global__ void __launch_bounds__(512) k_mid(const float* __restrict__ Wk,
                                             const float* __restrict__ bk) {
    extern __shared__ float smd[];
    float* aw_s = smd;                       // 512
    float* Wks  = smd + 512;                 // 16 x 516 (padded)
    float* W1s  = smd + 512 + 16*WKP;        // 512 x 64
    float* red  = Wks;                       // alias (bias path: 8x64)
    float* Cp   = W1s;                       // alias (combine: 8x16x64)
    float* Ms   = Wks;                       // alias (M tile: 16x64)

    int tid = threadIdx.x;                   // 0..511
    int b = blockIdx.x / 17;
    int part = blockIdx.x % 17;

    aw_s[tid] = g_aw[b*Dd + tid];
    __syncthreads();

    if (part == 16) {
        int h = tid & 63, seg = tid >> 6;    // 8 segs of 64 k
        float acc = 0.f;
        #pragma unroll 4
        for (int d = seg*64; d < seg*64 + 64; ++d)
            acc += aw_s[d] * bk[d] * g_W1[(size_t)d*Hh + h];
        red[seg*64 + h] = acc;
        __syncthreads();
        if (tid < 64) {
            float s = g_c0[tid];
            #pragma unroll
            for (int sg = 0; sg < 8; ++sg) s += red[sg*64 + tid];
            g_bias[b*Hh + tid] = s;
        }
        return;
    }

    int r0 = part * 16;
    int ks = tid >> 6;            // K slice 0..7 (64 k each)
    int rg = (tid >> 4) & 3;      // row group: rows 4rg..4rg+3
    int hq = tid & 15;            // head quad
    int h0 = hq * 4;

    #pragma unroll
    for (int i = 0; i < 4; ++i) {
        int idx = tid + i*512;
        int row = idx >> 7, q = (idx & 127) * 4;
        *(float4*)(Wks + row*WKP + q) =
            *(const float4*)(Wk + (size_t)(r0 + row)*Dd + q);
    }
    #pragma unroll
    for (int i = 0; i < 16; ++i) {
        int idx = tid + i*512;
        int k = idx >> 4, h4 = (idx & 15) * 4;
        float4 wv = *(const float4*)(g_W1 + (size_t)k*Hh + h4);
        float a = aw_s[k];
        wv.x *= a; wv.y *= a; wv.z *= a; wv.w *= a;
        *(float4*)(W1s + k*64 + h4) = wv;
    }
    __syncthreads();

    float4 acc0 = make_float4(0.f,0.f,0.f,0.f);
    float4 acc1 = acc0, acc2 = acc0, acc3 = acc0;
    {
        const float* w1b = W1s + (size_t)(ks*64)*64 + h0;
        const float* wk0 = Wks + (4*rg + 0)*WKP + ks*64;
        const float* wk1 = Wks + (4*rg + 1)*WKP + ks*64;
        const float* wk2 = Wks + (4*rg + 2)*WKP + ks*64;
        const float* wk3 = Wks + (4*rg + 3)*WKP + ks*64;
        #pragma unroll 8
        for (int k = 0; k < 64; ++k) {
            float4 bv = *(const float4*)(w1b + k*64);
            float a0 = wk0[k], a1 = wk1[k], a2 = wk2[k], a3 = wk3[k];
            acc0.x += a0*bv.x; acc0.y += a0*bv.y; acc0.z += a0*bv.z; acc0.w += a0*bv.w;
            acc1.x += a1*bv.x; acc1.y += a1*bv.y; acc1.z += a1*bv.z; acc1.w += a1*bv.w;
            acc2.x += a2*bv.x; acc2.y += a2*bv.y; acc2.z += a2*bv.z; acc2.w += a2*bv.w;
            acc3.x += a3*bv.x; acc3.y += a3*bv.y; acc3.z += a3*bv.z; acc3.w += a3*bv.w;
        }
    }
    __syncthreads();
    *(float4*)(Cp + (ks*16 + 4*rg + 0)*64 + h0) = acc0;
    *(float4*)(Cp + (ks*16 + 4*rg + 1)*64 + h0) = acc1;
    *(float4*)(Cp + (ks*16 + 4*rg + 2)*64 + h0) = acc2;
    *(float4*)(Cp + (ks*16 + 4*rg + 3)*64 + h0) = acc3;
    __syncthreads();
    #pragma unroll
    for (int e = 0; e < 2; ++e) {
        int entry = tid + e*512;           // 0..1023 = r*64 + h
        int r = entry >> 6, h = entry & 63;
        float s = g_A[(size_t)(r0 + r)*Hh + h];
        #pragma unroll
        for (int sg = 0; sg < 8; ++sg) s += Cp[(sg*16 + r)*64 + h];
        Ms[entry] = s;
    }
    __syncthreads();
    {
        int rp = tid >> 6;
        int h = tid & 63;
        float m0 = Ms[(2*rp)*64 + h];
        float m1 = Ms[(2*rp + 1)*64 + h];
        int rr = r0 + 2*rp;                 // even global k index
        int kc16 = rr >> 4;
        int kk = rr & 15;
        int tig = (kk >> 1) & 3;
        int sel = kk >> 3;
        uint32_t hp = pack2bf(m0, m1);
        float l0 = m0 - __uint_as_float(hp << 16);
        float l1 = m1 - __uint_as_float(hp & 0xFFFF0000u);
        uint32_t lp = pack2bf(l0, l1);
        int lanef = (h & 7)*4 + tig;
        int j = h >> 3;
        size_t idx = ((((size_t)b*16 + kc16)*8 + j)*32 + lanef)*2 + sel;
        g_BfH[idx] = hp;
        g_BfL[idx] = lp;
    }
}

// ---------------------------------------------------------------------------
// pass 2 (mma.sync m16n8k16 bf16, 3-term split): out = x @ M_b + bias_b
// CTA: 128 tokens x 64 heads, 8 warps; warp: 16 tokens x 64 heads.
// x fed by a 4-stage WARP-LOCAL cp.async pipeline (each lane stages exactly
// the rows its warp consumes -> wait_group + __syncwarp only, no block
// barriers in the mainloop). Stage rows padded to 24 floats: fragment
// LDS.64s are bank-conflict-free.
// ---------------------------------------------------------------------------
#define P2_STAGES 4
#define XROWF 24
#define STAGE_BYTES (128*XROWF*4)                      // 12288
#define P2_XBUF 65792                                  // BsH+BsL+bias
#define P2_SMEM (P2_XBUF + P2_STAGES*STAGE_BYTES)      // 114944
__global__ void __launch_bounds__(256, 2) k_pass2(const float* __restrict__ x,
                                                  float* __restrict__ out) {
    extern __shared__ char sm[];
    uint32_t* BsH = (uint32_t*)sm;              // 32 KB
    uint32_t* BsL = (uint32_t*)(sm + 32768);    // 32 KB
    float* bias_s = (float*)(sm + 65536);
    uint32_t smb = smem_u32(sm);

    int tid = threadIdx.x;
    int w = tid >> 5, lane = tid & 31;
    int b = blockIdx.y;
    int tile = gridDim.x - 1 - blockIdx.x;      // reversed for L2 reuse
    int tok0 = tile * 128;

    const float* xb = x + ((size_t)b*Nseq + tok0) * CIN;

    // cp.async producer mapping: lane stages rows (16w + lane>>2) and +8,
    // 16 B each at col (lane&3)*4 of the 16-float chunk.
    int lr = lane >> 2;
    int lc = (lane & 3) * 4;
    const float* srcA = xb + (size_t)(w*16 + lr)*CIN + lc;
    const float* srcB = srcA + 8*CIN;
    uint32_t dstA = smb + P2_XBUF + (uint32_t)(((w*16 + lr)*XROWF + lc) * 4);
    uint32_t dstB = dstA + 8*XROWF*4;

    // prologue: stages 0..2 in flight before B staging
    #pragma unroll
    for (int s = 0; s < 3; ++s) {
        cpa16(dstA + s*STAGE_BYTES, srcA + s*16);
        cpa16(dstB + s*STAGE_BYTES, srcB + s*16);
        CP_COMMIT();
    }

    // stage B fragments + bias
    {
        const uint4* srcHg = (const uint4*)(g_BfH + (size_t)b*8192);
        const uint4* srcLg = (const uint4*)(g_BfL + (size_t)b*8192);
        #pragma unroll
        for (int i = 0; i < 8; ++i) {
            ((uint4*)BsH)[tid + i*256] = srcHg[tid + i*256];
            ((uint4*)BsL)[tid + i*256] = srcLg[tid + i*256];
        }
        if (tid < 64) bias_s[tid] = g_bias[b*Hh + tid];
    }
    __syncthreads();

    int rrow = lane >> 2;
    int tig = lane & 3;
    const float* apBase = (const float*)(sm + P2_XBUF) + (w*16 + rrow)*XROWF + 2*tig;

    float acc[8][4];
    #pragma unroll
    for (int j = 0; j < 8; ++j)
        #pragma unroll
        for (int q = 0; q < 4; ++q) acc[j][q] = 0.f;

    #pragma unroll
    for (int kc = 0; kc < 16; ++kc) {
        if (kc + 3 < 16) {
            int s = (kc + 3) & 3;
            cpa16(dstA + s*STAGE_BYTES, srcA + (kc + 3)*16);
            cpa16(dstB + s*STAGE_BYTES, srcB + (kc + 3)*16);
            CP_COMMIT();
            asm volatile("cp.async.wait_group 3;" ::: "memory");
        } else if (kc == 13) {
            asm volatile("cp.async.wait_group 2;" ::: "memory");
        } else if (kc == 14) {
            asm volatile("cp.async.wait_group 1;" ::: "memory");
        } else {
            asm volatile("cp.async.wait_group 0;" ::: "memory");
        }
        __syncwarp();

        const float* ap = apBase + (kc & 3)*(STAGE_BYTES/4);
        float2 v0 = *(const float2*)(ap);                 // (r,   k0..k1)
        float2 v1 = *(const float2*)(ap + 8*XROWF);       // (r+8, k0..k1)
        float2 v2 = *(const float2*)(ap + 8);             // (r,   k8..k9)
        float2 v3 = *(const float2*)(ap + 8*XROWF + 8);   // (r+8, k8..k9)

        uint32_t aH0 = pack2bf(v0.x, v0.y);
        uint32_t aH1 = pack2bf(v1.x, v1.y);
        uint32_t aH2 = pack2bf(v2.x, v2.y);
        uint32_t aH3 = pack2bf(v3.x, v3.y);
        uint32_t aL0 = pack2bf(v0.x - __uint_as_float(aH0 << 16),
                               v0.y - __uint_as_float(aH0 & 0xFFFF0000u));
        uint32_t aL1 = pack2bf(v1.x - __uint_as_float(aH1 << 16),
                               v1.y - __uint_as_float(aH1 & 0xFFFF0000u));
        uint32_t aL2 = pack2bf(v2.x - __uint_as_float(aH2 << 16),
                               v2.y - __uint_as_float(aH2 & 0xFFFF0000u));
        uint32_t aL3 = pack2bf(v3.x - __uint_as_float(aH3 << 16),
                               v3.y - __uint_as_float(aH3 & 0xFFFF0000u));

        const uint32_t* bh = BsH + (kc*8*32 + lane)*2;
        const uint32_t* bl = BsL + (kc*8*32 + lane)*2;
        #pragma unroll
        for (int j = 0; j < 8; ++j) {
            uint2 bhj = *(const uint2*)(bh + j*64);
            uint2 blj = *(const uint2*)(bl + j*64);
            mma16816(acc[j], aH0, aH1, aH2, aH3, bhj.x, bhj.y);
            mma16816(acc[j], aL0, aL1, aL2, aL3, bhj.x, bhj.y);
            mma16816(acc[j], aH0, aH1, aH2, aH3, blj.x, blj.y);
        }
    }

    float* o0 = out + ((size_t)b*Nseq + tok0 + w*16 + rrow)*Hh + tig*2;
    float* o8 = o0 + 8*Hh;
    #pragma unroll
    for (int j = 0; j < 8; ++j) {
        float2 bj = *(const float2*)(bias_s + tig*2 + 8*j);
        *(float2*)(o0 + 8*j) = make_float2(acc[j][0] + bj.x, acc[j][1] + bj.y);
        *(float2*)(o8 + 8*j) = make_float2(acc[j][2] + bj.x, acc[j][3] + bj.y);
    }
}

extern "C" void kernel_launch(void* const* d_in, const int* in_sizes, int n_in,
                              void* d_out, int out_size) {
    const float* x  = (const float*)d_in[0];
    const float* Wq = (const float*)d_in[1];
    const float* bq = (const float*)d_in[2];
    const float* Wk = (const float*)d_in[3];
    const float* bk = (const float*)d_in[4];
    const float* qw = (const float*)d_in[5];
    const float* Wp = (const float*)d_in[6];
    const float* bp = (const float*)d_in[7];
    const float* Wo = (const float*)d_in[8];
    const float* bo = (const float*)d_in[9];
    float* out = (float*)d_out;
    (void)in_sizes; (void)n_in; (void)out_size;

    cudaFuncSetAttribute(k_pass2, cudaFuncAttributeMaxDynamicSharedMemorySize, P2_SMEM);
    cudaFuncSetAttribute(k_mid, cudaFuncAttributeMaxDynamicSharedMemorySize, MID_SMEM);

    k_prep_small<<<33, 256>>>(Wq, bq, qw);
    {
        dim3 g(128, 8);
        k_pass1<<<g, 256>>>(x);
    }
    k_aw_prep<<<209, 256>>>(Wq, bq, qw, bp, Wo, bo, Wp);
    k_mid<<<136, 512, MID_SMEM>>>(Wk, bk);
    {
        dim3 g(128, 8);
        k_pass2<<<g, 256, P2_SMEM>>>(x, out);
    }
}